// round 10
// baseline (speedup 1.0000x reference)
#include <cuda_runtime.h>
#include <cuda_bf16.h>

typedef unsigned long long u64;
typedef unsigned int u32;

#define NBATCH 512
#define NTT    257
#define NIVL   256
#define NIN    32
#define NH     128
#define NBN    256
#define NOUT   64
#define GRID_CTAS 128
#define TPB    256
#define NGRP   32

// ---- shared memory byte offsets ----
#define SM_FRAGB 0          // [16 kt][16 nt][32 lane] uint4 = 128KB
#define SM_W1    131072     // [128][8] f32
#define SM_W2    135168     // [256][8] f32
#define SM_B3    143360     // [128] f32
#define SM_B1    143872     // [8]
#define SM_B2    143904     // [8]
#define SM_MW    143936     // [128][2]
#define SM_SW    144960     // [128][2]
#define SM_MB    145984     // [2]
#define SM_SB    145992     // [2] (+pad)
#define SM_ACT   146016     // 2 x 2048 f32 staging (16KB)
#define SMEM_BYTES 162400

// ---- global scratch (parity double-buffered) ----
__device__ float g_zc[2][4 * NH * 128];    // col-major [h][r] per bb
__device__ float g_h1[2][4 * NBN * 128];   // col-major [c][r] per bb
__device__ uint4 g_fAhi[2][4][4096];       // A frags [(kt*8+mt)*32+lane]
__device__ uint4 g_fAlo[2][4][4096];

// ---- per-(bb, half, stage) arrive counters ----
// index: 0=zA 1=zB 2=h1A 3=h1B 4=h2A 5=h2B
struct PadCnt { unsigned v; unsigned pad[127]; };
__device__ PadCnt g_c6[4][6];

struct PadU { unsigned v; unsigned pad[31]; };
__device__ PadU g_cnt[4];
__device__ PadU g_rel[4];

// ---- helpers ----
__device__ __forceinline__ u64 pack2(float x, float y) {
    u64 r;
    asm("mov.b64 %0, {%1, %2};" : "=l"(r) : "f"(x), "f"(y));
    return r;
}
__device__ __forceinline__ float2 unpack2(u64 v) {
    float2 r;
    asm("mov.b64 {%0, %1}, %2;" : "=f"(r.x), "=f"(r.y) : "l"(v));
    return r;
}
__device__ __forceinline__ void fma2(u64& d, u64 a, u64 b) {
    asm("fma.rn.f32x2 %0, %1, %2, %0;" : "+l"(d) : "l"(a), "l"(b));
}
__device__ __forceinline__ float fast_tanh(float x) {
    float e;
    asm("ex2.approx.f32 %0, %1;" : "=f"(e) : "f"(x * 2.8853900817779268f));
    float r;
    asm("rcp.approx.f32 %0, %1;" : "=f"(r) : "f"(e + 1.0f));
    return fmaf(-2.0f, r, 1.0f);
}
__device__ __forceinline__ float softplus_f(float x) {
    return fmaxf(x, 0.0f) + log1pf(expf(-fabsf(x)));
}
__device__ __forceinline__ void mma16816(float* c, uint4 a, u32 b0, u32 b1) {
    asm volatile(
        "mma.sync.aligned.m16n8k16.row.col.f32.bf16.bf16.f32 "
        "{%0,%1,%2,%3}, {%4,%5,%6,%7}, {%8,%9}, {%0,%1,%2,%3};"
        : "+f"(c[0]), "+f"(c[1]), "+f"(c[2]), "+f"(c[3])
        : "r"(a.x), "r"(a.y), "r"(a.z), "r"(a.w), "r"(b0), "r"(b1));
}
__device__ __forceinline__ void bf_split(float x, unsigned short& h, unsigned short& l) {
    __nv_bfloat16 bh = __float2bfloat16_rn(x);
    __nv_bfloat16 bl = __float2bfloat16_rn(x - __bfloat162float(bh));
    h = __bfloat16_as_ushort(bh);
    l = __bfloat16_as_ushort(bl);
}

// ---- counter publish / wait ----
__device__ __forceinline__ void publish_cnt(PadCnt* c) {
    __syncthreads();
    if (threadIdx.x == 0) {
        asm volatile("red.release.gpu.global.add.u32 [%0], %1;"
                     :: "l"(&c->v), "r"(1u) : "memory");
    }
}
__device__ __forceinline__ void wait_cnt(PadCnt* c, unsigned target) {
    if (threadIdx.x == 0) {
        unsigned v;
        do {
            asm volatile("ld.acquire.gpu.u32 %0, [%1];"
                         : "=r"(v) : "l"(&c->v) : "memory");
        } while ((int)(v - target) < 0);
    }
    __syncthreads();
}
__device__ __forceinline__ void gbar_val(int grp, unsigned target) {
    __syncthreads();
    if (threadIdx.x == 0) {
        __threadfence();
        unsigned old = atomicAdd(&g_cnt[grp].v, 1u);
        if (old == (NGRP - 1u)) {
            g_cnt[grp].v = 0u;
            asm volatile("st.release.gpu.u32 [%0], %1;"
                         :: "l"(&g_rel[grp].v), "r"(target) : "memory");
        } else {
            unsigned v;
            do {
                asm volatile("ld.acquire.gpu.u32 %0, [%1];"
                             : "=r"(v) : "l"(&g_rel[grp].v) : "memory");
            } while (v != target);
        }
    }
    __syncthreads();
}

// ---- half-batch MLP core: acc[2 cols] over gin_cm[KT][128], rows rowHalf*64.. ----
// 256 threads: r = tid&63, ch = tid>>6 (cols ch*2, ch*2+1)
template <int KT>
__device__ __forceinline__ float2 mlp_half(const float* __restrict__ gin_cm,
                                           int rowHalf,
                                           const float* __restrict__ sW,
                                           const float* __restrict__ sb,
                                           float* __restrict__ sAct, int tid) {
    const int r  = tid & 63;
    const int ch = tid >> 6;
    u64 acc = pack2(sb[ch * 2], sb[ch * 2 + 1]);

    const int s0k = tid >> 4;            // 0..15
    const int sq  = tid & 15;
    const int s1k = s0k + 16;            // 16..31
    const float* base = gin_cm + rowHalf * 64;

    float4 v0 = __ldcg((const float4*)(base + s0k * 128) + sq);
    float4 v1 = __ldcg((const float4*)(base + s1k * 128) + sq);

    const int NCH = KT / 32;
#pragma unroll 1
    for (int kc = 0; kc < NCH; kc++) {
        float4* buf4 = (float4*)(sAct + (kc & 1) * 2048);
        buf4[s0k * 16 + sq] = v0;
        buf4[s1k * 16 + sq] = v1;
        __syncthreads();
        if (kc + 1 < NCH) {
            const float* nb = base + (kc + 1) * 32 * 128;
            v0 = __ldcg((const float4*)(nb + s0k * 128) + sq);
            v1 = __ldcg((const float4*)(nb + s1k * 128) + sq);
        }
        const float* buf = sAct + (kc & 1) * 2048;
        const float* wk  = sW + kc * 32 * 8 + ch * 2;
#pragma unroll
        for (int k = 0; k < 32; k++) {
            float a = buf[k * 64 + r];
            fma2(acc, pack2(a, a), *(const u64*)(wk + k * 8));
        }
        __syncthreads();
    }
    return unpack2(acc);
}

// ---- stage 3 half: one m-tile per warp, 8 n-tiles ----
__device__ __forceinline__ void stage3_half(const uint4* __restrict__ fAh,
                                            const uint4* __restrict__ fAl,
                                            const uint4* __restrict__ sFragB,
                                            const float* __restrict__ sb3,
                                            int mtg, int nhalf, int lane, int t4,
                                            const float dxr[2][8], float kq[2][2]) {
    float acc[8][4];
#pragma unroll
    for (int nt = 0; nt < 8; nt++) {
        float bx = sb3[(nhalf * 8 + nt) * 8 + t4 * 2];
        float by = sb3[(nhalf * 8 + nt) * 8 + t4 * 2 + 1];
        acc[nt][0] = bx; acc[nt][1] = by;
        acc[nt][2] = bx; acc[nt][3] = by;
    }
    uint4 ah = __ldcg(fAh + mtg * 32 + lane);
    uint4 al = __ldcg(fAl + mtg * 32 + lane);
#pragma unroll 1
    for (int kt = 0; kt < 16; kt++) {
        uint4 ahn, aln;
        if (kt < 15) {
            ahn = __ldcg(fAh + ((kt + 1) * 8 + mtg) * 32 + lane);
            aln = __ldcg(fAl + ((kt + 1) * 8 + mtg) * 32 + lane);
        }
        const uint4* bfr = sFragB + (kt * 16 + nhalf * 8) * 32 + lane;
#pragma unroll
        for (int nt = 0; nt < 8; nt++) {
            uint4 b = bfr[nt * 32];
            mma16816(acc[nt], ah, b.x, b.y);
            mma16816(acc[nt], ah, b.z, b.w);
            mma16816(acc[nt], al, b.x, b.y);
        }
        ah = ahn; al = aln;
    }
    kq[0][0] = 0.f; kq[0][1] = 0.f; kq[1][0] = 0.f; kq[1][1] = 0.f;
#pragma unroll
    for (int nt = 0; nt < 8; nt++) {
        int hli = nt >> 2, qb = (nt & 3) * 2;
        float y;
        y = fast_tanh(acc[nt][0]); kq[0][hli] = fmaf(y, dxr[0][qb],     kq[0][hli]);
        y = fast_tanh(acc[nt][1]); kq[0][hli] = fmaf(y, dxr[0][qb + 1], kq[0][hli]);
        y = fast_tanh(acc[nt][2]); kq[1][hli] = fmaf(y, dxr[1][qb],     kq[1][hli]);
        y = fast_tanh(acc[nt][3]); kq[1][hli] = fmaf(y, dxr[1][qb + 1], kq[1][hli]);
    }
#pragma unroll
    for (int rs = 0; rs < 2; rs++)
#pragma unroll
        for (int h = 0; h < 2; h++) {
            kq[rs][h] += __shfl_xor_sync(0xffffffffu, kq[rs][h], 1);
            kq[rs][h] += __shfl_xor_sync(0xffffffffu, kq[rs][h], 2);
        }
}

// ================= persistent kernel =================
__global__ void __launch_bounds__(TPB, 1)
cde_persistent(const float* __restrict__ t, const float* __restrict__ z0,
               const float* __restrict__ X,
               const float* __restrict__ W1, const float* __restrict__ b1,
               const float* __restrict__ W2, const float* __restrict__ b2,
               const float* __restrict__ W3, const float* __restrict__ b3,
               const float* __restrict__ mW, const float* __restrict__ mb,
               const float* __restrict__ sWp, const float* __restrict__ sbp,
               float* __restrict__ out) {
    extern __shared__ char smb[];
    uint4* sFragB = (uint4*)(smb + SM_FRAGB);
    float* sW1  = (float*)(smb + SM_W1);
    float* sW2  = (float*)(smb + SM_W2);
    float* sb3  = (float*)(smb + SM_B3);
    float* sb1  = (float*)(smb + SM_B1);
    float* sb2  = (float*)(smb + SM_B2);
    float* smW  = (float*)(smb + SM_MW);
    float* ssW  = (float*)(smb + SM_SW);
    float* smb_ = (float*)(smb + SM_MB);
    float* ssb  = (float*)(smb + SM_SB);
    float* sAct = (float*)(smb + SM_ACT);

    const int tid  = threadIdx.x;
    const int wid  = tid >> 5;
    const int lane = tid & 31;
    const int bb   = blockIdx.x >> 5;
    const int g    = blockIdx.x & 31;
    const int rowBase = bb * 128;

    PadCnt* C = &g_c6[bb][0];

    // ---- init: W3 slice -> B fragments (hi/lo) in smem ----
    for (int i = tid; i < 16 * 16 * 32; i += TPB) {
        int ln = i & 31, nt = (i >> 5) & 15, kt = i >> 9;
        int nl = nt * 8 + (ln >> 2);
        int k0 = kt * 16 + (ln & 3) * 2;
        const float* wp = W3 + (size_t)k0 * 4096 + g * 128 + nl;
        unsigned short h0, h1, h8, h9, l0, l1, l8, l9;
        bf_split(wp[0],        h0, l0);
        bf_split(wp[4096],     h1, l1);
        bf_split(wp[8 * 4096], h8, l8);
        bf_split(wp[9 * 4096], h9, l9);
        uint4 v;
        v.x = ((u32)h1 << 16) | h0;
        v.y = ((u32)h9 << 16) | h8;
        v.z = ((u32)l1 << 16) | l0;
        v.w = ((u32)l9 << 16) | l8;
        sFragB[i] = v;
    }
    for (int i = tid; i < 128 * 2; i += TPB) {
        int k = i >> 1, c4 = i & 1;
        *(float4*)(sW1 + k * 8 + c4 * 4) =
            __ldg((const float4*)(W1 + (size_t)k * 256 + g * 8) + c4);
    }
    for (int i = tid; i < 256 * 2; i += TPB) {
        int k = i >> 1, c4 = i & 1;
        *(float4*)(sW2 + k * 8 + c4 * 4) =
            __ldg((const float4*)(W2 + (size_t)k * 256 + g * 8) + c4);
    }
    for (int i = tid; i < 128; i += TPB) sb3[i] = __ldg(&b3[g * 128 + i]);
    if (tid < 8)  sb1[tid] = __ldg(&b1[g * 8 + tid]);
    if (tid >= 8 && tid < 16) sb2[tid - 8] = __ldg(&b2[g * 8 + tid - 8]);
    for (int i = tid; i < 256; i += TPB) {
        int h = i >> 1, c = i & 1;
        smW[i] = __ldg(&mW[(size_t)h * 64 + g * 2 + c]);
        ssW[i] = __ldg(&sWp[(size_t)h * 64 + g * 2 + c]);
    }
    if (tid < 2)  smb_[tid] = __ldg(&mb[g * 2 + tid]);
    if (tid >= 2 && tid < 4) ssb[tid - 2] = __ldg(&sbp[g * 2 + tid - 2]);
    __syncthreads();

    // ---- warp-local RK state ----
    // warp (mt = wid&3, nhalf = wid>>2) owns rows hf*64 + mt*16 + rsub (+8)
    // and h cols g*4 + nhalf*2 + {0,1}.
    const int mt    = wid & 3;
    const int nhalf = wid >> 2;
    const int rsub  = lane >> 2;
    const int t4    = lane & 3;
    const int rloc  = mt * 16 + rsub;           // local row (within half), rowset 0

    float zb[2][2][2];                          // [half][rowset][hl]
#pragma unroll
    for (int hf = 0; hf < 2; hf++)
#pragma unroll
        for (int rs = 0; rs < 2; rs++) {
            int row = rowBase + hf * 64 + rloc + rs * 8;
            float2 z = __ldg((const float2*)&z0[(size_t)row * 128 + g * 4 + nhalf * 2]);
            zb[hf][rs][0] = z.x;
            zb[hf][rs][1] = z.y;
        }

    const size_t zOff  = (size_t)bb * (NH * 128);
    const size_t h1Off = (size_t)bb * (NBN * 128);

    unsigned phz = 1, ph1 = 0, ph2 = 0;

    // ---- bootstrap: publish z0 (parity 1) ----
    if (t4 < 2) {
        float* zc = &g_zc[1][zOff + (size_t)(g * 4 + nhalf * 2 + t4) * 128];
#pragma unroll
        for (int hf = 0; hf < 2; hf++) {
            __stcg(zc + hf * 64 + rloc,     zb[hf][0][t4]);
            __stcg(zc + hf * 64 + rloc + 8, zb[hf][1][t4]);
        }
    }
    publish_cnt(&C[0]);
    publish_cnt(&C[1]);

    // stage2 fragment constants (r = global row within bb, 2 cols per thread)
    const int s2r  = tid & 63;                   // local row within half
    const int s2ch = tid >> 6;                   // 0..3 -> cols ch*2
    const int s2kt = g >> 1;
    const int s2reg_base = 2 * (g & 1);

#pragma unroll 1
    for (int tau = 0; tau < NIVL; tau++) {
        float t0v = __ldg(&t[tau]);
        float t1v = __ldg(&t[tau + 1]);
        float dti = t1v - t0v;
        float hstep = dti * 0.25f;
        float h6 = hstep / 6.0f;

        // dxdt into registers: [half][rowset][8] (i-slice by t4)
        float dxm[2][2][8];
#pragma unroll
        for (int hf = 0; hf < 2; hf++)
#pragma unroll
            for (int rs = 0; rs < 2; rs++) {
                int row = rowBase + hf * 64 + rloc + rs * 8;
                const float* Xr = X + ((size_t)row * NTT + tau) * NIN;
#pragma unroll
                for (int blk = 0; blk < 4; blk++) {
                    float2 x0 = __ldg((const float2*)(Xr + blk * 8 + t4 * 2));
                    float2 x1 = __ldg((const float2*)(Xr + NIN + blk * 8 + t4 * 2));
                    dxm[hf][rs][blk * 2 + 0] = (x1.x - x0.x) / dti;
                    dxm[hf][rs][blk * 2 + 1] = (x1.y - x0.y) / dti;
                }
            }

#pragma unroll 1
        for (int sub = 0; sub < 4; sub++) {
            float aacc[2][2][2] = {};
#pragma unroll 1
            for (int s = 0; s < 4; s++) {
                const int pz = phz & 1;
                ++ph1; const int p1 = ph1 & 1;

                // ---- stage 1: halves A, B ----
                wait_cnt(&C[0], phz * NGRP);
                {
                    float2 o = mlp_half<128>(&g_zc[pz][zOff], 0, sW1, sb1, sAct, tid);
                    float* gout = &g_h1[p1][h1Off + (size_t)(g * 8 + s2ch * 2) * 128];
                    __stcg(gout + s2r,       fmaxf(o.x, 0.f));
                    __stcg(gout + 128 + s2r, fmaxf(o.y, 0.f));
                }
                publish_cnt(&C[2]);
                wait_cnt(&C[1], phz * NGRP);
                {
                    float2 o = mlp_half<128>(&g_zc[pz][zOff], 1, sW1, sb1, sAct, tid);
                    float* gout = &g_h1[p1][h1Off + (size_t)(g * 8 + s2ch * 2) * 128 + 64];
                    __stcg(gout + s2r,       fmaxf(o.x, 0.f));
                    __stcg(gout + 128 + s2r, fmaxf(o.y, 0.f));
                }
                publish_cnt(&C[3]);

                ++ph2; const int p2 = ph2 & 1;
                u32* fHi = (u32*)&g_fAhi[p2][bb][0];
                u32* fLo = (u32*)&g_fAlo[p2][bb][0];

                // ---- stage 2: halves A, B -> A fragments ----
#pragma unroll 1
                for (int hf = 0; hf < 2; hf++) {
                    wait_cnt(&C[2 + hf], ph1 * NGRP);
                    float2 o = mlp_half<256>(&g_h1[p1][h1Off], hf, sW2, sb2, sAct, tid);
                    float o0 = fmaxf(o.x, 0.f), o1 = fmaxf(o.y, 0.f);
                    unsigned short hh0, hh1, ll0, ll1;
                    bf_split(o0, hh0, ll0);
                    bf_split(o1, hh1, ll1);
                    int rg  = hf * 64 + s2r;
                    int mtg = rg >> 4;
                    int lnf = (rg & 7) * 4 + s2ch;
                    int reg = ((rg >> 3) & 1) + s2reg_base;
                    int idx = ((s2kt * 8 + mtg) * 32 + lnf) * 4 + reg;
                    __stcg(&fHi[idx], ((u32)hh1 << 16) | hh0);
                    __stcg(&fLo[idx], ((u32)ll1 << 16) | ll0);
                    publish_cnt(&C[4 + hf]);
                }

                ++phz; const int pzn = phz & 1;
                const float ws = (s == 0 || s == 3) ? 1.f : 2.f;
                const float cnext = (s == 2) ? hstep : 0.5f * hstep;

                // ---- stage 3 + RK + z-publish: halves A, B ----
#pragma unroll 1
                for (int hf = 0; hf < 2; hf++) {
                    wait_cnt(&C[4 + hf], ph2 * NGRP);
                    float kq[2][2];
                    stage3_half(&g_fAhi[p2][bb][0], &g_fAlo[p2][bb][0],
                                sFragB, sb3, hf * 4 + mt, nhalf, lane, t4,
                                dxm[hf], kq);
                    float zn[2][2];
#pragma unroll
                    for (int rs = 0; rs < 2; rs++)
#pragma unroll
                        for (int h = 0; h < 2; h++) {
                            aacc[hf][rs][h] = fmaf(ws, kq[rs][h], aacc[hf][rs][h]);
                            if (s < 3) {
                                zn[rs][h] = fmaf(cnext, kq[rs][h], zb[hf][rs][h]);
                            } else {
                                zb[hf][rs][h] = fmaf(h6, aacc[hf][rs][h], zb[hf][rs][h]);
                                zn[rs][h] = zb[hf][rs][h];
                            }
                        }
                    if (t4 < 2) {
                        float v0 = (t4 == 0) ? zn[0][0] : zn[0][1];
                        float v1 = (t4 == 0) ? zn[1][0] : zn[1][1];
                        float* zc = &g_zc[pzn][zOff + (size_t)(g * 4 + nhalf * 2 + t4) * 128];
                        __stcg(zc + hf * 64 + rloc,     v0);
                        __stcg(zc + hf * 64 + rloc + 8, v1);
                    }
                    publish_cnt(&C[hf]);
                }
            }
        }

        // ---- interval end: heads (z already published by last stage3) ----
        wait_cnt(&C[0], phz * NGRP);
        wait_cnt(&C[1], phz * NGRP);
        {
            const int r  = tid & 127;
            const int hh = tid >> 7;
            const int b  = rowBase + r;
            const float* wsel = hh ? ssW : smW;
            float acc0 = hh ? ssb[0] : smb_[0];
            float acc1 = hh ? ssb[1] : smb_[1];
            const float* zbase = &g_zc[phz & 1][zOff];
#pragma unroll 8
            for (int h = 0; h < 128; h++) {
                float zv = __ldcg(zbase + (size_t)h * 128 + r);
                acc0 = fmaf(zv, wsel[h * 2 + 0], acc0);
                acc1 = fmaf(zv, wsel[h * 2 + 1], acc1);
            }
            if (hh) { acc0 = softplus_f(acc0); acc1 = softplus_f(acc1); }
            float* dst = out + (hh ? (size_t)NBATCH * NIVL * NOUT : 0)
                         + ((size_t)b * NIVL + tau) * NOUT + g * 2;
            dst[0] = acc0;
            dst[1] = acc1;
        }
    }

    // ---- end-of-kernel reset for deterministic graph replay ----
    gbar_val(bb, 1u);
    if (tid == 0 && g == 0) {
#pragma unroll
        for (int q = 0; q < 6; q++) g_c6[bb][q].v = 0u;
    }
    gbar_val(bb, 0u);
}

extern "C" void kernel_launch(void* const* d_in, const int* in_sizes, int n_in,
                              void* d_out, int out_size) {
    const float* t   = (const float*)d_in[0];
    const float* z0  = (const float*)d_in[1];
    const float* X   = (const float*)d_in[2];
    const float* W1  = (const float*)d_in[3];
    const float* b1  = (const float*)d_in[4];
    const float* W2  = (const float*)d_in[5];
    const float* b2  = (const float*)d_in[6];
    const float* W3  = (const float*)d_in[7];
    const float* b3  = (const float*)d_in[8];
    const float* mW  = (const float*)d_in[9];
    const float* mb  = (const float*)d_in[10];
    const float* sW  = (const float*)d_in[11];
    const float* sb  = (const float*)d_in[12];
    float* out = (float*)d_out;

    cudaFuncSetAttribute(cde_persistent,
                         cudaFuncAttributeMaxDynamicSharedMemorySize, SMEM_BYTES);
    cde_persistent<<<GRID_CTAS, TPB, SMEM_BYTES>>>(t, z0, X, W1, b1, W2, b2,
                                                   W3, b3, mW, mb, sW, sb, out);
}

// round 11
// speedup vs baseline: 1.4578x; 1.4578x over previous
#include <cuda_runtime.h>
#include <cuda_bf16.h>

typedef unsigned long long u64;
typedef unsigned int u32;

#define NBATCH 512
#define NTT    257
#define NIVL   256
#define NIN    32
#define NH     128
#define NBN    256
#define NOUT   64
#define GRID_CTAS 128
#define TPB    256
#define NGRP   32

// ---- shared memory byte offsets ----
#define SM_FRAGB 0          // [16 kt][16 nt][32 lane] uint4 = 128KB
#define SM_W1    131072     // [128][8] f32
#define SM_W2    135168     // [256][8] f32
#define SM_B3    143360     // [128] f32
#define SM_B1    143872     // [8]
#define SM_B2    143904     // [8]
#define SM_MW    143936     // [128][2]
#define SM_SW    144960     // [128][2]
#define SM_MB    145984     // [2]
#define SM_SB    145992     // [2] (+pad)
#define SM_DX    146016     // [128][36] f32 = 18432B
#define SM_ACT   164448     // 2 x 4096 f32 staging (32KB)
#define SMEM_BYTES 197216

// ---- global scratch (parity double-buffered) ----
__device__ float g_zc[2][4 * NH * 128];    // col-major [h][r] per bb
__device__ float g_h1[2][4 * NBN * 128];   // col-major [c][r] per bb
__device__ uint4 g_fAhi[2][4][4096];       // A frags [(kt*8+mt)*32+lane]
__device__ uint4 g_fAlo[2][4][4096];

// ---- arrive counters: [bb][0=z 1=h1 2=h2] ----
struct PadCnt { unsigned v; unsigned pad[127]; };
__device__ PadCnt g_cc[4][3];

struct PadU { unsigned v; unsigned pad[31]; };
__device__ PadU g_cnt[4];
__device__ PadU g_rel[4];

// ---- helpers ----
__device__ __forceinline__ u64 pack2(float x, float y) {
    u64 r;
    asm("mov.b64 %0, {%1, %2};" : "=l"(r) : "f"(x), "f"(y));
    return r;
}
__device__ __forceinline__ float2 unpack2(u64 v) {
    float2 r;
    asm("mov.b64 {%0, %1}, %2;" : "=f"(r.x), "=f"(r.y) : "l"(v));
    return r;
}
__device__ __forceinline__ void fma2(u64& d, u64 a, u64 b) {
    asm("fma.rn.f32x2 %0, %1, %2, %0;" : "+l"(d) : "l"(a), "l"(b));
}
__device__ __forceinline__ float fast_tanh(float x) {
    float e;
    asm("ex2.approx.f32 %0, %1;" : "=f"(e) : "f"(x * 2.8853900817779268f));
    float r;
    asm("rcp.approx.f32 %0, %1;" : "=f"(r) : "f"(e + 1.0f));
    return fmaf(-2.0f, r, 1.0f);
}
__device__ __forceinline__ float softplus_f(float x) {
    return fmaxf(x, 0.0f) + log1pf(expf(-fabsf(x)));
}
__device__ __forceinline__ void mma16816(float* c, uint4 a, u32 b0, u32 b1) {
    asm volatile(
        "mma.sync.aligned.m16n8k16.row.col.f32.bf16.bf16.f32 "
        "{%0,%1,%2,%3}, {%4,%5,%6,%7}, {%8,%9}, {%0,%1,%2,%3};"
        : "+f"(c[0]), "+f"(c[1]), "+f"(c[2]), "+f"(c[3])
        : "r"(a.x), "r"(a.y), "r"(a.z), "r"(a.w), "r"(b0), "r"(b1));
}
__device__ __forceinline__ void bf_split(float x, unsigned short& h, unsigned short& l) {
    __nv_bfloat16 bh = __float2bfloat16_rn(x);
    __nv_bfloat16 bl = __float2bfloat16_rn(x - __bfloat162float(bh));
    h = __bfloat16_as_ushort(bh);
    l = __bfloat16_as_ushort(bl);
}

// ---- counter publish / wait (R6-proven) ----
__device__ __forceinline__ void publish_cnt(PadCnt* c) {
    __syncthreads();
    if (threadIdx.x == 0) {
        asm volatile("red.release.gpu.global.add.u32 [%0], %1;"
                     :: "l"(&c->v), "r"(1u) : "memory");
    }
}
__device__ __forceinline__ void wait_cnt(PadCnt* c, unsigned target) {
    if (threadIdx.x == 0) {
        unsigned v;
        do {
            asm volatile("ld.acquire.gpu.u32 %0, [%1];"
                         : "=r"(v) : "l"(&c->v) : "memory");
        } while ((int)(v - target) < 0);
    }
    __syncthreads();
}
__device__ __forceinline__ void gbar_val(int grp, unsigned target) {
    __syncthreads();
    if (threadIdx.x == 0) {
        __threadfence();
        unsigned old = atomicAdd(&g_cnt[grp].v, 1u);
        if (old == (NGRP - 1u)) {
            g_cnt[grp].v = 0u;
            asm volatile("st.release.gpu.u32 [%0], %1;"
                         :: "l"(&g_rel[grp].v), "r"(target) : "memory");
        } else {
            unsigned v;
            do {
                asm volatile("ld.acquire.gpu.u32 %0, [%1];"
                             : "=r"(v) : "l"(&g_rel[grp].v) : "memory");
            } while (v != target);
        }
    }
    __syncthreads();
}

// ---- stage 1: h1[8 cols col-major] = relu(z @ W1slice + b1) [R6 verbatim] ----
__device__ __forceinline__ void stage1(const float* __restrict__ gin_cm,
                                       const float* __restrict__ sW,
                                       const float* __restrict__ sb,
                                       float* __restrict__ gout_cm,
                                       float* __restrict__ sAct, int tid) {
    const int r  = tid & 127;
    const int ch = tid >> 7;
    u64 acc0 = pack2(sb[ch * 4 + 0], sb[ch * 4 + 1]);
    u64 acc1 = pack2(sb[ch * 4 + 2], sb[ch * 4 + 3]);

    const float4* src = (const float4*)gin_cm;
    float4 v0 = __ldcg(src + 0 * 256 + tid);
    float4 v1 = __ldcg(src + 1 * 256 + tid);
    float4 v2 = __ldcg(src + 2 * 256 + tid);
    float4 v3 = __ldcg(src + 3 * 256 + tid);

#pragma unroll 1
    for (int kc = 0; kc < 4; kc++) {
        float4* buf4 = (float4*)(sAct + (kc & 1) * 4096);
        buf4[0 * 256 + tid] = v0;
        buf4[1 * 256 + tid] = v1;
        buf4[2 * 256 + tid] = v2;
        buf4[3 * 256 + tid] = v3;
        __syncthreads();
        if (kc + 1 < 4) {
            const float4* sn = src + (kc + 1) * 1024;
            v0 = __ldcg(sn + 0 * 256 + tid);
            v1 = __ldcg(sn + 1 * 256 + tid);
            v2 = __ldcg(sn + 2 * 256 + tid);
            v3 = __ldcg(sn + 3 * 256 + tid);
        }
        const float* buf = sAct + (kc & 1) * 4096;
        const float* wk  = sW + kc * 32 * 8 + ch * 4;
#pragma unroll
        for (int k = 0; k < 32; k++) {
            float a = buf[k * 128 + r];
            u64 aa  = pack2(a, a);
            ulonglong2 w = *(const ulonglong2*)(wk + k * 8);
            fma2(acc0, aa, w.x);
            fma2(acc1, aa, w.y);
        }
        __syncthreads();
    }
    float2 u0 = unpack2(acc0), u1 = unpack2(acc1);
    __stcg(gout_cm + (ch * 4 + 0) * 128 + r, fmaxf(u0.x, 0.f));
    __stcg(gout_cm + (ch * 4 + 1) * 128 + r, fmaxf(u0.y, 0.f));
    __stcg(gout_cm + (ch * 4 + 2) * 128 + r, fmaxf(u1.x, 0.f));
    __stcg(gout_cm + (ch * 4 + 3) * 128 + r, fmaxf(u1.y, 0.f));
}

// ---- stage 2: h2 cols -> bf16 hi/lo mma A-fragments in gmem [R6 verbatim] ----
__device__ __forceinline__ void stage2_frag(const float* __restrict__ gin_cm,
                                            const float* __restrict__ sW,
                                            const float* __restrict__ sb,
                                            u32* __restrict__ fHi,
                                            u32* __restrict__ fLo,
                                            int g, float* __restrict__ sAct, int tid) {
    const int r  = tid & 127;
    const int ch = tid >> 7;
    u64 acc0 = pack2(sb[ch * 4 + 0], sb[ch * 4 + 1]);
    u64 acc1 = pack2(sb[ch * 4 + 2], sb[ch * 4 + 3]);

    const float4* src = (const float4*)gin_cm;
    float4 v0 = __ldcg(src + 0 * 256 + tid);
    float4 v1 = __ldcg(src + 1 * 256 + tid);
    float4 v2 = __ldcg(src + 2 * 256 + tid);
    float4 v3 = __ldcg(src + 3 * 256 + tid);

#pragma unroll 1
    for (int kc = 0; kc < 8; kc++) {
        float4* buf4 = (float4*)(sAct + (kc & 1) * 4096);
        buf4[0 * 256 + tid] = v0;
        buf4[1 * 256 + tid] = v1;
        buf4[2 * 256 + tid] = v2;
        buf4[3 * 256 + tid] = v3;
        __syncthreads();
        if (kc + 1 < 8) {
            const float4* sn = src + (kc + 1) * 1024;
            v0 = __ldcg(sn + 0 * 256 + tid);
            v1 = __ldcg(sn + 1 * 256 + tid);
            v2 = __ldcg(sn + 2 * 256 + tid);
            v3 = __ldcg(sn + 3 * 256 + tid);
        }
        const float* buf = sAct + (kc & 1) * 4096;
        const float* wk  = sW + kc * 32 * 8 + ch * 4;
#pragma unroll
        for (int k = 0; k < 32; k++) {
            float a = buf[k * 128 + r];
            u64 aa  = pack2(a, a);
            ulonglong2 w = *(const ulonglong2*)(wk + k * 8);
            fma2(acc0, aa, w.x);
            fma2(acc1, aa, w.y);
        }
        __syncthreads();
    }
    float2 u0 = unpack2(acc0), u1 = unpack2(acc1);
    float o0 = fmaxf(u0.x, 0.f), o1 = fmaxf(u0.y, 0.f);
    float o2 = fmaxf(u1.x, 0.f), o3 = fmaxf(u1.y, 0.f);

    unsigned short h0, h1, h2, h3, l0, l1, l2, l3;
    bf_split(o0, h0, l0); bf_split(o1, h1, l1);
    bf_split(o2, h2, l2); bf_split(o3, h3, l3);
    u32 hi01 = ((u32)h1 << 16) | h0;
    u32 hi23 = ((u32)h3 << 16) | h2;
    u32 lo01 = ((u32)l1 << 16) | l0;
    u32 lo23 = ((u32)l3 << 16) | l2;

    const int kt   = g >> 1;
    const int mt   = r >> 4;
    const int lane = (r & 7) * 4 + 2 * ch;
    const int reg  = ((r >> 3) & 1) + 2 * (g & 1);
    const int idx0 = ((kt * 8 + mt) * 32 + lane) * 4 + reg;
    __stcg(&fHi[idx0], hi01);
    __stcg(&fHi[idx0 + 4], hi23);
    __stcg(&fLo[idx0], lo01);
    __stcg(&fLo[idx0 + 4], lo23);
}

// ================= persistent kernel =================
__global__ void __launch_bounds__(TPB, 1)
cde_persistent(const float* __restrict__ t, const float* __restrict__ z0,
               const float* __restrict__ X,
               const float* __restrict__ W1, const float* __restrict__ b1,
               const float* __restrict__ W2, const float* __restrict__ b2,
               const float* __restrict__ W3, const float* __restrict__ b3,
               const float* __restrict__ mW, const float* __restrict__ mb,
               const float* __restrict__ sWp, const float* __restrict__ sbp,
               float* __restrict__ out) {
    extern __shared__ char smb[];
    uint4* sFragB = (uint4*)(smb + SM_FRAGB);
    float* sW1  = (float*)(smb + SM_W1);
    float* sW2  = (float*)(smb + SM_W2);
    float* sb3  = (float*)(smb + SM_B3);
    float* sb1  = (float*)(smb + SM_B1);
    float* sb2  = (float*)(smb + SM_B2);
    float* smW  = (float*)(smb + SM_MW);
    float* ssW  = (float*)(smb + SM_SW);
    float* smb_ = (float*)(smb + SM_MB);
    float* ssb  = (float*)(smb + SM_SB);
    float* sDx  = (float*)(smb + SM_DX);
    float* sAct = (float*)(smb + SM_ACT);

    const int tid  = threadIdx.x;
    const int wid  = tid >> 5;
    const int lane = tid & 31;
    const int bb   = blockIdx.x >> 5;
    const int g    = blockIdx.x & 31;
    const int rowBase = bb * 128;

    PadCnt* Cz = &g_cc[bb][0];
    PadCnt* C1 = &g_cc[bb][1];
    PadCnt* C2 = &g_cc[bb][2];

    // ---- init: W3 slice -> B fragments (hi/lo) in smem ----
    for (int i = tid; i < 16 * 16 * 32; i += TPB) {
        int ln = i & 31, nt = (i >> 5) & 15, kt = i >> 9;
        int nl = nt * 8 + (ln >> 2);
        int k0 = kt * 16 + (ln & 3) * 2;
        const float* wp = W3 + (size_t)k0 * 4096 + g * 128 + nl;
        unsigned short h0, h1, h8, h9, l0, l1, l8, l9;
        bf_split(wp[0],        h0, l0);
        bf_split(wp[4096],     h1, l1);
        bf_split(wp[8 * 4096], h8, l8);
        bf_split(wp[9 * 4096], h9, l9);
        uint4 v;
        v.x = ((u32)h1 << 16) | h0;
        v.y = ((u32)h9 << 16) | h8;
        v.z = ((u32)l1 << 16) | l0;
        v.w = ((u32)l9 << 16) | l8;
        sFragB[i] = v;
    }
    for (int i = tid; i < 128 * 2; i += TPB) {
        int k = i >> 1, c4 = i & 1;
        *(float4*)(sW1 + k * 8 + c4 * 4) =
            __ldg((const float4*)(W1 + (size_t)k * 256 + g * 8) + c4);
    }
    for (int i = tid; i < 256 * 2; i += TPB) {
        int k = i >> 1, c4 = i & 1;
        *(float4*)(sW2 + k * 8 + c4 * 4) =
            __ldg((const float4*)(W2 + (size_t)k * 256 + g * 8) + c4);
    }
    for (int i = tid; i < 128; i += TPB) sb3[i] = __ldg(&b3[g * 128 + i]);
    if (tid < 8)  sb1[tid] = __ldg(&b1[g * 8 + tid]);
    if (tid >= 8 && tid < 16) sb2[tid - 8] = __ldg(&b2[g * 8 + tid - 8]);
    for (int i = tid; i < 256; i += TPB) {
        int h = i >> 1, c = i & 1;
        smW[i] = __ldg(&mW[(size_t)h * 64 + g * 2 + c]);
        ssW[i] = __ldg(&sWp[(size_t)h * 64 + g * 2 + c]);
    }
    if (tid < 2)  smb_[tid] = __ldg(&mb[g * 2 + tid]);
    if (tid >= 2 && tid < 4) ssb[tid - 2] = __ldg(&sbp[g * 2 + tid - 2]);
    __syncthreads();

    // ---- warp-local RK state (redundant across quad lanes) ----
    // warp: m = wid&3 (rows m*32..+31, mtiles 2m,2m+1), nh = wid>>2 (h cols nh*2,nh*2+1)
    const int m    = wid & 3;
    const int nh   = wid >> 2;
    const int rsub = lane >> 2;
    const int t4   = lane & 3;
    const int mbase = m * 32;

    float zb[2][2][2];    // [mti][rp][hl]
#pragma unroll
    for (int mti = 0; mti < 2; mti++)
#pragma unroll
        for (int rp = 0; rp < 2; rp++) {
            int row = rowBase + mbase + mti * 16 + rsub + rp * 8;
            float2 z = __ldg((const float2*)&z0[(size_t)row * 128 + g * 4 + nh * 2]);
            zb[mti][rp][0] = z.x;
            zb[mti][rp][1] = z.y;
        }

    const size_t zOff  = (size_t)bb * (NH * 128);
    const size_t h1Off = (size_t)bb * (NBN * 128);

    // ---- bootstrap: publish z0 at parity 1 ----
    if (t4 < 2) {
        float* zc = &g_zc[1][zOff + (size_t)(g * 4 + nh * 2 + t4) * 128];
#pragma unroll
        for (int mti = 0; mti < 2; mti++)
#pragma unroll
            for (int rp = 0; rp < 2; rp++)
                __stcg(zc + mbase + mti * 16 + rsub + rp * 8, zb[mti][rp][t4]);
    }
    publish_cnt(Cz);
    unsigned cz = 1, c1 = 0, c2 = 0;

#pragma unroll 1
    for (int tau = 0; tau < NIVL; tau++) {
        float t0v = __ldg(&t[tau]);
        float t1v = __ldg(&t[tau + 1]);
        float dti = t1v - t0v;
        float hstep = dti * 0.25f;
        float h6 = hstep / 6.0f;
        __syncthreads();
        for (int i = tid; i < 1024; i += TPB) {
            int rr = i >> 3, q = i & 7;
            const float* Xr = X + ((size_t)(rowBase + rr) * NTT + tau) * NIN;
            float4 x0 = __ldg((const float4*)Xr + q);
            float4 x1 = __ldg((const float4*)(Xr + NIN) + q);
            float* d = sDx + rr * 36 + q * 4;
            d[0] = (x1.x - x0.x) / dti;
            d[1] = (x1.y - x0.y) / dti;
            d[2] = (x1.z - x0.z) / dti;
            d[3] = (x1.w - x0.w) / dti;
        }
        __syncthreads();

#pragma unroll 1
        for (int sub = 0; sub < 4; sub++) {
            float aacc[2][2][2] = {};
#pragma unroll 1
            for (int s = 0; s < 4; s++) {
                // z for this stage published by previous stage3 (or bootstrap)
                wait_cnt(Cz, cz * NGRP);
                const int pz = cz & 1;

                // stage 1
                ++c1; const int p1 = c1 & 1;
                stage1(&g_zc[pz][zOff], sW1, sb1,
                       &g_h1[p1][h1Off + (size_t)(g * 8) * 128], sAct, tid);
                publish_cnt(C1);
                wait_cnt(C1, c1 * NGRP);

                // stage 2 -> A fragments
                ++c2; const int p2 = c2 & 1;
                stage2_frag(&g_h1[p1][h1Off], sW2, sb2,
                            (u32*)&g_fAhi[p2][bb][0], (u32*)&g_fAlo[p2][bb][0],
                            g, sAct, tid);
                publish_cnt(C2);
                wait_cnt(C2, c2 * NGRP);

                // ---- stage 3: mma, 2 m-tiles x 8 n-tiles per warp ----
                float acc[2][8][4];
#pragma unroll
                for (int nt = 0; nt < 8; nt++) {
                    float bx = sb3[nh * 64 + nt * 8 + t4 * 2];
                    float by = sb3[nh * 64 + nt * 8 + t4 * 2 + 1];
                    acc[0][nt][0] = bx; acc[0][nt][1] = by;
                    acc[0][nt][2] = bx; acc[0][nt][3] = by;
                    acc[1][nt][0] = bx; acc[1][nt][1] = by;
                    acc[1][nt][2] = bx; acc[1][nt][3] = by;
                }
                const uint4* fAh = &g_fAhi[p2][bb][0];
                const uint4* fAl = &g_fAlo[p2][bb][0];
                uint4 a0h = __ldcg(fAh + (0 * 8 + 2 * m + 0) * 32 + lane);
                uint4 a0l = __ldcg(fAl + (0 * 8 + 2 * m + 0) * 32 + lane);
                uint4 a1h = __ldcg(fAh + (0 * 8 + 2 * m + 1) * 32 + lane);
                uint4 a1l = __ldcg(fAl + (0 * 8 + 2 * m + 1) * 32 + lane);
#pragma unroll 1
                for (int kt = 0; kt < 16; kt++) {
                    uint4 n0h, n0l, n1h, n1l;
                    if (kt < 15) {
                        n0h = __ldcg(fAh + ((kt + 1) * 8 + 2 * m + 0) * 32 + lane);
                        n0l = __ldcg(fAl + ((kt + 1) * 8 + 2 * m + 0) * 32 + lane);
                        n1h = __ldcg(fAh + ((kt + 1) * 8 + 2 * m + 1) * 32 + lane);
                        n1l = __ldcg(fAl + ((kt + 1) * 8 + 2 * m + 1) * 32 + lane);
                    }
                    const uint4* bfr = sFragB + (kt * 16 + nh * 8) * 32 + lane;
#pragma unroll
                    for (int nt = 0; nt < 8; nt++) {
                        uint4 b = bfr[nt * 32];
                        mma16816(acc[0][nt], a0h, b.x, b.y);
                        mma16816(acc[0][nt], a0h, b.z, b.w);
                        mma16816(acc[0][nt], a0l, b.x, b.y);
                        mma16816(acc[1][nt], a1h, b.x, b.y);
                        mma16816(acc[1][nt], a1h, b.z, b.w);
                        mma16816(acc[1][nt], a1l, b.x, b.y);
                    }
                    a0h = n0h; a0l = n0l; a1h = n1h; a1l = n1l;
                }

                // ---- epilogue: tanh + dxdt contraction, butterfly over t4 ----
                float kq[2][2][2] = {};
#pragma unroll
                for (int mti = 0; mti < 2; mti++) {
                    const int lr0 = mbase + mti * 16 + rsub;
#pragma unroll
                    for (int nt = 0; nt < 8; nt++) {
                        int hl = nt >> 2, iblk = nt & 3;
                        float2 dxa = *(const float2*)&sDx[lr0 * 36 + iblk * 8 + t4 * 2];
                        float2 dxb = *(const float2*)&sDx[(lr0 + 8) * 36 + iblk * 8 + t4 * 2];
                        float y;
                        y = fast_tanh(acc[mti][nt][0]);
                        kq[mti][0][hl] = fmaf(y, dxa.x, kq[mti][0][hl]);
                        y = fast_tanh(acc[mti][nt][1]);
                        kq[mti][0][hl] = fmaf(y, dxa.y, kq[mti][0][hl]);
                        y = fast_tanh(acc[mti][nt][2]);
                        kq[mti][1][hl] = fmaf(y, dxb.x, kq[mti][1][hl]);
                        y = fast_tanh(acc[mti][nt][3]);
                        kq[mti][1][hl] = fmaf(y, dxb.y, kq[mti][1][hl]);
                    }
                }
#pragma unroll
                for (int mti = 0; mti < 2; mti++)
#pragma unroll
                    for (int rp = 0; rp < 2; rp++)
#pragma unroll
                        for (int hl = 0; hl < 2; hl++) {
                            float v = kq[mti][rp][hl];
                            v += __shfl_xor_sync(0xffffffffu, v, 1);
                            v += __shfl_xor_sync(0xffffffffu, v, 2);
                            kq[mti][rp][hl] = v;
                        }

                // ---- RK update + publish z for next stage ----
                const float ws = (s == 0 || s == 3) ? 1.f : 2.f;
                const float cnext = (s == 2) ? hstep : 0.5f * hstep;
                ++cz; const int pzn = cz & 1;
                float zn[2][2][2];
#pragma unroll
                for (int mti = 0; mti < 2; mti++)
#pragma unroll
                    for (int rp = 0; rp < 2; rp++)
#pragma unroll
                        for (int hl = 0; hl < 2; hl++) {
                            float kv = kq[mti][rp][hl];
                            aacc[mti][rp][hl] = fmaf(ws, kv, aacc[mti][rp][hl]);
                            if (s < 3) {
                                zn[mti][rp][hl] = fmaf(cnext, kv, zb[mti][rp][hl]);
                            } else {
                                zb[mti][rp][hl] = fmaf(h6, aacc[mti][rp][hl],
                                                       zb[mti][rp][hl]);
                                zn[mti][rp][hl] = zb[mti][rp][hl];
                            }
                        }
                if (t4 < 2) {
                    float* zc = &g_zc[pzn][zOff + (size_t)(g * 4 + nh * 2 + t4) * 128];
#pragma unroll
                    for (int mti = 0; mti < 2; mti++)
#pragma unroll
                        for (int rp = 0; rp < 2; rp++)
                            __stcg(zc + mbase + mti * 16 + rsub + rp * 8,
                                   zn[mti][rp][t4]);
                }
                publish_cnt(Cz);
            }
        }

        // ---- interval end: output heads (final z = last stage3 publish) ----
        wait_cnt(Cz, cz * NGRP);
        {
            const int r  = tid & 127;
            const int hh = tid >> 7;
            const int b  = rowBase + r;
            const float* wsel = hh ? ssW : smW;
            float acc0 = hh ? ssb[0] : smb_[0];
            float acc1 = hh ? ssb[1] : smb_[1];
            const float* zbase = &g_zc[cz & 1][zOff];
#pragma unroll 8
            for (int h = 0; h < 128; h++) {
                float zv = __ldcg(zbase + (size_t)h * 128 + r);
                acc0 = fmaf(zv, wsel[h * 2 + 0], acc0);
                acc1 = fmaf(zv, wsel[h * 2 + 1], acc1);
            }
            if (hh) { acc0 = softplus_f(acc0); acc1 = softplus_f(acc1); }
            float* dst = out + (hh ? (size_t)NBATCH * NIVL * NOUT : 0)
                         + ((size_t)b * NIVL + tau) * NOUT + g * 2;
            dst[0] = acc0;
            dst[1] = acc1;
        }
    }

    // ---- end-of-kernel reset for deterministic graph replay ----
    gbar_val(bb, 1u);
    if (tid == 0 && g == 0) {
        g_cc[bb][0].v = 0u;
        g_cc[bb][1].v = 0u;
        g_cc[bb][2].v = 0u;
    }
    gbar_val(bb, 0u);
}

extern "C" void kernel_launch(void* const* d_in, const int* in_sizes, int n_in,
                              void* d_out, int out_size) {
    const float* t   = (const float*)d_in[0];
    const float* z0  = (const float*)d_in[1];
    const float* X   = (const float*)d_in[2];
    const float* W1  = (const float*)d_in[3];
    const float* b1  = (const float*)d_in[4];
    const float* W2  = (const float*)d_in[5];
    const float* b2  = (const float*)d_in[6];
    const float* W3  = (const float*)d_in[7];
    const float* b3  = (const float*)d_in[8];
    const float* mW  = (const float*)d_in[9];
    const float* mb  = (const float*)d_in[10];
    const float* sW  = (const float*)d_in[11];
    const float* sb  = (const float*)d_in[12];
    float* out = (float*)d_out;

    cudaFuncSetAttribute(cde_persistent,
                         cudaFuncAttributeMaxDynamicSharedMemorySize, SMEM_BYTES);
    cde_persistent<<<GRID_CTAS, TPB, SMEM_BYTES>>>(t, z0, X, W1, b1, W2, b2,
                                                   W3, b3, mW, mb, sW, sb, out);
}

// round 12
// speedup vs baseline: 1.4634x; 1.0038x over previous
#include <cuda_runtime.h>
#include <cuda_bf16.h>

typedef unsigned long long u64;
typedef unsigned int u32;

#define NBATCH 512
#define NTT    257
#define NIVL   256
#define NIN    32
#define NH     128
#define NBN    256
#define NOUT   64
#define GRID_CTAS 128
#define TPB    256
#define NGRP   32

// ---- shared memory byte offsets ----
#define SM_FRAGB 0          // [16 kt][16 nt][32 lane] uint4 = 128KB
#define SM_W1    131072     // [128][8] f32
#define SM_W2    135168     // [256][8] f32
#define SM_B3    143360     // [128] f32
#define SM_B1    143872     // [8]
#define SM_B2    143904     // [8]
#define SM_MW    143936     // [128][2]
#define SM_SW    144960     // [128][2]
#define SM_MB    145984     // [2]
#define SM_SB    145992     // [2] (+pad)
#define SM_DX    146016     // [128][36] f32 = 18432B
#define SM_ACT   164448     // 2 x 4096 f32 staging (32KB)
#define SMEM_BYTES 197216

// ---- global scratch (parity double-buffered) ----
__device__ float g_zc[2][4 * NH * 128];    // col-major [h][r] per bb
__device__ float g_h1[2][4 * NBN * 128];   // col-major [c][r] per bb
__device__ uint4 g_fAhi[2][4][4096];       // A frags [(kt*8+mt)*32+lane]
__device__ uint4 g_fAlo[2][4][4096];

// ---- arrive counters: [bb][0=z 1=h1 2=h2] ----
struct PadCnt { unsigned v; unsigned pad[127]; };
__device__ PadCnt g_cc[4][3];

struct PadU { unsigned v; unsigned pad[31]; };
__device__ PadU g_cnt[4];
__device__ PadU g_rel[4];

// ---- helpers ----
__device__ __forceinline__ u64 pack2(float x, float y) {
    u64 r;
    asm("mov.b64 %0, {%1, %2};" : "=l"(r) : "f"(x), "f"(y));
    return r;
}
__device__ __forceinline__ float2 unpack2(u64 v) {
    float2 r;
    asm("mov.b64 {%0, %1}, %2;" : "=f"(r.x), "=f"(r.y) : "l"(v));
    return r;
}
__device__ __forceinline__ void fma2(u64& d, u64 a, u64 b) {
    asm("fma.rn.f32x2 %0, %1, %2, %0;" : "+l"(d) : "l"(a), "l"(b));
}
__device__ __forceinline__ float fast_tanh(float x) {
    float e;
    asm("ex2.approx.f32 %0, %1;" : "=f"(e) : "f"(x * 2.8853900817779268f));
    float r;
    asm("rcp.approx.f32 %0, %1;" : "=f"(r) : "f"(e + 1.0f));
    return fmaf(-2.0f, r, 1.0f);
}
__device__ __forceinline__ float softplus_f(float x) {
    return fmaxf(x, 0.0f) + log1pf(expf(-fabsf(x)));
}
__device__ __forceinline__ void mma16816(float* c, uint4 a, u32 b0, u32 b1) {
    asm volatile(
        "mma.sync.aligned.m16n8k16.row.col.f32.bf16.bf16.f32 "
        "{%0,%1,%2,%3}, {%4,%5,%6,%7}, {%8,%9}, {%0,%1,%2,%3};"
        : "+f"(c[0]), "+f"(c[1]), "+f"(c[2]), "+f"(c[3])
        : "r"(a.x), "r"(a.y), "r"(a.z), "r"(a.w), "r"(b0), "r"(b1));
}
__device__ __forceinline__ void bf_split(float x, unsigned short& h, unsigned short& l) {
    __nv_bfloat16 bh = __float2bfloat16_rn(x);
    __nv_bfloat16 bl = __float2bfloat16_rn(x - __bfloat162float(bh));
    h = __bfloat16_as_ushort(bh);
    l = __bfloat16_as_ushort(bl);
}

// ---- counter publish (block) / wait (warp-autonomous) ----
__device__ __forceinline__ void publish_cnt(PadCnt* c) {
    __syncthreads();
    if (threadIdx.x == 0) {
        asm volatile("red.release.gpu.global.add.u32 [%0], %1;"
                     :: "l"(&c->v), "r"(1u) : "memory");
    }
}
// All 32 lanes poll the SAME address (coalesces to one L2 transaction per
// warp per round); every lane gets acquire semantics, so subsequent global
// loads in any lane are correctly ordered. No CTA barrier: each warp
// proceeds the moment the counter lands.
__device__ __forceinline__ void warp_wait(PadCnt* c, unsigned target) {
    unsigned v;
    do {
        asm volatile("ld.acquire.gpu.u32 %0, [%1];"
                     : "=r"(v) : "l"(&c->v) : "memory");
    } while ((int)(v - target) < 0);
}
__device__ __forceinline__ void gbar_val(int grp, unsigned target) {
    __syncthreads();
    if (threadIdx.x == 0) {
        __threadfence();
        unsigned old = atomicAdd(&g_cnt[grp].v, 1u);
        if (old == (NGRP - 1u)) {
            g_cnt[grp].v = 0u;
            asm volatile("st.release.gpu.u32 [%0], %1;"
                         :: "l"(&g_rel[grp].v), "r"(target) : "memory");
        } else {
            unsigned v;
            do {
                asm volatile("ld.acquire.gpu.u32 %0, [%1];"
                             : "=r"(v) : "l"(&g_rel[grp].v) : "memory");
            } while (v != target);
        }
    }
    __syncthreads();
}

// ---- stage 1: h1[8 cols col-major] = relu(z @ W1slice + b1) ----
__device__ __forceinline__ void stage1(const float* __restrict__ gin_cm,
                                       const float* __restrict__ sW,
                                       const float* __restrict__ sb,
                                       float* __restrict__ gout_cm,
                                       float* __restrict__ sAct, int tid) {
    const int r  = tid & 127;
    const int ch = tid >> 7;
    u64 acc0 = pack2(sb[ch * 4 + 0], sb[ch * 4 + 1]);
    u64 acc1 = pack2(sb[ch * 4 + 2], sb[ch * 4 + 3]);

    const float4* src = (const float4*)gin_cm;
    float4 v0 = __ldcg(src + 0 * 256 + tid);
    float4 v1 = __ldcg(src + 1 * 256 + tid);
    float4 v2 = __ldcg(src + 2 * 256 + tid);
    float4 v3 = __ldcg(src + 3 * 256 + tid);

#pragma unroll 1
    for (int kc = 0; kc < 4; kc++) {
        float4* buf4 = (float4*)(sAct + (kc & 1) * 4096);
        buf4[0 * 256 + tid] = v0;
        buf4[1 * 256 + tid] = v1;
        buf4[2 * 256 + tid] = v2;
        buf4[3 * 256 + tid] = v3;
        __syncthreads();
        if (kc + 1 < 4) {
            const float4* sn = src + (kc + 1) * 1024;
            v0 = __ldcg(sn + 0 * 256 + tid);
            v1 = __ldcg(sn + 1 * 256 + tid);
            v2 = __ldcg(sn + 2 * 256 + tid);
            v3 = __ldcg(sn + 3 * 256 + tid);
        }
        const float* buf = sAct + (kc & 1) * 4096;
        const float* wk  = sW + kc * 32 * 8 + ch * 4;
#pragma unroll
        for (int k = 0; k < 32; k++) {
            float a = buf[k * 128 + r];
            u64 aa  = pack2(a, a);
            ulonglong2 w = *(const ulonglong2*)(wk + k * 8);
            fma2(acc0, aa, w.x);
            fma2(acc1, aa, w.y);
        }
        __syncthreads();
    }
    float2 u0 = unpack2(acc0), u1 = unpack2(acc1);
    __stcg(gout_cm + (ch * 4 + 0) * 128 + r, fmaxf(u0.x, 0.f));
    __stcg(gout_cm + (ch * 4 + 1) * 128 + r, fmaxf(u0.y, 0.f));
    __stcg(gout_cm + (ch * 4 + 2) * 128 + r, fmaxf(u1.x, 0.f));
    __stcg(gout_cm + (ch * 4 + 3) * 128 + r, fmaxf(u1.y, 0.f));
}

// ---- stage 2: h2 cols -> bf16 hi/lo mma A-fragments in gmem ----
__device__ __forceinline__ void stage2_frag(const float* __restrict__ gin_cm,
                                            const float* __restrict__ sW,
                                            const float* __restrict__ sb,
                                            u32* __restrict__ fHi,
                                            u32* __restrict__ fLo,
                                            int g, float* __restrict__ sAct, int tid) {
    const int r  = tid & 127;
    const int ch = tid >> 7;
    u64 acc0 = pack2(sb[ch * 4 + 0], sb[ch * 4 + 1]);
    u64 acc1 = pack2(sb[ch * 4 + 2], sb[ch * 4 + 3]);

    const float4* src = (const float4*)gin_cm;
    float4 v0 = __ldcg(src + 0 * 256 + tid);
    float4 v1 = __ldcg(src + 1 * 256 + tid);
    float4 v2 = __ldcg(src + 2 * 256 + tid);
    float4 v3 = __ldcg(src + 3 * 256 + tid);

#pragma unroll 1
    for (int kc = 0; kc < 8; kc++) {
        float4* buf4 = (float4*)(sAct + (kc & 1) * 4096);
        buf4[0 * 256 + tid] = v0;
        buf4[1 * 256 + tid] = v1;
        buf4[2 * 256 + tid] = v2;
        buf4[3 * 256 + tid] = v3;
        __syncthreads();
        if (kc + 1 < 8) {
            const float4* sn = src + (kc + 1) * 1024;
            v0 = __ldcg(sn + 0 * 256 + tid);
            v1 = __ldcg(sn + 1 * 256 + tid);
            v2 = __ldcg(sn + 2 * 256 + tid);
            v3 = __ldcg(sn + 3 * 256 + tid);
        }
        const float* buf = sAct + (kc & 1) * 4096;
        const float* wk  = sW + kc * 32 * 8 + ch * 4;
#pragma unroll
        for (int k = 0; k < 32; k++) {
            float a = buf[k * 128 + r];
            u64 aa  = pack2(a, a);
            ulonglong2 w = *(const ulonglong2*)(wk + k * 8);
            fma2(acc0, aa, w.x);
            fma2(acc1, aa, w.y);
        }
        __syncthreads();
    }
    float2 u0 = unpack2(acc0), u1 = unpack2(acc1);
    float o0 = fmaxf(u0.x, 0.f), o1 = fmaxf(u0.y, 0.f);
    float o2 = fmaxf(u1.x, 0.f), o3 = fmaxf(u1.y, 0.f);

    unsigned short h0, h1, h2, h3, l0, l1, l2, l3;
    bf_split(o0, h0, l0); bf_split(o1, h1, l1);
    bf_split(o2, h2, l2); bf_split(o3, h3, l3);
    u32 hi01 = ((u32)h1 << 16) | h0;
    u32 hi23 = ((u32)h3 << 16) | h2;
    u32 lo01 = ((u32)l1 << 16) | l0;
    u32 lo23 = ((u32)l3 << 16) | l2;

    const int kt   = g >> 1;
    const int mt   = r >> 4;
    const int lane = (r & 7) * 4 + 2 * ch;
    const int reg  = ((r >> 3) & 1) + 2 * (g & 1);
    const int idx0 = ((kt * 8 + mt) * 32 + lane) * 4 + reg;
    __stcg(&fHi[idx0], hi01);
    __stcg(&fHi[idx0 + 4], hi23);
    __stcg(&fLo[idx0], lo01);
    __stcg(&fLo[idx0 + 4], lo23);
}

// ================= persistent kernel =================
__global__ void __launch_bounds__(TPB, 1)
cde_persistent(const float* __restrict__ t, const float* __restrict__ z0,
               const float* __restrict__ X,
               const float* __restrict__ W1, const float* __restrict__ b1,
               const float* __restrict__ W2, const float* __restrict__ b2,
               const float* __restrict__ W3, const float* __restrict__ b3,
               const float* __restrict__ mW, const float* __restrict__ mb,
               const float* __restrict__ sWp, const float* __restrict__ sbp,
               float* __restrict__ out) {
    extern __shared__ char smb[];
    uint4* sFragB = (uint4*)(smb + SM_FRAGB);
    float* sW1  = (float*)(smb + SM_W1);
    float* sW2  = (float*)(smb + SM_W2);
    float* sb3  = (float*)(smb + SM_B3);
    float* sb1  = (float*)(smb + SM_B1);
    float* sb2  = (float*)(smb + SM_B2);
    float* smW  = (float*)(smb + SM_MW);
    float* ssW  = (float*)(smb + SM_SW);
    float* smb_ = (float*)(smb + SM_MB);
    float* ssb  = (float*)(smb + SM_SB);
    float* sDx  = (float*)(smb + SM_DX);
    float* sAct = (float*)(smb + SM_ACT);

    const int tid  = threadIdx.x;
    const int wid  = tid >> 5;
    const int lane = tid & 31;
    const int bb   = blockIdx.x >> 5;
    const int g    = blockIdx.x & 31;
    const int rowBase = bb * 128;

    PadCnt* Cz = &g_cc[bb][0];
    PadCnt* C1 = &g_cc[bb][1];
    PadCnt* C2 = &g_cc[bb][2];

    // ---- init: W3 slice -> B fragments (hi/lo) in smem ----
    for (int i = tid; i < 16 * 16 * 32; i += TPB) {
        int ln = i & 31, nt = (i >> 5) & 15, kt = i >> 9;
        int nl = nt * 8 + (ln >> 2);
        int k0 = kt * 16 + (ln & 3) * 2;
        const float* wp = W3 + (size_t)k0 * 4096 + g * 128 + nl;
        unsigned short h0, h1, h8, h9, l0, l1, l8, l9;
        bf_split(wp[0],        h0, l0);
        bf_split(wp[4096],     h1, l1);
        bf_split(wp[8 * 4096], h8, l8);
        bf_split(wp[9 * 4096], h9, l9);
        uint4 v;
        v.x = ((u32)h1 << 16) | h0;
        v.y = ((u32)h9 << 16) | h8;
        v.z = ((u32)l1 << 16) | l0;
        v.w = ((u32)l9 << 16) | l8;
        sFragB[i] = v;
    }
    for (int i = tid; i < 128 * 2; i += TPB) {
        int k = i >> 1, c4 = i & 1;
        *(float4*)(sW1 + k * 8 + c4 * 4) =
            __ldg((const float4*)(W1 + (size_t)k * 256 + g * 8) + c4);
    }
    for (int i = tid; i < 256 * 2; i += TPB) {
        int k = i >> 1, c4 = i & 1;
        *(float4*)(sW2 + k * 8 + c4 * 4) =
            __ldg((const float4*)(W2 + (size_t)k * 256 + g * 8) + c4);
    }
    for (int i = tid; i < 128; i += TPB) sb3[i] = __ldg(&b3[g * 128 + i]);
    if (tid < 8)  sb1[tid] = __ldg(&b1[g * 8 + tid]);
    if (tid >= 8 && tid < 16) sb2[tid - 8] = __ldg(&b2[g * 8 + tid - 8]);
    for (int i = tid; i < 256; i += TPB) {
        int h = i >> 1, c = i & 1;
        smW[i] = __ldg(&mW[(size_t)h * 64 + g * 2 + c]);
        ssW[i] = __ldg(&sWp[(size_t)h * 64 + g * 2 + c]);
    }
    if (tid < 2)  smb_[tid] = __ldg(&mb[g * 2 + tid]);
    if (tid >= 2 && tid < 4) ssb[tid - 2] = __ldg(&sbp[g * 2 + tid - 2]);
    __syncthreads();

    // ---- warp-local RK state (redundant across quad lanes) ----
    const int m    = wid & 3;
    const int nh   = wid >> 2;
    const int rsub = lane >> 2;
    const int t4   = lane & 3;
    const int mbase = m * 32;

    float zb[2][2][2];    // [mti][rp][hl]
#pragma unroll
    for (int mti = 0; mti < 2; mti++)
#pragma unroll
        for (int rp = 0; rp < 2; rp++) {
            int row = rowBase + mbase + mti * 16 + rsub + rp * 8;
            float2 z = __ldg((const float2*)&z0[(size_t)row * 128 + g * 4 + nh * 2]);
            zb[mti][rp][0] = z.x;
            zb[mti][rp][1] = z.y;
        }

    const size_t zOff  = (size_t)bb * (NH * 128);
    const size_t h1Off = (size_t)bb * (NBN * 128);

    // ---- bootstrap: publish z0 at parity 1 ----
    if (t4 < 2) {
        float* zc = &g_zc[1][zOff + (size_t)(g * 4 + nh * 2 + t4) * 128];
#pragma unroll
        for (int mti = 0; mti < 2; mti++)
#pragma unroll
            for (int rp = 0; rp < 2; rp++)
                __stcg(zc + mbase + mti * 16 + rsub + rp * 8, zb[mti][rp][t4]);
    }
    publish_cnt(Cz);
    unsigned cz = 1, c1 = 0, c2 = 0;

#pragma unroll 1
    for (int tau = 0; tau < NIVL; tau++) {
        float t0v = __ldg(&t[tau]);
        float t1v = __ldg(&t[tau + 1]);
        float dti = t1v - t0v;
        float hstep = dti * 0.25f;
        float h6 = hstep / 6.0f;
        __syncthreads();
        for (int i = tid; i < 1024; i += TPB) {
            int rr = i >> 3, q = i & 7;
            const float* Xr = X + ((size_t)(rowBase + rr) * NTT + tau) * NIN;
            float4 x0 = __ldg((const float4*)Xr + q);
            float4 x1 = __ldg((const float4*)(Xr + NIN) + q);
            float* d = sDx + rr * 36 + q * 4;
            d[0] = (x1.x - x0.x) / dti;
            d[1] = (x1.y - x0.y) / dti;
            d[2] = (x1.z - x0.z) / dti;
            d[3] = (x1.w - x0.w) / dti;
        }
        __syncthreads();

#pragma unroll 1
        for (int sub = 0; sub < 4; sub++) {
            float aacc[2][2][2] = {};
#pragma unroll 1
            for (int s = 0; s < 4; s++) {
                // z for this stage published by previous stage3 (or bootstrap)
                warp_wait(Cz, cz * NGRP);
                const int pz = cz & 1;

                // stage 1
                ++c1; const int p1 = c1 & 1;
                stage1(&g_zc[pz][zOff], sW1, sb1,
                       &g_h1[p1][h1Off + (size_t)(g * 8) * 128], sAct, tid);
                publish_cnt(C1);
                warp_wait(C1, c1 * NGRP);

                // stage 2 -> A fragments
                ++c2; const int p2 = c2 & 1;
                stage2_frag(&g_h1[p1][h1Off], sW2, sb2,
                            (u32*)&g_fAhi[p2][bb][0], (u32*)&g_fAlo[p2][bb][0],
                            g, sAct, tid);
                publish_cnt(C2);
                warp_wait(C2, c2 * NGRP);

                // ---- stage 3: mma, 2 m-tiles x 8 n-tiles per warp ----
                float acc[2][8][4];
#pragma unroll
                for (int nt = 0; nt < 8; nt++) {
                    float bx = sb3[nh * 64 + nt * 8 + t4 * 2];
                    float by = sb3[nh * 64 + nt * 8 + t4 * 2 + 1];
                    acc[0][nt][0] = bx; acc[0][nt][1] = by;
                    acc[0][nt][2] = bx; acc[0][nt][3] = by;
                    acc[1][nt][0] = bx; acc[1][nt][1] = by;
                    acc[1][nt][2] = bx; acc[1][nt][3] = by;
                }
                const uint4* fAh = &g_fAhi[p2][bb][0];
                const uint4* fAl = &g_fAlo[p2][bb][0];
                uint4 a0h = __ldcg(fAh + (0 * 8 + 2 * m + 0) * 32 + lane);
                uint4 a0l = __ldcg(fAl + (0 * 8 + 2 * m + 0) * 32 + lane);
                uint4 a1h = __ldcg(fAh + (0 * 8 + 2 * m + 1) * 32 + lane);
                uint4 a1l = __ldcg(fAl + (0 * 8 + 2 * m + 1) * 32 + lane);
#pragma unroll 1
                for (int kt = 0; kt < 16; kt++) {
                    uint4 n0h, n0l, n1h, n1l;
                    if (kt < 15) {
                        n0h = __ldcg(fAh + ((kt + 1) * 8 + 2 * m + 0) * 32 + lane);
                        n0l = __ldcg(fAl + ((kt + 1) * 8 + 2 * m + 0) * 32 + lane);
                        n1h = __ldcg(fAh + ((kt + 1) * 8 + 2 * m + 1) * 32 + lane);
                        n1l = __ldcg(fAl + ((kt + 1) * 8 + 2 * m + 1) * 32 + lane);
                    }
                    const uint4* bfr = sFragB + (kt * 16 + nh * 8) * 32 + lane;
#pragma unroll
                    for (int nt = 0; nt < 8; nt++) {
                        uint4 b = bfr[nt * 32];
                        mma16816(acc[0][nt], a0h, b.x, b.y);
                        mma16816(acc[0][nt], a0h, b.z, b.w);
                        mma16816(acc[0][nt], a0l, b.x, b.y);
                        mma16816(acc[1][nt], a1h, b.x, b.y);
                        mma16816(acc[1][nt], a1h, b.z, b.w);
                        mma16816(acc[1][nt], a1l, b.x, b.y);
                    }
                    a0h = n0h; a0l = n0l; a1h = n1h; a1l = n1l;
                }

                // ---- epilogue: tanh + dxdt contraction, butterfly over t4 ----
                float kq[2][2][2] = {};
#pragma unroll
                for (int mti = 0; mti < 2; mti++) {
                    const int lr0 = mbase + mti * 16 + rsub;
#pragma unroll
                    for (int nt = 0; nt < 8; nt++) {
                        int hl = nt >> 2, iblk = nt & 3;
                        float2 dxa = *(const float2*)&sDx[lr0 * 36 + iblk * 8 + t4 * 2];
                        float2 dxb = *(const float2*)&sDx[(lr0 + 8) * 36 + iblk * 8 + t4 * 2];
                        float y;
                        y = fast_tanh(acc[mti][nt][0]);
                        kq[mti][0][hl] = fmaf(y, dxa.x, kq[mti][0][hl]);
                        y = fast_tanh(acc[mti][nt][1]);
                        kq[mti][0][hl] = fmaf(y, dxa.y, kq[mti][0][hl]);
                        y = fast_tanh(acc[mti][nt][2]);
                        kq[mti][1][hl] = fmaf(y, dxb.x, kq[mti][1][hl]);
                        y = fast_tanh(acc[mti][nt][3]);
                        kq[mti][1][hl] = fmaf(y, dxb.y, kq[mti][1][hl]);
                    }
                }
#pragma unroll
                for (int mti = 0; mti < 2; mti++)
#pragma unroll
                    for (int rp = 0; rp < 2; rp++)
#pragma unroll
                        for (int hl = 0; hl < 2; hl++) {
                            float v = kq[mti][rp][hl];
                            v += __shfl_xor_sync(0xffffffffu, v, 1);
                            v += __shfl_xor_sync(0xffffffffu, v, 2);
                            kq[mti][rp][hl] = v;
                        }

                // ---- RK update + publish z for next stage ----
                const float ws = (s == 0 || s == 3) ? 1.f : 2.f;
                const float cnext = (s == 2) ? hstep : 0.5f * hstep;
                ++cz; const int pzn = cz & 1;
                float zn[2][2][2];
#pragma unroll
                for (int mti = 0; mti < 2; mti++)
#pragma unroll
                    for (int rp = 0; rp < 2; rp++)
#pragma unroll
                        for (int hl = 0; hl < 2; hl++) {
                            float kv = kq[mti][rp][hl];
                            aacc[mti][rp][hl] = fmaf(ws, kv, aacc[mti][rp][hl]);
                            if (s < 3) {
                                zn[mti][rp][hl] = fmaf(cnext, kv, zb[mti][rp][hl]);
                            } else {
                                zb[mti][rp][hl] = fmaf(h6, aacc[mti][rp][hl],
                                                       zb[mti][rp][hl]);
                                zn[mti][rp][hl] = zb[mti][rp][hl];
                            }
                        }
                if (t4 < 2) {
                    float* zc = &g_zc[pzn][zOff + (size_t)(g * 4 + nh * 2 + t4) * 128];
#pragma unroll
                    for (int mti = 0; mti < 2; mti++)
#pragma unroll
                        for (int rp = 0; rp < 2; rp++)
                            __stcg(zc + mbase + mti * 16 + rsub + rp * 8,
                                   zn[mti][rp][t4]);
                }
                publish_cnt(Cz);
            }
        }

        // ---- interval end: output heads (final z = last stage3 publish) ----
        warp_wait(Cz, cz * NGRP);
        {
            const int r  = tid & 127;
            const int hh = tid >> 7;
            const int b  = rowBase + r;
            const float* wsel = hh ? ssW : smW;
            float acc0 = hh ? ssb[0] : smb_[0];
            float acc1 = hh ? ssb[1] : smb_[1];
            const float* zbase = &g_zc[cz & 1][zOff];
#pragma unroll 8
            for (int h = 0; h < 128; h++) {
                float zv = __ldcg(zbase + (size_t)h * 128 + r);
                acc0 = fmaf(zv, wsel[h * 2 + 0], acc0);
                acc1 = fmaf(zv, wsel[h * 2 + 1], acc1);
            }
            if (hh) { acc0 = softplus_f(acc0); acc1 = softplus_f(acc1); }
            float* dst = out + (hh ? (size_t)NBATCH * NIVL * NOUT : 0)
                         + ((size_t)b * NIVL + tau) * NOUT + g * 2;
            dst[0] = acc0;
            dst[1] = acc1;
        }
    }

    // ---- end-of-kernel reset for deterministic graph replay ----
    gbar_val(bb, 1u);
    if (tid == 0 && g == 0) {
        g_cc[bb][0].v = 0u;
        g_cc[bb][1].v = 0u;
        g_cc[bb][2].v = 0u;
    }
    gbar_val(bb, 0u);
}

extern "C" void kernel_launch(void* const* d_in, const int* in_sizes, int n_in,
                              void* d_out, int out_size) {
    const float* t   = (const float*)d_in[0];
    const float* z0  = (const float*)d_in[1];
    const float* X   = (const float*)d_in[2];
    const float* W1  = (const float*)d_in[3];
    const float* b1  = (const float*)d_in[4];
    const float* W2  = (const float*)d_in[5];
    const float* b2  = (const float*)d_in[6];
    const float* W3  = (const float*)d_in[7];
    const float* b3  = (const float*)d_in[8];
    const float* mW  = (const float*)d_in[9];
    const float* mb  = (const float*)d_in[10];
    const float* sW  = (const float*)d_in[11];
    const float* sb  = (const float*)d_in[12];
    float* out = (float*)d_out;

    cudaFuncSetAttribute(cde_persistent,
                         cudaFuncAttributeMaxDynamicSharedMemorySize, SMEM_BYTES);
    cde_persistent<<<GRID_CTAS, TPB, SMEM_BYTES>>>(t, z0, X, W1, b1, W2, b2,
                                                   W3, b3, mW, mb, sW, sb, out);
}

// round 13
// speedup vs baseline: 1.8932x; 1.2937x over previous
#include <cuda_runtime.h>
#include <cuda_bf16.h>

typedef unsigned long long u64;
typedef unsigned int u32;

#define NBATCH 512
#define NTT    257
#define NIVL   256
#define NIN    32
#define NH     128
#define NBN    256
#define NOUT   64
#define GRID_CTAS 128
#define TPB    256
#define NGRP   32
#define NARR   256          // warp arrivals per phase (32 CTAs x 8 warps)

// ---- shared memory byte offsets ----
#define SM_FRAGB 0          // W3 B-frags [16kt][16nt][32] uint4 = 128KB
#define SM_W1F   131072     // W1 B-frags [8kt][32] uint4 = 4KB
#define SM_W2F   135168     // W2 B-frags [16kt][32] uint4 = 8KB
#define SM_B3    143360     // [128] f32
#define SM_B1    143872     // [8]
#define SM_B2    143904     // [8]
#define SM_MW    143936     // [128][2]
#define SM_SW    144960     // [128][2]
#define SM_MB    145984     // [2]
#define SM_SB    145992     // [2]
#define SMEM_BYTES 146016

// ---- global frag exchanges (parity double-buffered, per bb) ----
__device__ uint4 g_zfh[2][4][2048];   // z  frags: 8kt x 8mt x 32
__device__ uint4 g_zfl[2][4][2048];
__device__ uint4 g_f1h[2][4][4096];   // h1 frags: 16kt x 8mt x 32
__device__ uint4 g_f1l[2][4][4096];
__device__ uint4 g_fAh[2][4][4096];   // h2 frags
__device__ uint4 g_fAl[2][4][4096];

// ---- arrive counters: [bb][0=z 1=h1 2=h2] ----
struct PadCnt { unsigned v; unsigned pad[127]; };
__device__ PadCnt g_cc[4][3];

struct PadU { unsigned v; unsigned pad[31]; };
__device__ PadU g_cnt[4];
__device__ PadU g_rel[4];

// ---- helpers ----
__device__ __forceinline__ float fast_tanh(float x) {
    float e;
    asm("ex2.approx.f32 %0, %1;" : "=f"(e) : "f"(x * 2.8853900817779268f));
    float r;
    asm("rcp.approx.f32 %0, %1;" : "=f"(r) : "f"(e + 1.0f));
    return fmaf(-2.0f, r, 1.0f);
}
__device__ __forceinline__ float softplus_f(float x) {
    return fmaxf(x, 0.0f) + log1pf(expf(-fabsf(x)));
}
__device__ __forceinline__ void mma16816(float* c, uint4 a, u32 b0, u32 b1) {
    asm volatile(
        "mma.sync.aligned.m16n8k16.row.col.f32.bf16.bf16.f32 "
        "{%0,%1,%2,%3}, {%4,%5,%6,%7}, {%8,%9}, {%0,%1,%2,%3};"
        : "+f"(c[0]), "+f"(c[1]), "+f"(c[2]), "+f"(c[3])
        : "r"(a.x), "r"(a.y), "r"(a.z), "r"(a.w), "r"(b0), "r"(b1));
}
__device__ __forceinline__ void bf_split(float x, unsigned short& h, unsigned short& l) {
    __nv_bfloat16 bh = __float2bfloat16_rn(x);
    __nv_bfloat16 bl = __float2bfloat16_rn(x - __bfloat162float(bh));
    h = __bfloat16_as_ushort(bh);
    l = __bfloat16_as_ushort(bl);
}
__device__ __forceinline__ float bf2f(u32 bits16) {
    return __bfloat162float(__ushort_as_bfloat16((unsigned short)bits16));
}

// ---- warp-granularity publish / wait ----
__device__ __forceinline__ void warp_publish(PadCnt* c, int lane) {
    __syncwarp();
    if (lane == 0)
        asm volatile("red.release.gpu.global.add.u32 [%0], %1;"
                     :: "l"(&c->v), "r"(1u) : "memory");
}
__device__ __forceinline__ void warp_wait(PadCnt* c, unsigned target) {
    unsigned v;
    do {
        asm volatile("ld.acquire.gpu.u32 %0, [%1];"
                     : "=r"(v) : "l"(&c->v) : "memory");
    } while ((int)(v - target) < 0);
}
__device__ __forceinline__ void gbar_val(int grp, unsigned target) {
    __syncthreads();
    if (threadIdx.x == 0) {
        __threadfence();
        unsigned old = atomicAdd(&g_cnt[grp].v, 1u);
        if (old == (NGRP - 1u)) {
            g_cnt[grp].v = 0u;
            asm volatile("st.release.gpu.u32 [%0], %1;"
                         :: "l"(&g_rel[grp].v), "r"(target) : "memory");
        } else {
            unsigned v;
            do {
                asm volatile("ld.acquire.gpu.u32 %0, [%1];"
                             : "=r"(v) : "l"(&g_rel[grp].v) : "memory");
            } while (v != target);
        }
    }
    __syncthreads();
}

// ---- generic mma MLP stage (per warp): out 8 cols for rows mt=wid ----
// A-frags from gmem (hi/lo), B-frags from smem, bias+relu, write out-frags.
template <int NKT>
__device__ __forceinline__ void mlp_mma(const uint4* __restrict__ fAh,
                                        const uint4* __restrict__ fAl,
                                        const uint4* __restrict__ sBf,
                                        const float* __restrict__ sbias,
                                        u64* __restrict__ outHi,
                                        u64* __restrict__ outLo,
                                        int wid, int lane, int g) {
    const int c0 = (lane & 3) * 2;
    float aP[4], aQ[4] = {0.f, 0.f, 0.f, 0.f}, aR[4] = {0.f, 0.f, 0.f, 0.f};
    aP[0] = sbias[c0];
    aP[1] = sbias[c0 + 1];
    aP[2] = sbias[c0];
    aP[3] = sbias[c0 + 1];

    uint4 rh[4], rl[4];
#pragma unroll
    for (int d = 0; d < 4; d++) {
        rh[d] = __ldcg(fAh + (d * 8 + wid) * 32 + lane);
        rl[d] = __ldcg(fAl + (d * 8 + wid) * 32 + lane);
    }
#pragma unroll
    for (int kt = 0; kt < NKT; kt++) {
        uint4 ah = rh[kt & 3], al = rl[kt & 3];
        if (kt + 4 < NKT) {
            rh[kt & 3] = __ldcg(fAh + ((kt + 4) * 8 + wid) * 32 + lane);
            rl[kt & 3] = __ldcg(fAl + ((kt + 4) * 8 + wid) * 32 + lane);
        }
        uint4 b = sBf[kt * 32 + lane];
        mma16816(aP, ah, b.x, b.y);
        mma16816(aQ, ah, b.z, b.w);
        mma16816(aR, al, b.x, b.y);
    }
    float o0 = fmaxf((aP[0] + aQ[0]) + aR[0], 0.f);
    float o1 = fmaxf((aP[1] + aQ[1]) + aR[1], 0.f);
    float o2 = fmaxf((aP[2] + aQ[2]) + aR[2], 0.f);
    float o3 = fmaxf((aP[3] + aQ[3]) + aR[3], 0.f);

    unsigned short h0, h1, h2, h3, l0, l1, l2, l3;
    bf_split(o0, h0, l0); bf_split(o1, h1, l1);
    bf_split(o2, h2, l2); bf_split(o3, h3, l3);
    u32 hiA = ((u32)h1 << 16) | h0;     // row r0,   col pair
    u32 hiB = ((u32)h3 << 16) | h2;     // row r0+8, col pair
    u32 loA = ((u32)l1 << 16) | l0;
    u32 loB = ((u32)l3 << 16) | l2;

    const int F = ((g >> 1) * 8 + wid) * 32 + (lane >> 2) * 4 + (lane & 3);
    const int slot = F * 2 + (g & 1);
    __stcg(&outHi[slot], (u64)hiA | ((u64)hiB << 32));
    __stcg(&outLo[slot], (u64)loA | ((u64)loB << 32));
}

// ================= persistent kernel =================
__global__ void __launch_bounds__(TPB, 1)
cde_persistent(const float* __restrict__ t, const float* __restrict__ z0,
               const float* __restrict__ X,
               const float* __restrict__ W1, const float* __restrict__ b1,
               const float* __restrict__ W2, const float* __restrict__ b2,
               const float* __restrict__ W3, const float* __restrict__ b3,
               const float* __restrict__ mW, const float* __restrict__ mb,
               const float* __restrict__ sWp, const float* __restrict__ sbp,
               float* __restrict__ out) {
    extern __shared__ char smb[];
    uint4* sFragB = (uint4*)(smb + SM_FRAGB);
    uint4* sW1f  = (uint4*)(smb + SM_W1F);
    uint4* sW2f  = (uint4*)(smb + SM_W2F);
    float* sb3   = (float*)(smb + SM_B3);
    float* sb1   = (float*)(smb + SM_B1);
    float* sb2   = (float*)(smb + SM_B2);
    float* smW   = (float*)(smb + SM_MW);
    float* ssW   = (float*)(smb + SM_SW);
    float* smb_  = (float*)(smb + SM_MB);
    float* ssb   = (float*)(smb + SM_SB);

    const int tid  = threadIdx.x;
    const int wid  = tid >> 5;
    const int lane = tid & 31;
    const int bb   = blockIdx.x >> 5;
    const int g    = blockIdx.x & 31;
    const int rowBase = bb * 128;

    PadCnt* Cz = &g_cc[bb][0];
    PadCnt* C1 = &g_cc[bb][1];
    PadCnt* C2 = &g_cc[bb][2];

    // ---- init: W3 slice -> B fragments ----
    for (int i = tid; i < 16 * 16 * 32; i += TPB) {
        int ln = i & 31, nt = (i >> 5) & 15, kt = i >> 9;
        int nl = nt * 8 + (ln >> 2);
        int k0 = kt * 16 + (ln & 3) * 2;
        const float* wp = W3 + (size_t)k0 * 4096 + g * 128 + nl;
        unsigned short h0, h1, h8, h9, l0, l1, l8, l9;
        bf_split(wp[0],        h0, l0);
        bf_split(wp[4096],     h1, l1);
        bf_split(wp[8 * 4096], h8, l8);
        bf_split(wp[9 * 4096], h9, l9);
        uint4 v;
        v.x = ((u32)h1 << 16) | h0;
        v.y = ((u32)h9 << 16) | h8;
        v.z = ((u32)l1 << 16) | l0;
        v.w = ((u32)l9 << 16) | l8;
        sFragB[i] = v;
    }
    // W1 slice -> B-frags [8kt][32]
    for (int i = tid; i < 8 * 32; i += TPB) {
        int kt = i >> 5, ln = i & 31;
        int n  = g * 8 + (ln >> 2);
        int k0 = kt * 16 + (ln & 3) * 2;
        unsigned short h0, h1, h8, h9, l0, l1, l8, l9;
        bf_split(__ldg(&W1[(size_t)k0 * 256 + n]),       h0, l0);
        bf_split(__ldg(&W1[(size_t)(k0 + 1) * 256 + n]), h1, l1);
        bf_split(__ldg(&W1[(size_t)(k0 + 8) * 256 + n]), h8, l8);
        bf_split(__ldg(&W1[(size_t)(k0 + 9) * 256 + n]), h9, l9);
        uint4 v;
        v.x = ((u32)h1 << 16) | h0;
        v.y = ((u32)h9 << 16) | h8;
        v.z = ((u32)l1 << 16) | l0;
        v.w = ((u32)l9 << 16) | l8;
        sW1f[i] = v;
    }
    // W2 slice -> B-frags [16kt][32]
    for (int i = tid; i < 16 * 32; i += TPB) {
        int kt = i >> 5, ln = i & 31;
        int n  = g * 8 + (ln >> 2);
        int k0 = kt * 16 + (ln & 3) * 2;
        unsigned short h0, h1, h8, h9, l0, l1, l8, l9;
        bf_split(__ldg(&W2[(size_t)k0 * 256 + n]),       h0, l0);
        bf_split(__ldg(&W2[(size_t)(k0 + 1) * 256 + n]), h1, l1);
        bf_split(__ldg(&W2[(size_t)(k0 + 8) * 256 + n]), h8, l8);
        bf_split(__ldg(&W2[(size_t)(k0 + 9) * 256 + n]), h9, l9);
        uint4 v;
        v.x = ((u32)h1 << 16) | h0;
        v.y = ((u32)h9 << 16) | h8;
        v.z = ((u32)l1 << 16) | l0;
        v.w = ((u32)l9 << 16) | l8;
        sW2f[i] = v;
    }
    for (int i = tid; i < 128; i += TPB) sb3[i] = __ldg(&b3[g * 128 + i]);
    if (tid < 8)  sb1[tid] = __ldg(&b1[g * 8 + tid]);
    if (tid >= 8 && tid < 16) sb2[tid - 8] = __ldg(&b2[g * 8 + tid - 8]);
    for (int i = tid; i < 256; i += TPB) {
        int h = i >> 1, c = i & 1;
        smW[i] = __ldg(&mW[(size_t)h * 64 + g * 2 + c]);
        ssW[i] = __ldg(&sWp[(size_t)h * 64 + g * 2 + c]);
    }
    if (tid < 2)  smb_[tid] = __ldg(&mb[g * 2 + tid]);
    if (tid >= 2 && tid < 4) ssb[tid - 2] = __ldg(&sbp[g * 2 + tid - 2]);

    // ---- warp-local RK state (redundant across quad lanes) ----
    const int m    = wid & 3;
    const int nh   = wid >> 2;
    const int rsub = lane >> 2;
    const int t4   = lane & 3;
    const int mbase = m * 32;

    float zb[2][2][2];    // [mti][rp][hl], cols g*4 + nh*2 + hl
#pragma unroll
    for (int mti = 0; mti < 2; mti++)
#pragma unroll
        for (int rp = 0; rp < 2; rp++) {
            int row = rowBase + mbase + mti * 16 + rsub + rp * 8;
            float2 z = __ldg((const float2*)&z0[(size_t)row * 128 + g * 4 + nh * 2]);
            zb[mti][rp][0] = z.x;
            zb[mti][rp][1] = z.y;
        }

    // ---- bootstrap: write z0 frags at parity 1 ----
    {
        u32* zfh = (u32*)&g_zfh[1][bb][0];
        u32* zfl = (u32*)&g_zfl[1][bb][0];
        for (int i = tid; i < 256; i += TPB) {
            int r = i >> 1, ps = i & 1;
            int c0 = g * 4 + ps * 2;
            float v0 = __ldg(&z0[(size_t)(rowBase + r) * 128 + c0]);
            float v1 = __ldg(&z0[(size_t)(rowBase + r) * 128 + c0 + 1]);
            unsigned short h0, l0, h1, l1;
            bf_split(v0, h0, l0);
            bf_split(v1, h1, l1);
            int kt = g >> 2, kk = c0 & 15;
            int mt = r >> 4, ln = (r & 7) * 4 + ((kk & 7) >> 1);
            int reg = ((r >> 3) & 1) + 2 * (kk >> 3);
            int idx = ((kt * 8 + mt) * 32 + ln) * 4 + reg;
            zfh[idx] = ((u32)h1 << 16) | h0;
            zfl[idx] = ((u32)l1 << 16) | l0;
        }
    }
    __syncthreads();                 // smem init complete; bootstrap stores done per-thread
    warp_publish(Cz, lane);          // 8 arrives per CTA
    unsigned cz = 1, c1 = 0, c2 = 0;

#pragma unroll 1
    for (int tau = 0; tau < NIVL; tau++) {
        float t0v = __ldg(&t[tau]);
        float t1v = __ldg(&t[tau + 1]);
        float dti = t1v - t0v;
        float hstep = dti * 0.25f;
        float h6 = hstep / 6.0f;

        // dxdt into registers: [mti][rp][8]
        float dxm[2][2][8];
#pragma unroll
        for (int mti = 0; mti < 2; mti++)
#pragma unroll
            for (int rp = 0; rp < 2; rp++) {
                int row = rowBase + mbase + mti * 16 + rsub + rp * 8;
                const float* Xr = X + ((size_t)row * NTT + tau) * NIN;
#pragma unroll
                for (int blk = 0; blk < 4; blk++) {
                    float2 x0 = __ldg((const float2*)(Xr + blk * 8 + t4 * 2));
                    float2 x1 = __ldg((const float2*)(Xr + NIN + blk * 8 + t4 * 2));
                    dxm[mti][rp][blk * 2 + 0] = (x1.x - x0.x) / dti;
                    dxm[mti][rp][blk * 2 + 1] = (x1.y - x0.y) / dti;
                }
            }

#pragma unroll 1
        for (int sub = 0; sub < 4; sub++) {
            float aacc[2][2][2] = {};
#pragma unroll 1
            for (int s = 0; s < 4; s++) {
                warp_wait(Cz, cz * NARR);
                const int pz = cz & 1;

                // ---- stage 1 (mma): z-frags -> h1-frags ----
                ++c1; const int p1 = c1 & 1;
                mlp_mma<8>(&g_zfh[pz][bb][0], &g_zfl[pz][bb][0], sW1f, sb1,
                           (u64*)&g_f1h[p1][bb][0], (u64*)&g_f1l[p1][bb][0],
                           wid, lane, g);
                warp_publish(C1, lane);
                warp_wait(C1, c1 * NARR);

                // ---- stage 2 (mma): h1-frags -> h2-frags ----
                ++c2; const int p2 = c2 & 1;
                mlp_mma<16>(&g_f1h[p1][bb][0], &g_f1l[p1][bb][0], sW2f, sb2,
                            (u64*)&g_fAh[p2][bb][0], (u64*)&g_fAl[p2][bb][0],
                            wid, lane, g);
                warp_publish(C2, lane);
                warp_wait(C2, c2 * NARR);

                // ---- stage 3: mma, 2 m-tiles x 8 n-tiles per warp ----
                float acc[2][8][4];
#pragma unroll
                for (int nt = 0; nt < 8; nt++) {
                    float bx = sb3[nh * 64 + nt * 8 + t4 * 2];
                    float by = sb3[nh * 64 + nt * 8 + t4 * 2 + 1];
                    acc[0][nt][0] = bx; acc[0][nt][1] = by;
                    acc[0][nt][2] = bx; acc[0][nt][3] = by;
                    acc[1][nt][0] = bx; acc[1][nt][1] = by;
                    acc[1][nt][2] = bx; acc[1][nt][3] = by;
                }
                const uint4* fAh = &g_fAh[p2][bb][0];
                const uint4* fAl = &g_fAl[p2][bb][0];
                uint4 a0h = __ldcg(fAh + (2 * m + 0) * 32 + lane);
                uint4 a0l = __ldcg(fAl + (2 * m + 0) * 32 + lane);
                uint4 a1h = __ldcg(fAh + (2 * m + 1) * 32 + lane);
                uint4 a1l = __ldcg(fAl + (2 * m + 1) * 32 + lane);
#pragma unroll 1
                for (int kt = 0; kt < 16; kt++) {
                    uint4 n0h, n0l, n1h, n1l;
                    if (kt < 15) {
                        n0h = __ldcg(fAh + ((kt + 1) * 8 + 2 * m + 0) * 32 + lane);
                        n0l = __ldcg(fAl + ((kt + 1) * 8 + 2 * m + 0) * 32 + lane);
                        n1h = __ldcg(fAh + ((kt + 1) * 8 + 2 * m + 1) * 32 + lane);
                        n1l = __ldcg(fAl + ((kt + 1) * 8 + 2 * m + 1) * 32 + lane);
                    }
                    const uint4* bfr = sFragB + (kt * 16 + nh * 8) * 32 + lane;
#pragma unroll
                    for (int nt = 0; nt < 8; nt++) {
                        uint4 b = bfr[nt * 32];
                        mma16816(acc[0][nt], a0h, b.x, b.y);
                        mma16816(acc[0][nt], a0h, b.z, b.w);
                        mma16816(acc[0][nt], a0l, b.x, b.y);
                        mma16816(acc[1][nt], a1h, b.x, b.y);
                        mma16816(acc[1][nt], a1h, b.z, b.w);
                        mma16816(acc[1][nt], a1l, b.x, b.y);
                    }
                    a0h = n0h; a0l = n0l; a1h = n1h; a1l = n1l;
                }

                // ---- epilogue: tanh + dxdt contraction, butterfly over t4 ----
                float kq[2][2][2] = {};
#pragma unroll
                for (int mti = 0; mti < 2; mti++) {
#pragma unroll
                    for (int nt = 0; nt < 8; nt++) {
                        int hl = nt >> 2, iblk = nt & 3;
                        float y;
                        y = fast_tanh(acc[mti][nt][0]);
                        kq[mti][0][hl] = fmaf(y, dxm[mti][0][iblk * 2],     kq[mti][0][hl]);
                        y = fast_tanh(acc[mti][nt][1]);
                        kq[mti][0][hl] = fmaf(y, dxm[mti][0][iblk * 2 + 1], kq[mti][0][hl]);
                        y = fast_tanh(acc[mti][nt][2]);
                        kq[mti][1][hl] = fmaf(y, dxm[mti][1][iblk * 2],     kq[mti][1][hl]);
                        y = fast_tanh(acc[mti][nt][3]);
                        kq[mti][1][hl] = fmaf(y, dxm[mti][1][iblk * 2 + 1], kq[mti][1][hl]);
                    }
                }
#pragma unroll
                for (int mti = 0; mti < 2; mti++)
#pragma unroll
                    for (int rp = 0; rp < 2; rp++)
#pragma unroll
                        for (int hl = 0; hl < 2; hl++) {
                            float v = kq[mti][rp][hl];
                            v += __shfl_xor_sync(0xffffffffu, v, 1);
                            v += __shfl_xor_sync(0xffffffffu, v, 2);
                            kq[mti][rp][hl] = v;
                        }

                // ---- RK update + publish z-frags for next stage ----
                const float ws = (s == 0 || s == 3) ? 1.f : 2.f;
                const float cnext = (s == 2) ? hstep : 0.5f * hstep;
                ++cz; const int pzn = cz & 1;
                float zn[2][2][2];
#pragma unroll
                for (int mti = 0; mti < 2; mti++)
#pragma unroll
                    for (int rp = 0; rp < 2; rp++)
#pragma unroll
                        for (int hl = 0; hl < 2; hl++) {
                            float kv = kq[mti][rp][hl];
                            aacc[mti][rp][hl] = fmaf(ws, kv, aacc[mti][rp][hl]);
                            if (s < 3) {
                                zn[mti][rp][hl] = fmaf(cnext, kv, zb[mti][rp][hl]);
                            } else {
                                zb[mti][rp][hl] = fmaf(h6, aacc[mti][rp][hl],
                                                       zb[mti][rp][hl]);
                                zn[mti][rp][hl] = zb[mti][rp][hl];
                            }
                        }
                {
                    const int mti_w = t4 & 1, rp_w = t4 >> 1;
                    unsigned short zh0, zl0, zh1, zl1;
                    bf_split(zn[mti_w][rp_w][0], zh0, zl0);
                    bf_split(zn[mti_w][rp_w][1], zh1, zl1);
                    const int c0 = g * 4 + nh * 2;
                    const int kk = c0 & 15, kt = g >> 2;
                    const int mt = 2 * m + mti_w;
                    const int ln = rsub * 4 + ((kk & 7) >> 1);
                    const int reg = (t4 >> 1) + 2 * (kk >> 3);
                    const int idx = ((kt * 8 + mt) * 32 + ln) * 4 + reg;
                    __stcg(&((u32*)&g_zfh[pzn][bb][0])[idx], ((u32)zh1 << 16) | zh0);
                    __stcg(&((u32*)&g_zfl[pzn][bb][0])[idx], ((u32)zl1 << 16) | zl0);
                }
                warp_publish(Cz, lane);
            }
        }

        // ---- interval end: output heads from z-frags ----
        warp_wait(Cz, cz * NARR);
        {
            const int r  = tid & 127;
            const int hh = tid >> 7;
            const int b  = rowBase + r;
            const float* wsel = hh ? ssW : smW;
            float acc0 = hh ? ssb[0] : smb_[0];
            float acc1 = hh ? ssb[1] : smb_[1];
            const u32* zfh = (const u32*)&g_zfh[cz & 1][bb][0];
            const u32* zfl = (const u32*)&g_zfl[cz & 1][bb][0];
            const int mt_r = r >> 4;
            const int lnb  = (r & 7) * 4;
            const int regb = (r >> 3) & 1;
#pragma unroll 4
            for (int hp = 0; hp < 64; hp++) {
                int h  = hp * 2;
                int kt = h >> 4, kk = h & 15;
                int idx = ((kt * 8 + mt_r) * 32 + lnb + ((kk & 7) >> 1)) * 4
                          + regb + 2 * (kk >> 3);
                u32 vh = __ldcg(zfh + idx);
                u32 vl = __ldcg(zfl + idx);
                float z0f = bf2f(vh & 0xffffu) + bf2f(vl & 0xffffu);
                float z1f = bf2f(vh >> 16) + bf2f(vl >> 16);
                acc0 = fmaf(z0f, wsel[h * 2 + 0], acc0);
                acc1 = fmaf(z0f, wsel[h * 2 + 1], acc1);
                acc0 = fmaf(z1f, wsel[(h + 1) * 2 + 0], acc0);
                acc1 = fmaf(z1f, wsel[(h + 1) * 2 + 1], acc1);
            }
            if (hh) { acc0 = softplus_f(acc0); acc1 = softplus_f(acc1); }
            float* dst = out + (hh ? (size_t)NBATCH * NIVL * NOUT : 0)
                         + ((size_t)b * NIVL + tau) * NOUT + g * 2;
            dst[0] = acc0;
            dst[1] = acc1;
        }
    }

    // ---- end-of-kernel reset for deterministic graph replay ----
    gbar_val(bb, 1u);
    if (tid == 0 && g == 0) {
        g_cc[bb][0].v = 0u;
        g_cc[bb][1].v = 0u;
        g_cc[bb][2].v = 0u;
    }
    gbar_val(bb, 0u);
}

extern "C" void kernel_launch(void* const* d_in, const int* in_sizes, int n_in,
                              void* d_out, int out_size) {
    const float* t   = (const float*)d_in[0];
    const float* z0  = (const float*)d_in[1];
    const float* X   = (const float*)d_in[2];
    const float* W1  = (const float*)d_in[3];
    const float* b1  = (const float*)d_in[4];
    const float* W2  = (const float*)d_in[5];
    const float* b2  = (const float*)d_in[6];
    const float* W3  = (const float*)d_in[7];
    const float* b3  = (const float*)d_in[8];
    const float* mW  = (const float*)d_in[9];
    const float* mb  = (const float*)d_in[10];
    const float* sW  = (const float*)d_in[11];
    const float* sb  = (const float*)d_in[12];
    float* out = (float*)d_out;

    cudaFuncSetAttribute(cde_persistent,
                         cudaFuncAttributeMaxDynamicSharedMemorySize, SMEM_BYTES);
    cde_persistent<<<GRID_CTAS, TPB, SMEM_BYTES>>>(t, z0, X, W1, b1, W2, b2,
                                                   W3, b3, mW, mb, sW, sb, out);
}

// round 14
// speedup vs baseline: 1.9433x; 1.0265x over previous
#include <cuda_runtime.h>
#include <cuda_bf16.h>

typedef unsigned long long u64;
typedef unsigned int u32;

#define NBATCH 512
#define NTT    257
#define NIVL   256
#define NIN    32
#define NH     128
#define NBN    256
#define NOUT   64
#define GRID_CTAS 128
#define TPB    256
#define NGRP   32

// ---- shared memory byte offsets ----
#define SM_FRAGB 0          // W3 B-frags [16kt][16nt][32] uint4 = 128KB
#define SM_W1F   131072     // W1 B-frags [8kt][32] uint4 = 4KB
#define SM_W2F   135168     // W2 B-frags [16kt][32] uint4 = 8KB
#define SM_B3    143360     // [128] f32
#define SM_B1    143872     // [8]
#define SM_B2    143904     // [8]
#define SM_MW    143936     // [128][2]
#define SM_SW    144960     // [128][2]
#define SM_MB    145984     // [2]
#define SM_SB    145992     // [2]
#define SMEM_BYTES 146016

// ---- global frag exchanges (parity double-buffered, per bb) ----
__device__ uint4 g_zfh[2][4][2048];   // z  frags: 8kt x 8mt x 32
__device__ uint4 g_zfl[2][4][2048];
__device__ uint4 g_f1h[2][4][4096];   // h1 frags: 16kt x 8mt x 32
__device__ uint4 g_f1l[2][4][4096];
__device__ uint4 g_fAh[2][4][4096];   // h2 frags
__device__ uint4 g_fAl[2][4][4096];

// ---- dependency-exact arrive counters ----
// cz[bb][m]  : z rows {2m,2m+1}; producers = warps (m, nh=0/1) x 32 CTAs -> target 64/phase
// c1[bb][wid]: h1 rows mt=wid;   producers = warp wid x 32 CTAs          -> target 32/phase
// c2[bb][wid]: h2 rows mt=wid;   producers = warp wid x 32 CTAs          -> target 32/phase
struct PadCnt { unsigned v; unsigned pad[127]; };
__device__ PadCnt g_czc[4][4];
__device__ PadCnt g_c1c[4][8];
__device__ PadCnt g_c2c[4][8];

struct PadU { unsigned v; unsigned pad[31]; };
__device__ PadU g_cnt[4];
__device__ PadU g_rel[4];

// ---- helpers ----
__device__ __forceinline__ float fast_tanh(float x) {
    float e;
    asm("ex2.approx.f32 %0, %1;" : "=f"(e) : "f"(x * 2.8853900817779268f));
    float r;
    asm("rcp.approx.f32 %0, %1;" : "=f"(r) : "f"(e + 1.0f));
    return fmaf(-2.0f, r, 1.0f);
}
__device__ __forceinline__ float softplus_f(float x) {
    return fmaxf(x, 0.0f) + log1pf(expf(-fabsf(x)));
}
__device__ __forceinline__ void mma16816(float* c, uint4 a, u32 b0, u32 b1) {
    asm volatile(
        "mma.sync.aligned.m16n8k16.row.col.f32.bf16.bf16.f32 "
        "{%0,%1,%2,%3}, {%4,%5,%6,%7}, {%8,%9}, {%0,%1,%2,%3};"
        : "+f"(c[0]), "+f"(c[1]), "+f"(c[2]), "+f"(c[3])
        : "r"(a.x), "r"(a.y), "r"(a.z), "r"(a.w), "r"(b0), "r"(b1));
}
__device__ __forceinline__ void bf_split(float x, unsigned short& h, unsigned short& l) {
    __nv_bfloat16 bh = __float2bfloat16_rn(x);
    __nv_bfloat16 bl = __float2bfloat16_rn(x - __bfloat162float(bh));
    h = __bfloat16_as_ushort(bh);
    l = __bfloat16_as_ushort(bl);
}
__device__ __forceinline__ float bf2f(u32 bits16) {
    return __bfloat162float(__ushort_as_bfloat16((unsigned short)bits16));
}

// ---- warp-granularity publish / wait ----
__device__ __forceinline__ void warp_publish(PadCnt* c, int lane) {
    __syncwarp();
    if (lane == 0)
        asm volatile("red.release.gpu.global.add.u32 [%0], %1;"
                     :: "l"(&c->v), "r"(1u) : "memory");
}
__device__ __forceinline__ void warp_wait(PadCnt* c, unsigned target) {
    unsigned v;
    do {
        asm volatile("ld.acquire.gpu.u32 %0, [%1];"
                     : "=r"(v) : "l"(&c->v) : "memory");
    } while ((int)(v - target) < 0);
}
__device__ __forceinline__ void gbar_val(int grp, unsigned target) {
    __syncthreads();
    if (threadIdx.x == 0) {
        __threadfence();
        unsigned old = atomicAdd(&g_cnt[grp].v, 1u);
        if (old == (NGRP - 1u)) {
            g_cnt[grp].v = 0u;
            asm volatile("st.release.gpu.u32 [%0], %1;"
                         :: "l"(&g_rel[grp].v), "r"(target) : "memory");
        } else {
            unsigned v;
            do {
                asm volatile("ld.acquire.gpu.u32 %0, [%1];"
                             : "=r"(v) : "l"(&g_rel[grp].v) : "memory");
            } while (v != target);
        }
    }
    __syncthreads();
}

// ---- generic mma MLP stage (per warp): out 8 cols for rows mt=wid ----
template <int NKT>
__device__ __forceinline__ void mlp_mma(const uint4* __restrict__ fAh,
                                        const uint4* __restrict__ fAl,
                                        const uint4* __restrict__ sBf,
                                        const float* __restrict__ sbias,
                                        u64* __restrict__ outHi,
                                        u64* __restrict__ outLo,
                                        int wid, int lane, int g) {
    const int c0 = (lane & 3) * 2;
    float aP[4], aQ[4] = {0.f, 0.f, 0.f, 0.f}, aR[4] = {0.f, 0.f, 0.f, 0.f};
    aP[0] = sbias[c0];
    aP[1] = sbias[c0 + 1];
    aP[2] = sbias[c0];
    aP[3] = sbias[c0 + 1];

    uint4 rh[4], rl[4];
#pragma unroll
    for (int d = 0; d < 4; d++) {
        rh[d] = __ldcg(fAh + (d * 8 + wid) * 32 + lane);
        rl[d] = __ldcg(fAl + (d * 8 + wid) * 32 + lane);
    }
#pragma unroll
    for (int kt = 0; kt < NKT; kt++) {
        uint4 ah = rh[kt & 3], al = rl[kt & 3];
        if (kt + 4 < NKT) {
            rh[kt & 3] = __ldcg(fAh + ((kt + 4) * 8 + wid) * 32 + lane);
            rl[kt & 3] = __ldcg(fAl + ((kt + 4) * 8 + wid) * 32 + lane);
        }
        uint4 b = sBf[kt * 32 + lane];
        mma16816(aP, ah, b.x, b.y);
        mma16816(aQ, ah, b.z, b.w);
        mma16816(aR, al, b.x, b.y);
    }
    float o0 = fmaxf((aP[0] + aQ[0]) + aR[0], 0.f);
    float o1 = fmaxf((aP[1] + aQ[1]) + aR[1], 0.f);
    float o2 = fmaxf((aP[2] + aQ[2]) + aR[2], 0.f);
    float o3 = fmaxf((aP[3] + aQ[3]) + aR[3], 0.f);

    unsigned short h0, h1, h2, h3, l0, l1, l2, l3;
    bf_split(o0, h0, l0); bf_split(o1, h1, l1);
    bf_split(o2, h2, l2); bf_split(o3, h3, l3);
    u32 hiA = ((u32)h1 << 16) | h0;
    u32 hiB = ((u32)h3 << 16) | h2;
    u32 loA = ((u32)l1 << 16) | l0;
    u32 loB = ((u32)l3 << 16) | l2;

    const int F = ((g >> 1) * 8 + wid) * 32 + (lane >> 2) * 4 + (lane & 3);
    const int slot = F * 2 + (g & 1);
    __stcg(&outHi[slot], (u64)hiA | ((u64)hiB << 32));
    __stcg(&outLo[slot], (u64)loA | ((u64)loB << 32));
}

// ================= persistent kernel =================
__global__ void __launch_bounds__(TPB, 1)
cde_persistent(const float* __restrict__ t, const float* __restrict__ z0,
               const float* __restrict__ X,
               const float* __restrict__ W1, const float* __restrict__ b1,
               const float* __restrict__ W2, const float* __restrict__ b2,
               const float* __restrict__ W3, const float* __restrict__ b3,
               const float* __restrict__ mW, const float* __restrict__ mb,
               const float* __restrict__ sWp, const float* __restrict__ sbp,
               float* __restrict__ out) {
    extern __shared__ char smb[];
    uint4* sFragB = (uint4*)(smb + SM_FRAGB);
    uint4* sW1f  = (uint4*)(smb + SM_W1F);
    uint4* sW2f  = (uint4*)(smb + SM_W2F);
    float* sb3   = (float*)(smb + SM_B3);
    float* sb1   = (float*)(smb + SM_B1);
    float* sb2   = (float*)(smb + SM_B2);
    float* smW   = (float*)(smb + SM_MW);
    float* ssW   = (float*)(smb + SM_SW);
    float* smb_  = (float*)(smb + SM_MB);
    float* ssb   = (float*)(smb + SM_SB);

    const int tid  = threadIdx.x;
    const int wid  = tid >> 5;
    const int lane = tid & 31;
    const int bb   = blockIdx.x >> 5;
    const int g    = blockIdx.x & 31;
    const int rowBase = bb * 128;

    // ---- init: W3 slice -> B fragments ----
    for (int i = tid; i < 16 * 16 * 32; i += TPB) {
        int ln = i & 31, nt = (i >> 5) & 15, kt = i >> 9;
        int nl = nt * 8 + (ln >> 2);
        int k0 = kt * 16 + (ln & 3) * 2;
        const float* wp = W3 + (size_t)k0 * 4096 + g * 128 + nl;
        unsigned short h0, h1, h8, h9, l0, l1, l8, l9;
        bf_split(wp[0],        h0, l0);
        bf_split(wp[4096],     h1, l1);
        bf_split(wp[8 * 4096], h8, l8);
        bf_split(wp[9 * 4096], h9, l9);
        uint4 v;
        v.x = ((u32)h1 << 16) | h0;
        v.y = ((u32)h9 << 16) | h8;
        v.z = ((u32)l1 << 16) | l0;
        v.w = ((u32)l9 << 16) | l8;
        sFragB[i] = v;
    }
    // W1 slice -> B-frags [8kt][32]
    for (int i = tid; i < 8 * 32; i += TPB) {
        int kt = i >> 5, ln = i & 31;
        int n  = g * 8 + (ln >> 2);
        int k0 = kt * 16 + (ln & 3) * 2;
        unsigned short h0, h1, h8, h9, l0, l1, l8, l9;
        bf_split(__ldg(&W1[(size_t)k0 * 256 + n]),       h0, l0);
        bf_split(__ldg(&W1[(size_t)(k0 + 1) * 256 + n]), h1, l1);
        bf_split(__ldg(&W1[(size_t)(k0 + 8) * 256 + n]), h8, l8);
        bf_split(__ldg(&W1[(size_t)(k0 + 9) * 256 + n]), h9, l9);
        uint4 v;
        v.x = ((u32)h1 << 16) | h0;
        v.y = ((u32)h9 << 16) | h8;
        v.z = ((u32)l1 << 16) | l0;
        v.w = ((u32)l9 << 16) | l8;
        sW1f[i] = v;
    }
    // W2 slice -> B-frags [16kt][32]
    for (int i = tid; i < 16 * 32; i += TPB) {
        int kt = i >> 5, ln = i & 31;
        int n  = g * 8 + (ln >> 2);
        int k0 = kt * 16 + (ln & 3) * 2;
        unsigned short h0, h1, h8, h9, l0, l1, l8, l9;
        bf_split(__ldg(&W2[(size_t)k0 * 256 + n]),       h0, l0);
        bf_split(__ldg(&W2[(size_t)(k0 + 1) * 256 + n]), h1, l1);
        bf_split(__ldg(&W2[(size_t)(k0 + 8) * 256 + n]), h8, l8);
        bf_split(__ldg(&W2[(size_t)(k0 + 9) * 256 + n]), h9, l9);
        uint4 v;
        v.x = ((u32)h1 << 16) | h0;
        v.y = ((u32)h9 << 16) | h8;
        v.z = ((u32)l1 << 16) | l0;
        v.w = ((u32)l9 << 16) | l8;
        sW2f[i] = v;
    }
    for (int i = tid; i < 128; i += TPB) sb3[i] = __ldg(&b3[g * 128 + i]);
    if (tid < 8)  sb1[tid] = __ldg(&b1[g * 8 + tid]);
    if (tid >= 8 && tid < 16) sb2[tid - 8] = __ldg(&b2[g * 8 + tid - 8]);
    for (int i = tid; i < 256; i += TPB) {
        int h = i >> 1, c = i & 1;
        smW[i] = __ldg(&mW[(size_t)h * 64 + g * 2 + c]);
        ssW[i] = __ldg(&sWp[(size_t)h * 64 + g * 2 + c]);
    }
    if (tid < 2)  smb_[tid] = __ldg(&mb[g * 2 + tid]);
    if (tid >= 2 && tid < 4) ssb[tid - 2] = __ldg(&sbp[g * 2 + tid - 2]);

    // ---- warp-local RK state (redundant across quad lanes) ----
    const int m    = wid & 3;
    const int nh   = wid >> 2;
    const int rsub = lane >> 2;
    const int t4   = lane & 3;
    const int mbase = m * 32;

    PadCnt* CZm = &g_czc[bb][0];          // wait: stage1 warp wid -> CZm[wid>>1]
    PadCnt* C1m = &g_c1c[bb][0];
    PadCnt* C2m = &g_c2c[bb][0];

    float zb[2][2][2];    // [mti][rp][hl], cols g*4 + nh*2 + hl
#pragma unroll
    for (int mti = 0; mti < 2; mti++)
#pragma unroll
        for (int rp = 0; rp < 2; rp++) {
            int row = rowBase + mbase + mti * 16 + rsub + rp * 8;
            float2 z = __ldg((const float2*)&z0[(size_t)row * 128 + g * 4 + nh * 2]);
            zb[mti][rp][0] = z.x;
            zb[mti][rp][1] = z.y;
        }

    // ---- bootstrap: write z0 frags at parity 1 ----
    {
        u32* zfh = (u32*)&g_zfh[1][bb][0];
        u32* zfl = (u32*)&g_zfl[1][bb][0];
        for (int i = tid; i < 256; i += TPB) {
            int r = i >> 1, ps = i & 1;
            int c0 = g * 4 + ps * 2;
            float v0 = __ldg(&z0[(size_t)(rowBase + r) * 128 + c0]);
            float v1 = __ldg(&z0[(size_t)(rowBase + r) * 128 + c0 + 1]);
            unsigned short h0, l0, h1, l1;
            bf_split(v0, h0, l0);
            bf_split(v1, h1, l1);
            int kt = g >> 2, kk = c0 & 15;
            int mt = r >> 4, ln = (r & 7) * 4 + ((kk & 7) >> 1);
            int reg = ((r >> 3) & 1) + 2 * (kk >> 3);
            int idx = ((kt * 8 + mt) * 32 + ln) * 4 + reg;
            zfh[idx] = ((u32)h1 << 16) | h0;
            zfl[idx] = ((u32)l1 << 16) | l0;
        }
    }
    __syncthreads();                 // all bootstrap stores done CTA-wide
    warp_publish(&CZm[m], lane);     // warp (m,nh) arrives on cz[m] -> 2/CTA/m
    unsigned cz = 1, c1 = 0, c2 = 0;

#pragma unroll 1
    for (int tau = 0; tau < NIVL; tau++) {
        float t0v = __ldg(&t[tau]);
        float t1v = __ldg(&t[tau + 1]);
        float dti = t1v - t0v;
        float hstep = dti * 0.25f;
        float h6 = hstep / 6.0f;

        // dxdt into registers: [mti][rp][8]
        float dxm[2][2][8];
#pragma unroll
        for (int mti = 0; mti < 2; mti++)
#pragma unroll
            for (int rp = 0; rp < 2; rp++) {
                int row = rowBase + mbase + mti * 16 + rsub + rp * 8;
                const float* Xr = X + ((size_t)row * NTT + tau) * NIN;
#pragma unroll
                for (int blk = 0; blk < 4; blk++) {
                    float2 x0 = __ldg((const float2*)(Xr + blk * 8 + t4 * 2));
                    float2 x1 = __ldg((const float2*)(Xr + NIN + blk * 8 + t4 * 2));
                    dxm[mti][rp][blk * 2 + 0] = (x1.x - x0.x) / dti;
                    dxm[mti][rp][blk * 2 + 1] = (x1.y - x0.y) / dti;
                }
            }

#pragma unroll 1
        for (int sub = 0; sub < 4; sub++) {
            float aacc[2][2][2] = {};
#pragma unroll 1
            for (int s = 0; s < 4; s++) {
                // stage1 warp wid consumes z rows mt=wid -> cz[wid>>1], 64 arrivals
                warp_wait(&CZm[wid >> 1], cz * 64u);
                const int pz = cz & 1;

                // ---- stage 1 (mma): z-frags -> h1-frags (rows mt=wid) ----
                ++c1; const int p1 = c1 & 1;
                mlp_mma<8>(&g_zfh[pz][bb][0], &g_zfl[pz][bb][0], sW1f, sb1,
                           (u64*)&g_f1h[p1][bb][0], (u64*)&g_f1l[p1][bb][0],
                           wid, lane, g);
                warp_publish(&C1m[wid], lane);
                warp_wait(&C1m[wid], c1 * 32u);

                // ---- stage 2 (mma): h1-frags -> h2-frags (rows mt=wid) ----
                ++c2; const int p2 = c2 & 1;
                mlp_mma<16>(&g_f1h[p1][bb][0], &g_f1l[p1][bb][0], sW2f, sb2,
                            (u64*)&g_fAh[p2][bb][0], (u64*)&g_fAl[p2][bb][0],
                            wid, lane, g);
                warp_publish(&C2m[wid], lane);
                // stage3 needs h2 rows {2m, 2m+1}
                warp_wait(&C2m[2 * m + 0], c2 * 32u);
                warp_wait(&C2m[2 * m + 1], c2 * 32u);

                // ---- stage 3: mma, 2 m-tiles x 8 n-tiles per warp ----
                float acc[2][8][4];
#pragma unroll
                for (int nt = 0; nt < 8; nt++) {
                    float bx = sb3[nh * 64 + nt * 8 + t4 * 2];
                    float by = sb3[nh * 64 + nt * 8 + t4 * 2 + 1];
                    acc[0][nt][0] = bx; acc[0][nt][1] = by;
                    acc[0][nt][2] = bx; acc[0][nt][3] = by;
                    acc[1][nt][0] = bx; acc[1][nt][1] = by;
                    acc[1][nt][2] = bx; acc[1][nt][3] = by;
                }
                const uint4* fAh = &g_fAh[p2][bb][0];
                const uint4* fAl = &g_fAl[p2][bb][0];
                uint4 a0h = __ldcg(fAh + (2 * m + 0) * 32 + lane);
                uint4 a0l = __ldcg(fAl + (2 * m + 0) * 32 + lane);
                uint4 a1h = __ldcg(fAh + (2 * m + 1) * 32 + lane);
                uint4 a1l = __ldcg(fAl + (2 * m + 1) * 32 + lane);
#pragma unroll 1
                for (int kt = 0; kt < 16; kt++) {
                    uint4 n0h, n0l, n1h, n1l;
                    if (kt < 15) {
                        n0h = __ldcg(fAh + ((kt + 1) * 8 + 2 * m + 0) * 32 + lane);
                        n0l = __ldcg(fAl + ((kt + 1) * 8 + 2 * m + 0) * 32 + lane);
                        n1h = __ldcg(fAh + ((kt + 1) * 8 + 2 * m + 1) * 32 + lane);
                        n1l = __ldcg(fAl + ((kt + 1) * 8 + 2 * m + 1) * 32 + lane);
                    }
                    const uint4* bfr = sFragB + (kt * 16 + nh * 8) * 32 + lane;
#pragma unroll
                    for (int nt = 0; nt < 8; nt++) {
                        uint4 b = bfr[nt * 32];
                        mma16816(acc[0][nt], a0h, b.x, b.y);
                        mma16816(acc[0][nt], a0h, b.z, b.w);
                        mma16816(acc[0][nt], a0l, b.x, b.y);
                        mma16816(acc[1][nt], a1h, b.x, b.y);
                        mma16816(acc[1][nt], a1h, b.z, b.w);
                        mma16816(acc[1][nt], a1l, b.x, b.y);
                    }
                    a0h = n0h; a0l = n0l; a1h = n1h; a1l = n1l;
                }

                // ---- epilogue: tanh + dxdt contraction, butterfly over t4 ----
                float kq[2][2][2] = {};
#pragma unroll
                for (int mti = 0; mti < 2; mti++) {
#pragma unroll
                    for (int nt = 0; nt < 8; nt++) {
                        int hl = nt >> 2, iblk = nt & 3;
                        float y;
                        y = fast_tanh(acc[mti][nt][0]);
                        kq[mti][0][hl] = fmaf(y, dxm[mti][0][iblk * 2],     kq[mti][0][hl]);
                        y = fast_tanh(acc[mti][nt][1]);
                        kq[mti][0][hl] = fmaf(y, dxm[mti][0][iblk * 2 + 1], kq[mti][0][hl]);
                        y = fast_tanh(acc[mti][nt][2]);
                        kq[mti][1][hl] = fmaf(y, dxm[mti][1][iblk * 2],     kq[mti][1][hl]);
                        y = fast_tanh(acc[mti][nt][3]);
                        kq[mti][1][hl] = fmaf(y, dxm[mti][1][iblk * 2 + 1], kq[mti][1][hl]);
                    }
                }
#pragma unroll
                for (int mti = 0; mti < 2; mti++)
#pragma unroll
                    for (int rp = 0; rp < 2; rp++)
#pragma unroll
                        for (int hl = 0; hl < 2; hl++) {
                            float v = kq[mti][rp][hl];
                            v += __shfl_xor_sync(0xffffffffu, v, 1);
                            v += __shfl_xor_sync(0xffffffffu, v, 2);
                            kq[mti][rp][hl] = v;
                        }

                // ---- RK update + publish z-frags for next stage ----
                const float ws = (s == 0 || s == 3) ? 1.f : 2.f;
                const float cnext = (s == 2) ? hstep : 0.5f * hstep;
                ++cz; const int pzn = cz & 1;
                float zn[2][2][2];
#pragma unroll
                for (int mti = 0; mti < 2; mti++)
#pragma unroll
                    for (int rp = 0; rp < 2; rp++)
#pragma unroll
                        for (int hl = 0; hl < 2; hl++) {
                            float kv = kq[mti][rp][hl];
                            aacc[mti][rp][hl] = fmaf(ws, kv, aacc[mti][rp][hl]);
                            if (s < 3) {
                                zn[mti][rp][hl] = fmaf(cnext, kv, zb[mti][rp][hl]);
                            } else {
                                zb[mti][rp][hl] = fmaf(h6, aacc[mti][rp][hl],
                                                       zb[mti][rp][hl]);
                                zn[mti][rp][hl] = zb[mti][rp][hl];
                            }
                        }
                {
                    const int mti_w = t4 & 1, rp_w = t4 >> 1;
                    unsigned short zh0, zl0, zh1, zl1;
                    bf_split(zn[mti_w][rp_w][0], zh0, zl0);
                    bf_split(zn[mti_w][rp_w][1], zh1, zl1);
                    const int c0 = g * 4 + nh * 2;
                    const int kk = c0 & 15, kt = g >> 2;
                    const int mt = 2 * m + mti_w;
                    const int ln = rsub * 4 + ((kk & 7) >> 1);
                    const int reg = (t4 >> 1) + 2 * (kk >> 3);
                    const int idx = ((kt * 8 + mt) * 32 + ln) * 4 + reg;
                    __stcg(&((u32*)&g_zfh[pzn][bb][0])[idx], ((u32)zh1 << 16) | zh0);
                    __stcg(&((u32*)&g_zfl[pzn][bb][0])[idx], ((u32)zl1 << 16) | zl0);
                }
                warp_publish(&CZm[m], lane);
            }
        }

        // ---- interval end: output heads from z-frags (need ALL z) ----
        warp_wait(&CZm[0], cz * 64u);
        warp_wait(&CZm[1], cz * 64u);
        warp_wait(&CZm[2], cz * 64u);
        warp_wait(&CZm[3], cz * 64u);
        {
            const int r  = tid & 127;
            const int hh = tid >> 7;
            const int b  = rowBase + r;
            const float* wsel = hh ? ssW : smW;
            float acc0 = hh ? ssb[0] : smb_[0];
            float acc1 = hh ? ssb[1] : smb_[1];
            const u32* zfh = (const u32*)&g_zfh[cz & 1][bb][0];
            const u32* zfl = (const u32*)&g_zfl[cz & 1][bb][0];
            const int mt_r = r >> 4;
            const int lnb  = (r & 7) * 4;
            const int regb = (r >> 3) & 1;
#pragma unroll 4
            for (int hp = 0; hp < 64; hp++) {
                int h  = hp * 2;
                int kt = h >> 4, kk = h & 15;
                int idx = ((kt * 8 + mt_r) * 32 + lnb + ((kk & 7) >> 1)) * 4
                          + regb + 2 * (kk >> 3);
                u32 vh = __ldcg(zfh + idx);
                u32 vl = __ldcg(zfl + idx);
                float z0f = bf2f(vh & 0xffffu) + bf2f(vl & 0xffffu);
                float z1f = bf2f(vh >> 16) + bf2f(vl >> 16);
                acc0 = fmaf(z0f, wsel[h * 2 + 0], acc0);
                acc1 = fmaf(z0f, wsel[h * 2 + 1], acc1);
                acc0 = fmaf(z1f, wsel[(h + 1) * 2 + 0], acc0);
                acc1 = fmaf(z1f, wsel[(h + 1) * 2 + 1], acc1);
            }
            if (hh) { acc0 = softplus_f(acc0); acc1 = softplus_f(acc1); }
            float* dst = out + (hh ? (size_t)NBATCH * NIVL * NOUT : 0)
                         + ((size_t)b * NIVL + tau) * NOUT + g * 2;
            dst[0] = acc0;
            dst[1] = acc1;
        }
    }

    // ---- end-of-kernel reset for deterministic graph replay ----
    gbar_val(bb, 1u);
    if (tid == 0 && g == 0) {
#pragma unroll
        for (int q = 0; q < 4; q++) g_czc[bb][q].v = 0u;
#pragma unroll
        for (int q = 0; q < 8; q++) {
            g_c1c[bb][q].v = 0u;
            g_c2c[bb][q].v = 0u;
        }
    }
    gbar_val(bb, 0u);
}

extern "C" void kernel_launch(void* const* d_in, const int* in_sizes, int n_in,
                              void* d_out, int out_size) {
    const float* t   = (const float*)d_in[0];
    const float* z0  = (const float*)d_in[1];
    const float* X   = (const float*)d_in[2];
    const float* W1  = (const float*)d_in[3];
    const float* b1  = (const float*)d_in[4];
    const float* W2  = (const float*)d_in[5];
    const float* b2  = (const float*)d_in[6];
    const float* W3  = (const float*)d_in[7];
    const float* b3  = (const float*)d_in[8];
    const float* mW  = (const float*)d_in[9];
    const float* mb  = (const float*)d_in[10];
    const float* sW  = (const float*)d_in[11];
    const float* sb  = (const float*)d_in[12];
    float* out = (float*)d_out;

    cudaFuncSetAttribute(cde_persistent,
                         cudaFuncAttributeMaxDynamicSharedMemorySize, SMEM_BYTES);
    cde_persistent<<<GRID_CTAS, TPB, SMEM_BYTES>>>(t, z0, X, W1, b1, W2, b2,
                                                   W3, b3, mW, mb, sW, sb, out);
}

// round 15
// speedup vs baseline: 2.1969x; 1.1305x over previous
#include <cuda_runtime.h>
#include <cuda_bf16.h>

typedef unsigned long long u64;
typedef unsigned int u32;

#define NBATCH 512
#define NTT    257
#define NIVL   256
#define NIN    32
#define NH     128
#define NBN    256
#define NOUT   64
#define GRID_CTAS 128
#define TPB    256
#define NGRP   32

// ---- shared memory byte offsets (shared by both chains of a CTA) ----
#define SM_FRAGB 0          // W3 B-frags [16kt][16nt][32] uint4 = 128KB
#define SM_W1F   131072     // W1 B-frags [8kt][32] uint4 = 4KB
#define SM_W2F   135168     // W2 B-frags [16kt][32] uint4 = 8KB
#define SM_B3    143360     // [128] f32
#define SM_B1    143872     // [8]
#define SM_B2    143904     // [8]
#define SM_MW    143936     // [128][2]
#define SM_SW    144960     // [128][2]
#define SM_MB    145984     // [2]
#define SM_SB    145992     // [2]
#define SMEM_BYTES 146016

// ---- global frag exchanges: per chain (8 chains of 64 rows), parity 2 ----
__device__ uint4 g_zfh[2][8][1024];   // z  frags: 8kt x 4mt x 32
__device__ uint4 g_zfl[2][8][1024];
__device__ uint4 g_f1h[2][8][2048];   // h1 frags: 16kt x 4mt x 32
__device__ uint4 g_f1l[2][8][2048];
__device__ uint4 g_fAh[2][8][2048];   // h2 frags
__device__ uint4 g_fAl[2][8][2048];

// ---- diagonal counters: [chain][mt], producers = warp mt of 32 CTAs ----
struct PadCnt { unsigned v; unsigned pad[127]; };
__device__ PadCnt g_czc[8][4];
__device__ PadCnt g_c1c[8][4];
__device__ PadCnt g_c2c[8][4];

struct PadU { unsigned v; unsigned pad[31]; };
__device__ PadU g_cnt[4];
__device__ PadU g_rel[4];

// ---- helpers ----
__device__ __forceinline__ float fast_tanh(float x) {
    float e;
    asm("ex2.approx.f32 %0, %1;" : "=f"(e) : "f"(x * 2.8853900817779268f));
    float r;
    asm("rcp.approx.f32 %0, %1;" : "=f"(r) : "f"(e + 1.0f));
    return fmaf(-2.0f, r, 1.0f);
}
__device__ __forceinline__ float softplus_f(float x) {
    return fmaxf(x, 0.0f) + log1pf(expf(-fabsf(x)));
}
__device__ __forceinline__ void mma16816(float* c, uint4 a, u32 b0, u32 b1) {
    asm volatile(
        "mma.sync.aligned.m16n8k16.row.col.f32.bf16.bf16.f32 "
        "{%0,%1,%2,%3}, {%4,%5,%6,%7}, {%8,%9}, {%0,%1,%2,%3};"
        : "+f"(c[0]), "+f"(c[1]), "+f"(c[2]), "+f"(c[3])
        : "r"(a.x), "r"(a.y), "r"(a.z), "r"(a.w), "r"(b0), "r"(b1));
}
__device__ __forceinline__ void bf_split(float x, unsigned short& h, unsigned short& l) {
    __nv_bfloat16 bh = __float2bfloat16_rn(x);
    __nv_bfloat16 bl = __float2bfloat16_rn(x - __bfloat162float(bh));
    h = __bfloat16_as_ushort(bh);
    l = __bfloat16_as_ushort(bl);
}
__device__ __forceinline__ float bf2f(u32 bits16) {
    return __bfloat162float(__ushort_as_bfloat16((unsigned short)bits16));
}

// ---- warp-granularity publish / wait ----
__device__ __forceinline__ void warp_publish(PadCnt* c, int lane) {
    __syncwarp();
    if (lane == 0)
        asm volatile("red.release.gpu.global.add.u32 [%0], %1;"
                     :: "l"(&c->v), "r"(1u) : "memory");
}
__device__ __forceinline__ void warp_wait(PadCnt* c, unsigned target) {
    unsigned v;
    do {
        asm volatile("ld.acquire.gpu.u32 %0, [%1];"
                     : "=r"(v) : "l"(&c->v) : "memory");
    } while ((int)(v - target) < 0);
}
__device__ __forceinline__ void gbar_val(int grp, unsigned target) {
    __syncthreads();
    if (threadIdx.x == 0) {
        __threadfence();
        unsigned old = atomicAdd(&g_cnt[grp].v, 1u);
        if (old == (NGRP - 1u)) {
            g_cnt[grp].v = 0u;
            asm volatile("st.release.gpu.u32 [%0], %1;"
                         :: "l"(&g_rel[grp].v), "r"(target) : "memory");
        } else {
            unsigned v;
            do {
                asm volatile("ld.acquire.gpu.u32 %0, [%1];"
                             : "=r"(v) : "l"(&g_rel[grp].v) : "memory");
            } while (v != target);
        }
    }
    __syncthreads();
}

// ---- per-warp mma MLP stage: rows mt=w (16), out 8 cols (N-slice g) ----
// A-frags (hi/lo) from gmem with 4-mt layout; B-frags from smem.
template <int NKT>
__device__ __forceinline__ void mlp_mma(const uint4* __restrict__ fAh,
                                        const uint4* __restrict__ fAl,
                                        const uint4* __restrict__ sBf,
                                        const float* __restrict__ sbias,
                                        u64* __restrict__ outHi,
                                        u64* __restrict__ outLo,
                                        int w, int lane, int g) {
    const int c0 = (lane & 3) * 2;
    float aP[4], aQ[4] = {0.f, 0.f, 0.f, 0.f}, aR[4] = {0.f, 0.f, 0.f, 0.f};
    aP[0] = sbias[c0];
    aP[1] = sbias[c0 + 1];
    aP[2] = sbias[c0];
    aP[3] = sbias[c0 + 1];

    uint4 rh[4], rl[4];
#pragma unroll
    for (int d = 0; d < 4; d++) {
        int dd = (d < NKT) ? d : (NKT - 1);
        rh[d] = __ldcg(fAh + (dd * 4 + w) * 32 + lane);
        rl[d] = __ldcg(fAl + (dd * 4 + w) * 32 + lane);
    }
#pragma unroll
    for (int kt = 0; kt < NKT; kt++) {
        uint4 ah = rh[kt & 3], al = rl[kt & 3];
        if (kt + 4 < NKT) {
            rh[kt & 3] = __ldcg(fAh + ((kt + 4) * 4 + w) * 32 + lane);
            rl[kt & 3] = __ldcg(fAl + ((kt + 4) * 4 + w) * 32 + lane);
        }
        uint4 b = sBf[kt * 32 + lane];
        mma16816(aP, ah, b.x, b.y);
        mma16816(aQ, ah, b.z, b.w);
        mma16816(aR, al, b.x, b.y);
    }
    float o0 = fmaxf((aP[0] + aQ[0]) + aR[0], 0.f);
    float o1 = fmaxf((aP[1] + aQ[1]) + aR[1], 0.f);
    float o2 = fmaxf((aP[2] + aQ[2]) + aR[2], 0.f);
    float o3 = fmaxf((aP[3] + aQ[3]) + aR[3], 0.f);

    unsigned short h0, h1, h2, h3, l0, l1, l2, l3;
    bf_split(o0, h0, l0); bf_split(o1, h1, l1);
    bf_split(o2, h2, l2); bf_split(o3, h3, l3);
    u32 hiA = ((u32)h1 << 16) | h0;
    u32 hiB = ((u32)h3 << 16) | h2;
    u32 loA = ((u32)l1 << 16) | l0;
    u32 loB = ((u32)l3 << 16) | l2;

    const int F = ((g >> 1) * 4 + w) * 32 + (lane >> 2) * 4 + (lane & 3);
    const int slot = F * 2 + (g & 1);
    __stcg(&outHi[slot], (u64)hiA | ((u64)hiB << 32));
    __stcg(&outLo[slot], (u64)loA | ((u64)loB << 32));
}

// ================= persistent kernel =================
__global__ void __launch_bounds__(TPB, 1)
cde_persistent(const float* __restrict__ t, const float* __restrict__ z0,
               const float* __restrict__ X,
               const float* __restrict__ W1, const float* __restrict__ b1,
               const float* __restrict__ W2, const float* __restrict__ b2,
               const float* __restrict__ W3, const float* __restrict__ b3,
               const float* __restrict__ mW, const float* __restrict__ mb,
               const float* __restrict__ sWp, const float* __restrict__ sbp,
               float* __restrict__ out) {
    extern __shared__ char smb[];
    uint4* sFragB = (uint4*)(smb + SM_FRAGB);
    uint4* sW1f  = (uint4*)(smb + SM_W1F);
    uint4* sW2f  = (uint4*)(smb + SM_W2F);
    float* sb3   = (float*)(smb + SM_B3);
    float* sb1   = (float*)(smb + SM_B1);
    float* sb2   = (float*)(smb + SM_B2);
    float* smW   = (float*)(smb + SM_MW);
    float* ssW   = (float*)(smb + SM_SW);
    float* smb_  = (float*)(smb + SM_MB);
    float* ssb   = (float*)(smb + SM_SB);

    const int tid  = threadIdx.x;
    const int wid  = tid >> 5;
    const int lane = tid & 31;
    const int p    = blockIdx.x >> 5;      // CTA pool 0..3
    const int g    = blockIdx.x & 31;      // column group 0..31
    const int chx  = wid >> 2;             // chain select within CTA
    const int w    = wid & 3;              // m-tile / pipeline index
    const int chain = p * 2 + chx;         // 0..7
    const int rowBase = chain * 64;

    PadCnt* CZ = &g_czc[chain][0];
    PadCnt* C1 = &g_c1c[chain][0];
    PadCnt* C2 = &g_c2c[chain][0];

    // ---- init: W3 slice -> B fragments ----
    for (int i = tid; i < 16 * 16 * 32; i += TPB) {
        int ln = i & 31, nt = (i >> 5) & 15, kt = i >> 9;
        int nl = nt * 8 + (ln >> 2);
        int k0 = kt * 16 + (ln & 3) * 2;
        const float* wp = W3 + (size_t)k0 * 4096 + g * 128 + nl;
        unsigned short h0, h1, h8, h9, l0, l1, l8, l9;
        bf_split(wp[0],        h0, l0);
        bf_split(wp[4096],     h1, l1);
        bf_split(wp[8 * 4096], h8, l8);
        bf_split(wp[9 * 4096], h9, l9);
        uint4 v;
        v.x = ((u32)h1 << 16) | h0;
        v.y = ((u32)h9 << 16) | h8;
        v.z = ((u32)l1 << 16) | l0;
        v.w = ((u32)l9 << 16) | l8;
        sFragB[i] = v;
    }
    for (int i = tid; i < 8 * 32; i += TPB) {
        int kt = i >> 5, ln = i & 31;
        int n  = g * 8 + (ln >> 2);
        int k0 = kt * 16 + (ln & 3) * 2;
        unsigned short h0, h1, h8, h9, l0, l1, l8, l9;
        bf_split(__ldg(&W1[(size_t)k0 * 256 + n]),       h0, l0);
        bf_split(__ldg(&W1[(size_t)(k0 + 1) * 256 + n]), h1, l1);
        bf_split(__ldg(&W1[(size_t)(k0 + 8) * 256 + n]), h8, l8);
        bf_split(__ldg(&W1[(size_t)(k0 + 9) * 256 + n]), h9, l9);
        uint4 v;
        v.x = ((u32)h1 << 16) | h0;
        v.y = ((u32)h9 << 16) | h8;
        v.z = ((u32)l1 << 16) | l0;
        v.w = ((u32)l9 << 16) | l8;
        sW1f[i] = v;
    }
    for (int i = tid; i < 16 * 32; i += TPB) {
        int kt = i >> 5, ln = i & 31;
        int n  = g * 8 + (ln >> 2);
        int k0 = kt * 16 + (ln & 3) * 2;
        unsigned short h0, h1, h8, h9, l0, l1, l8, l9;
        bf_split(__ldg(&W2[(size_t)k0 * 256 + n]),       h0, l0);
        bf_split(__ldg(&W2[(size_t)(k0 + 1) * 256 + n]), h1, l1);
        bf_split(__ldg(&W2[(size_t)(k0 + 8) * 256 + n]), h8, l8);
        bf_split(__ldg(&W2[(size_t)(k0 + 9) * 256 + n]), h9, l9);
        uint4 v;
        v.x = ((u32)h1 << 16) | h0;
        v.y = ((u32)h9 << 16) | h8;
        v.z = ((u32)l1 << 16) | l0;
        v.w = ((u32)l9 << 16) | l8;
        sW2f[i] = v;
    }
    for (int i = tid; i < 128; i += TPB) sb3[i] = __ldg(&b3[g * 128 + i]);
    if (tid < 8)  sb1[tid] = __ldg(&b1[g * 8 + tid]);
    if (tid >= 8 && tid < 16) sb2[tid - 8] = __ldg(&b2[g * 8 + tid - 8]);
    for (int i = tid; i < 256; i += TPB) {
        int h = i >> 1, c = i & 1;
        smW[i] = __ldg(&mW[(size_t)h * 64 + g * 2 + c]);
        ssW[i] = __ldg(&sWp[(size_t)h * 64 + g * 2 + c]);
    }
    if (tid < 2)  smb_[tid] = __ldg(&mb[g * 2 + tid]);
    if (tid >= 2 && tid < 4) ssb[tid - 2] = __ldg(&sbp[g * 2 + tid - 2]);

    // ---- warp-local RK state: rows w*16 + rsub (+8), h cols g*4..g*4+3 ----
    const int rsub = lane >> 2;
    const int t4   = lane & 3;

    float zb[2][4];   // [rp][hh]
#pragma unroll
    for (int rp = 0; rp < 2; rp++) {
        int row = rowBase + w * 16 + rsub + rp * 8;
        float4 z = __ldg((const float4*)&z0[(size_t)row * 128 + g * 4]);
        zb[rp][0] = z.x; zb[rp][1] = z.y; zb[rp][2] = z.z; zb[rp][3] = z.w;
    }

    // ---- bootstrap: z0 frags at parity 1 for both chains ----
    for (int i = tid; i < 256; i += TPB) {
        int cs = i >> 7, j = i & 127;
        int r = j >> 1, ps = j & 1;
        int chainB = p * 2 + cs;
        int c0 = g * 4 + ps * 2;
        int rowG = chainB * 64 + r;
        float v0 = __ldg(&z0[(size_t)rowG * 128 + c0]);
        float v1 = __ldg(&z0[(size_t)rowG * 128 + c0 + 1]);
        unsigned short h0, l0, h1, l1;
        bf_split(v0, h0, l0);
        bf_split(v1, h1, l1);
        int kt = g >> 2, kk = c0 & 15;
        int mt = r >> 4, rit = r & 15;
        int ln = (rit & 7) * 4 + ((kk & 7) >> 1);
        int reg = (rit >> 3) + 2 * (kk >> 3);
        int idx = ((kt * 4 + mt) * 32 + ln) * 4 + reg;
        ((u32*)&g_zfh[1][chainB][0])[idx] = ((u32)h1 << 16) | h0;
        ((u32*)&g_zfl[1][chainB][0])[idx] = ((u32)l1 << 16) | l0;
    }
    __syncthreads();
    warp_publish(&CZ[w], lane);
    unsigned cz = 1, c1 = 0, c2 = 0;

#pragma unroll 1
    for (int tau = 0; tau < NIVL; tau++) {
        float t0v = __ldg(&t[tau]);
        float t1v = __ldg(&t[tau + 1]);
        float dti = t1v - t0v;
        float hstep = dti * 0.25f;
        float h6 = hstep / 6.0f;

        // dxdt into registers [rp][8]
        float dxm[2][8];
#pragma unroll
        for (int rp = 0; rp < 2; rp++) {
            int row = rowBase + w * 16 + rsub + rp * 8;
            const float* Xr = X + ((size_t)row * NTT + tau) * NIN;
#pragma unroll
            for (int blk = 0; blk < 4; blk++) {
                float2 x0 = __ldg((const float2*)(Xr + blk * 8 + t4 * 2));
                float2 x1 = __ldg((const float2*)(Xr + NIN + blk * 8 + t4 * 2));
                dxm[rp][blk * 2 + 0] = (x1.x - x0.x) / dti;
                dxm[rp][blk * 2 + 1] = (x1.y - x0.y) / dti;
            }
        }

#pragma unroll 1
        for (int sub = 0; sub < 4; sub++) {
            float aacc[2][4] = {};
#pragma unroll 1
            for (int s = 0; s < 4; s++) {
                warp_wait(&CZ[w], cz * 32u);
                const int pz = cz & 1;

                // ---- stage 1 ----
                ++c1; const int p1 = c1 & 1;
                mlp_mma<8>(&g_zfh[pz][chain][0], &g_zfl[pz][chain][0], sW1f, sb1,
                           (u64*)&g_f1h[p1][chain][0], (u64*)&g_f1l[p1][chain][0],
                           w, lane, g);
                warp_publish(&C1[w], lane);
                warp_wait(&C1[w], c1 * 32u);

                // ---- stage 2 ----
                ++c2; const int p2 = c2 & 1;
                mlp_mma<16>(&g_f1h[p1][chain][0], &g_f1l[p1][chain][0], sW2f, sb2,
                            (u64*)&g_fAh[p2][chain][0], (u64*)&g_fAl[p2][chain][0],
                            w, lane, g);
                warp_publish(&C2[w], lane);
                warp_wait(&C2[w], c2 * 32u);

                // ---- stage 3: 1 m-tile x 16 n-tiles per warp ----
                float acc[16][4];
#pragma unroll
                for (int nt = 0; nt < 16; nt++) {
                    float bx = sb3[nt * 8 + t4 * 2];
                    float by = sb3[nt * 8 + t4 * 2 + 1];
                    acc[nt][0] = bx; acc[nt][1] = by;
                    acc[nt][2] = bx; acc[nt][3] = by;
                }
                const uint4* fAh = &g_fAh[p2][chain][0];
                const uint4* fAl = &g_fAl[p2][chain][0];
                uint4 ah = __ldcg(fAh + w * 32 + lane);
                uint4 al = __ldcg(fAl + w * 32 + lane);
#pragma unroll 1
                for (int kt = 0; kt < 16; kt++) {
                    uint4 nhf, nlf;
                    if (kt < 15) {
                        nhf = __ldcg(fAh + ((kt + 1) * 4 + w) * 32 + lane);
                        nlf = __ldcg(fAl + ((kt + 1) * 4 + w) * 32 + lane);
                    }
                    const uint4* bfr = sFragB + (kt * 16) * 32 + lane;
#pragma unroll
                    for (int nt = 0; nt < 16; nt++) {
                        uint4 b = bfr[nt * 32];
                        mma16816(acc[nt], ah, b.x, b.y);
                        mma16816(acc[nt], ah, b.z, b.w);
                        mma16816(acc[nt], al, b.x, b.y);
                    }
                    ah = nhf; al = nlf;
                }

                // ---- epilogue: tanh + dxdt, butterfly over t4 ----
                float kq[2][4] = {};
#pragma unroll
                for (int nt = 0; nt < 16; nt++) {
                    int hl = nt >> 2, iblk = nt & 3;
                    float y;
                    y = fast_tanh(acc[nt][0]);
                    kq[0][hl] = fmaf(y, dxm[0][iblk * 2],     kq[0][hl]);
                    y = fast_tanh(acc[nt][1]);
                    kq[0][hl] = fmaf(y, dxm[0][iblk * 2 + 1], kq[0][hl]);
                    y = fast_tanh(acc[nt][2]);
                    kq[1][hl] = fmaf(y, dxm[1][iblk * 2],     kq[1][hl]);
                    y = fast_tanh(acc[nt][3]);
                    kq[1][hl] = fmaf(y, dxm[1][iblk * 2 + 1], kq[1][hl]);
                }
#pragma unroll
                for (int rp = 0; rp < 2; rp++)
#pragma unroll
                    for (int hl = 0; hl < 4; hl++) {
                        float v = kq[rp][hl];
                        v += __shfl_xor_sync(0xffffffffu, v, 1);
                        v += __shfl_xor_sync(0xffffffffu, v, 2);
                        kq[rp][hl] = v;
                    }

                // ---- RK update + publish z-frags ----
                const float ws = (s == 0 || s == 3) ? 1.f : 2.f;
                const float cnext = (s == 2) ? hstep : 0.5f * hstep;
                ++cz; const int pzn = cz & 1;
                float zn[2][4];
#pragma unroll
                for (int rp = 0; rp < 2; rp++)
#pragma unroll
                    for (int hl = 0; hl < 4; hl++) {
                        float kv = kq[rp][hl];
                        aacc[rp][hl] = fmaf(ws, kv, aacc[rp][hl]);
                        if (s < 3) {
                            zn[rp][hl] = fmaf(cnext, kv, zb[rp][hl]);
                        } else {
                            zb[rp][hl] = fmaf(h6, aacc[rp][hl], zb[rp][hl]);
                            zn[rp][hl] = zb[rp][hl];
                        }
                    }
                {
                    const int hh_sel = (t4 & 1) * 2;
                    const int rp_sel = t4 >> 1;
                    unsigned short zh0, zl0, zh1, zl1;
                    bf_split(zn[rp_sel][hh_sel],     zh0, zl0);
                    bf_split(zn[rp_sel][hh_sel + 1], zh1, zl1);
                    const int kk0 = 4 * (g & 3) + hh_sel;
                    const int ln  = rsub * 4 + ((kk0 & 7) >> 1);
                    const int reg = rp_sel + 2 * (kk0 >> 3);
                    const int idx = (((g >> 2) * 4 + w) * 32 + ln) * 4 + reg;
                    __stcg(&((u32*)&g_zfh[pzn][chain][0])[idx], ((u32)zh1 << 16) | zh0);
                    __stcg(&((u32*)&g_zfl[pzn][chain][0])[idx], ((u32)zl1 << 16) | zl0);
                }
                warp_publish(&CZ[w], lane);
            }
        }

        // ---- interval end: heads (needs all 4 mt of this chain) ----
        warp_wait(&CZ[0], cz * 32u);
        warp_wait(&CZ[1], cz * 32u);
        warp_wait(&CZ[2], cz * 32u);
        warp_wait(&CZ[3], cz * 32u);
        {
            const int tid2 = tid & 127;
            const int r   = tid2 >> 1;
            const int sel = tid2 & 1;           // 0 = mean, 1 = std
            const int b   = rowBase + r;
            const float* wsel = sel ? ssW : smW;
            float acc0 = sel ? ssb[0] : smb_[0];
            float acc1 = sel ? ssb[1] : smb_[1];
            const u32* zfh = (const u32*)&g_zfh[cz & 1][chain][0];
            const u32* zfl = (const u32*)&g_zfl[cz & 1][chain][0];
            const int mt_r = r >> 4;
            const int rit  = r & 15;
            const int lnb  = (rit & 7) * 4;
            const int regb = rit >> 3;
#pragma unroll 4
            for (int hp = 0; hp < 64; hp++) {
                int h  = hp * 2;
                int kt = h >> 4, kk = h & 15;
                int idx = ((kt * 4 + mt_r) * 32 + lnb + ((kk & 7) >> 1)) * 4
                          + regb + 2 * (kk >> 3);
                u32 vh = __ldcg(zfh + idx);
                u32 vl = __ldcg(zfl + idx);
                float z0f = bf2f(vh & 0xffffu) + bf2f(vl & 0xffffu);
                float z1f = bf2f(vh >> 16) + bf2f(vl >> 16);
                acc0 = fmaf(z0f, wsel[h * 2 + 0], acc0);
                acc1 = fmaf(z0f, wsel[h * 2 + 1], acc1);
                acc0 = fmaf(z1f, wsel[(h + 1) * 2 + 0], acc0);
                acc1 = fmaf(z1f, wsel[(h + 1) * 2 + 1], acc1);
            }
            if (sel) { acc0 = softplus_f(acc0); acc1 = softplus_f(acc1); }
            float* dst = out + (sel ? (size_t)NBATCH * NIVL * NOUT : 0)
                         + ((size_t)b * NIVL + tau) * NOUT + g * 2;
            dst[0] = acc0;
            dst[1] = acc1;
        }
    }

    // ---- end-of-kernel reset for deterministic graph replay ----
    gbar_val(p, 1u);
    if (tid == 0 && g == 0) {
#pragma unroll
        for (int cc = 0; cc < 2; cc++)
#pragma unroll
            for (int q = 0; q < 4; q++) {
                g_czc[p * 2 + cc][q].v = 0u;
                g_c1c[p * 2 + cc][q].v = 0u;
                g_c2c[p * 2 + cc][q].v = 0u;
            }
    }
    gbar_val(p, 0u);
}

extern "C" void kernel_launch(void* const* d_in, const int* in_sizes, int n_in,
                              void* d_out, int out_size) {
    const float* t   = (const float*)d_in[0];
    const float* z0  = (const float*)d_in[1];
    const float* X   = (const float*)d_in[2];
    const float* W1  = (const float*)d_in[3];
    const float* b1  = (const float*)d_in[4];
    const float* W2  = (const float*)d_in[5];
    const float* b2  = (const float*)d_in[6];
    const float* W3  = (const float*)d_in[7];
    const float* b3  = (const float*)d_in[8];
    const float* mW  = (const float*)d_in[9];
    const float* mb  = (const float*)d_in[10];
    const float* sW  = (const float*)d_in[11];
    const float* sb  = (const float*)d_in[12];
    float* out = (float*)d_out;

    cudaFuncSetAttribute(cde_persistent,
                         cudaFuncAttributeMaxDynamicSharedMemorySize, SMEM_BYTES);
    cde_persistent<<<GRID_CTAS, TPB, SMEM_BYTES>>>(t, z0, X, W1, b1, W2, b2,
                                                   W3, b3, mW, mb, sW, sb, out);
}

// round 16
// speedup vs baseline: 2.2513x; 1.0248x over previous
#include <cuda_runtime.h>
#include <cuda_bf16.h>

typedef unsigned long long u64;
typedef unsigned int u32;

#define NBATCH 512
#define NTT    257
#define NIVL   256
#define NIN    32
#define NH     128
#define NBN    256
#define NOUT   64
#define GRID_CTAS 128
#define TPB    256
#define NGRP   32

// ---- shared memory byte offsets (shared by all 4 chains of a CTA) ----
#define SM_FRAGB 0          // W3 B-frags [16kt][16nt][32] uint4 = 128KB
#define SM_W1F   131072     // W1 B-frags [8kt][32] uint4 = 4KB
#define SM_W2F   135168     // W2 B-frags [16kt][32] uint4 = 8KB
#define SM_B3    143360     // [128] f32
#define SM_B1    143872     // [8]
#define SM_B2    143904     // [8]
#define SM_MW    143936     // [128][2]
#define SM_SW    144960     // [128][2]
#define SM_MB    145984     // [2]
#define SM_SB    145992     // [2]
#define SMEM_BYTES 146016

// ---- global frag exchanges: 16 chains of 32 rows, parity 2 ----
__device__ uint4 g_zfh[2][16][512];    // z  frags: 8kt x 2mt x 32
__device__ uint4 g_zfl[2][16][512];
__device__ uint4 g_f1h[2][16][1024];   // h1 frags: 16kt x 2mt x 32
__device__ uint4 g_f1l[2][16][1024];
__device__ uint4 g_fAh[2][16][1024];   // h2 frags
__device__ uint4 g_fAl[2][16][1024];

// ---- diagonal counters: [chain][mt], producers = warp (chain,mt) of 32 CTAs ----
struct PadCnt { unsigned v; unsigned pad[127]; };
__device__ PadCnt g_czc[16][2];
__device__ PadCnt g_c1c[16][2];
__device__ PadCnt g_c2c[16][2];

struct PadU { unsigned v; unsigned pad[31]; };
__device__ PadU g_cnt[4];
__device__ PadU g_rel[4];

// ---- helpers ----
__device__ __forceinline__ float fast_tanh(float x) {
    float e;
    asm("ex2.approx.f32 %0, %1;" : "=f"(e) : "f"(x * 2.8853900817779268f));
    float r;
    asm("rcp.approx.f32 %0, %1;" : "=f"(r) : "f"(e + 1.0f));
    return fmaf(-2.0f, r, 1.0f);
}
__device__ __forceinline__ float softplus_f(float x) {
    return fmaxf(x, 0.0f) + log1pf(expf(-fabsf(x)));
}
__device__ __forceinline__ void mma16816(float* c, uint4 a, u32 b0, u32 b1) {
    asm volatile(
        "mma.sync.aligned.m16n8k16.row.col.f32.bf16.bf16.f32 "
        "{%0,%1,%2,%3}, {%4,%5,%6,%7}, {%8,%9}, {%0,%1,%2,%3};"
        : "+f"(c[0]), "+f"(c[1]), "+f"(c[2]), "+f"(c[3])
        : "r"(a.x), "r"(a.y), "r"(a.z), "r"(a.w), "r"(b0), "r"(b1));
}
__device__ __forceinline__ void bf_split(float x, unsigned short& h, unsigned short& l) {
    __nv_bfloat16 bh = __float2bfloat16_rn(x);
    __nv_bfloat16 bl = __float2bfloat16_rn(x - __bfloat162float(bh));
    h = __bfloat16_as_ushort(bh);
    l = __bfloat16_as_ushort(bl);
}
__device__ __forceinline__ float bf2f(u32 bits16) {
    return __bfloat162float(__ushort_as_bfloat16((unsigned short)bits16));
}

// ---- warp-granularity publish / wait ----
__device__ __forceinline__ void warp_publish(PadCnt* c, int lane) {
    __syncwarp();
    if (lane == 0)
        asm volatile("red.release.gpu.global.add.u32 [%0], %1;"
                     :: "l"(&c->v), "r"(1u) : "memory");
}
__device__ __forceinline__ void warp_wait(PadCnt* c, unsigned target) {
    unsigned v;
    do {
        asm volatile("ld.acquire.gpu.u32 %0, [%1];"
                     : "=r"(v) : "l"(&c->v) : "memory");
    } while ((int)(v - target) < 0);
}
__device__ __forceinline__ void gbar_val(int grp, unsigned target) {
    __syncthreads();
    if (threadIdx.x == 0) {
        __threadfence();
        unsigned old = atomicAdd(&g_cnt[grp].v, 1u);
        if (old == (NGRP - 1u)) {
            g_cnt[grp].v = 0u;
            asm volatile("st.release.gpu.u32 [%0], %1;"
                         :: "l"(&g_rel[grp].v), "r"(target) : "memory");
        } else {
            unsigned v;
            do {
                asm volatile("ld.acquire.gpu.u32 %0, [%1];"
                             : "=r"(v) : "l"(&g_rel[grp].v) : "memory");
            } while (v != target);
        }
    }
    __syncthreads();
}

// ---- per-warp mma MLP stage: rows mt=w (16 of 32), out 8 cols (N-slice g) ----
// A-frag layout: [(kt*2 + mt)*32 + lane]
template <int NKT>
__device__ __forceinline__ void mlp_mma(const uint4* __restrict__ fAh,
                                        const uint4* __restrict__ fAl,
                                        const uint4* __restrict__ sBf,
                                        const float* __restrict__ sbias,
                                        u64* __restrict__ outHi,
                                        u64* __restrict__ outLo,
                                        int w, int lane, int g) {
    const int c0 = (lane & 3) * 2;
    float aP[4], aQ[4] = {0.f, 0.f, 0.f, 0.f}, aR[4] = {0.f, 0.f, 0.f, 0.f};
    aP[0] = sbias[c0];
    aP[1] = sbias[c0 + 1];
    aP[2] = sbias[c0];
    aP[3] = sbias[c0 + 1];

    uint4 rh[4], rl[4];
#pragma unroll
    for (int d = 0; d < 4; d++) {
        int dd = (d < NKT) ? d : (NKT - 1);
        rh[d] = __ldcg(fAh + (dd * 2 + w) * 32 + lane);
        rl[d] = __ldcg(fAl + (dd * 2 + w) * 32 + lane);
    }
#pragma unroll
    for (int kt = 0; kt < NKT; kt++) {
        uint4 ah = rh[kt & 3], al = rl[kt & 3];
        if (kt + 4 < NKT) {
            rh[kt & 3] = __ldcg(fAh + ((kt + 4) * 2 + w) * 32 + lane);
            rl[kt & 3] = __ldcg(fAl + ((kt + 4) * 2 + w) * 32 + lane);
        }
        uint4 b = sBf[kt * 32 + lane];
        mma16816(aP, ah, b.x, b.y);
        mma16816(aQ, ah, b.z, b.w);
        mma16816(aR, al, b.x, b.y);
    }
    float o0 = fmaxf((aP[0] + aQ[0]) + aR[0], 0.f);
    float o1 = fmaxf((aP[1] + aQ[1]) + aR[1], 0.f);
    float o2 = fmaxf((aP[2] + aQ[2]) + aR[2], 0.f);
    float o3 = fmaxf((aP[3] + aQ[3]) + aR[3], 0.f);

    unsigned short h0, h1, h2, h3, l0, l1, l2, l3;
    bf_split(o0, h0, l0); bf_split(o1, h1, l1);
    bf_split(o2, h2, l2); bf_split(o3, h3, l3);
    u32 hiA = ((u32)h1 << 16) | h0;
    u32 hiB = ((u32)h3 << 16) | h2;
    u32 loA = ((u32)l1 << 16) | l0;
    u32 loB = ((u32)l3 << 16) | l2;

    const int F = ((g >> 1) * 2 + w) * 32 + (lane >> 2) * 4 + (lane & 3);
    const int slot = F * 2 + (g & 1);
    __stcg(&outHi[slot], (u64)hiA | ((u64)hiB << 32));
    __stcg(&outLo[slot], (u64)loA | ((u64)loB << 32));
}

// ================= persistent kernel =================
__global__ void __launch_bounds__(TPB, 1)
cde_persistent(const float* __restrict__ t, const float* __restrict__ z0,
               const float* __restrict__ X,
               const float* __restrict__ W1, const float* __restrict__ b1,
               const float* __restrict__ W2, const float* __restrict__ b2,
               const float* __restrict__ W3, const float* __restrict__ b3,
               const float* __restrict__ mW, const float* __restrict__ mb,
               const float* __restrict__ sWp, const float* __restrict__ sbp,
               float* __restrict__ out) {
    extern __shared__ char smb[];
    uint4* sFragB = (uint4*)(smb + SM_FRAGB);
    uint4* sW1f  = (uint4*)(smb + SM_W1F);
    uint4* sW2f  = (uint4*)(smb + SM_W2F);
    float* sb3   = (float*)(smb + SM_B3);
    float* sb1   = (float*)(smb + SM_B1);
    float* sb2   = (float*)(smb + SM_B2);
    float* smW   = (float*)(smb + SM_MW);
    float* ssW   = (float*)(smb + SM_SW);
    float* smb_  = (float*)(smb + SM_MB);
    float* ssb   = (float*)(smb + SM_SB);

    const int tid  = threadIdx.x;
    const int wid  = tid >> 5;
    const int lane = tid & 31;
    const int p    = blockIdx.x >> 5;      // CTA pool 0..3
    const int g    = blockIdx.x & 31;      // column group 0..31
    const int chx  = wid >> 1;             // chain select within CTA 0..3
    const int w    = wid & 1;              // m-tile index within chain
    const int chain = p * 4 + chx;         // 0..15
    const int rowBase = chain * 32;

    PadCnt* CZ = &g_czc[chain][0];
    PadCnt* C1 = &g_c1c[chain][0];
    PadCnt* C2 = &g_c2c[chain][0];

    // ---- init: W3 slice -> B fragments ----
    for (int i = tid; i < 16 * 16 * 32; i += TPB) {
        int ln = i & 31, nt = (i >> 5) & 15, kt = i >> 9;
        int nl = nt * 8 + (ln >> 2);
        int k0 = kt * 16 + (ln & 3) * 2;
        const float* wp = W3 + (size_t)k0 * 4096 + g * 128 + nl;
        unsigned short h0, h1, h8, h9, l0, l1, l8, l9;
        bf_split(wp[0],        h0, l0);
        bf_split(wp[4096],     h1, l1);
        bf_split(wp[8 * 4096], h8, l8);
        bf_split(wp[9 * 4096], h9, l9);
        uint4 v;
        v.x = ((u32)h1 << 16) | h0;
        v.y = ((u32)h9 << 16) | h8;
        v.z = ((u32)l1 << 16) | l0;
        v.w = ((u32)l9 << 16) | l8;
        sFragB[i] = v;
    }
    for (int i = tid; i < 8 * 32; i += TPB) {
        int kt = i >> 5, ln = i & 31;
        int n  = g * 8 + (ln >> 2);
        int k0 = kt * 16 + (ln & 3) * 2;
        unsigned short h0, h1, h8, h9, l0, l1, l8, l9;
        bf_split(__ldg(&W1[(size_t)k0 * 256 + n]),       h0, l0);
        bf_split(__ldg(&W1[(size_t)(k0 + 1) * 256 + n]), h1, l1);
        bf_split(__ldg(&W1[(size_t)(k0 + 8) * 256 + n]), h8, l8);
        bf_split(__ldg(&W1[(size_t)(k0 + 9) * 256 + n]), h9, l9);
        uint4 v;
        v.x = ((u32)h1 << 16) | h0;
        v.y = ((u32)h9 << 16) | h8;
        v.z = ((u32)l1 << 16) | l0;
        v.w = ((u32)l9 << 16) | l8;
        sW1f[i] = v;
    }
    for (int i = tid; i < 16 * 32; i += TPB) {
        int kt = i >> 5, ln = i & 31;
        int n  = g * 8 + (ln >> 2);
        int k0 = kt * 16 + (ln & 3) * 2;
        unsigned short h0, h1, h8, h9, l0, l1, l8, l9;
        bf_split(__ldg(&W2[(size_t)k0 * 256 + n]),       h0, l0);
        bf_split(__ldg(&W2[(size_t)(k0 + 1) * 256 + n]), h1, l1);
        bf_split(__ldg(&W2[(size_t)(k0 + 8) * 256 + n]), h8, l8);
        bf_split(__ldg(&W2[(size_t)(k0 + 9) * 256 + n]), h9, l9);
        uint4 v;
        v.x = ((u32)h1 << 16) | h0;
        v.y = ((u32)h9 << 16) | h8;
        v.z = ((u32)l1 << 16) | l0;
        v.w = ((u32)l9 << 16) | l8;
        sW2f[i] = v;
    }
    for (int i = tid; i < 128; i += TPB) sb3[i] = __ldg(&b3[g * 128 + i]);
    if (tid < 8)  sb1[tid] = __ldg(&b1[g * 8 + tid]);
    if (tid >= 8 && tid < 16) sb2[tid - 8] = __ldg(&b2[g * 8 + tid - 8]);
    for (int i = tid; i < 256; i += TPB) {
        int h = i >> 1, c = i & 1;
        smW[i] = __ldg(&mW[(size_t)h * 64 + g * 2 + c]);
        ssW[i] = __ldg(&sWp[(size_t)h * 64 + g * 2 + c]);
    }
    if (tid < 2)  smb_[tid] = __ldg(&mb[g * 2 + tid]);
    if (tid >= 2 && tid < 4) ssb[tid - 2] = __ldg(&sbp[g * 2 + tid - 2]);

    // ---- warp-local RK state: rows w*16 + rsub (+8), h cols g*4..g*4+3 ----
    const int rsub = lane >> 2;
    const int t4   = lane & 3;

    float zb[2][4];   // [rp][hh]
#pragma unroll
    for (int rp = 0; rp < 2; rp++) {
        int row = rowBase + w * 16 + rsub + rp * 8;
        float4 z = __ldg((const float4*)&z0[(size_t)row * 128 + g * 4]);
        zb[rp][0] = z.x; zb[rp][1] = z.y; zb[rp][2] = z.z; zb[rp][3] = z.w;
    }

    // ---- bootstrap: z0 frags at parity 1 for all 4 chains of this pool ----
    for (int i = tid; i < 256; i += TPB) {
        int cs = i >> 6, j = i & 63;
        int r = j >> 1, ps = j & 1;
        int chainB = p * 4 + cs;
        int c0 = g * 4 + ps * 2;
        int rowG = chainB * 32 + r;
        float v0 = __ldg(&z0[(size_t)rowG * 128 + c0]);
        float v1 = __ldg(&z0[(size_t)rowG * 128 + c0 + 1]);
        unsigned short h0, l0, h1, l1;
        bf_split(v0, h0, l0);
        bf_split(v1, h1, l1);
        int kt = g >> 2, kk = c0 & 15;
        int mt = r >> 4, rit = r & 15;
        int ln = (rit & 7) * 4 + ((kk & 7) >> 1);
        int reg = (rit >> 3) + 2 * (kk >> 3);
        int idx = ((kt * 2 + mt) * 32 + ln) * 4 + reg;
        ((u32*)&g_zfh[1][chainB][0])[idx] = ((u32)h1 << 16) | h0;
        ((u32*)&g_zfl[1][chainB][0])[idx] = ((u32)l1 << 16) | l0;
    }
    __syncthreads();
    warp_publish(&CZ[w], lane);
    unsigned cz = 1, c1 = 0, c2 = 0;

#pragma unroll 1
    for (int tau = 0; tau < NIVL; tau++) {
        float t0v = __ldg(&t[tau]);
        float t1v = __ldg(&t[tau + 1]);
        float dti = t1v - t0v;
        float hstep = dti * 0.25f;
        float h6 = hstep / 6.0f;

        // dxdt into registers [rp][8]
        float dxm[2][8];
#pragma unroll
        for (int rp = 0; rp < 2; rp++) {
            int row = rowBase + w * 16 + rsub + rp * 8;
            const float* Xr = X + ((size_t)row * NTT + tau) * NIN;
#pragma unroll
            for (int blk = 0; blk < 4; blk++) {
                float2 x0 = __ldg((const float2*)(Xr + blk * 8 + t4 * 2));
                float2 x1 = __ldg((const float2*)(Xr + NIN + blk * 8 + t4 * 2));
                dxm[rp][blk * 2 + 0] = (x1.x - x0.x) / dti;
                dxm[rp][blk * 2 + 1] = (x1.y - x0.y) / dti;
            }
        }

#pragma unroll 1
        for (int sub = 0; sub < 4; sub++) {
            float aacc[2][4] = {};
#pragma unroll 1
            for (int s = 0; s < 4; s++) {
                warp_wait(&CZ[w], cz * 32u);
                const int pz = cz & 1;

                // ---- stage 1 ----
                ++c1; const int p1 = c1 & 1;
                mlp_mma<8>(&g_zfh[pz][chain][0], &g_zfl[pz][chain][0], sW1f, sb1,
                           (u64*)&g_f1h[p1][chain][0], (u64*)&g_f1l[p1][chain][0],
                           w, lane, g);
                warp_publish(&C1[w], lane);
                warp_wait(&C1[w], c1 * 32u);

                // ---- stage 2 ----
                ++c2; const int p2 = c2 & 1;
                mlp_mma<16>(&g_f1h[p1][chain][0], &g_f1l[p1][chain][0], sW2f, sb2,
                            (u64*)&g_fAh[p2][chain][0], (u64*)&g_fAl[p2][chain][0],
                            w, lane, g);
                warp_publish(&C2[w], lane);
                warp_wait(&C2[w], c2 * 32u);

                // ---- stage 3: 1 m-tile x 16 n-tiles per warp ----
                float acc[16][4];
#pragma unroll
                for (int nt = 0; nt < 16; nt++) {
                    float bx = sb3[nt * 8 + t4 * 2];
                    float by = sb3[nt * 8 + t4 * 2 + 1];
                    acc[nt][0] = bx; acc[nt][1] = by;
                    acc[nt][2] = bx; acc[nt][3] = by;
                }
                const uint4* fAh = &g_fAh[p2][chain][0];
                const uint4* fAl = &g_fAl[p2][chain][0];
                uint4 ah = __ldcg(fAh + w * 32 + lane);
                uint4 al = __ldcg(fAl + w * 32 + lane);
#pragma unroll 1
                for (int kt = 0; kt < 16; kt++) {
                    uint4 nhf, nlf;
                    if (kt < 15) {
                        nhf = __ldcg(fAh + ((kt + 1) * 2 + w) * 32 + lane);
                        nlf = __ldcg(fAl + ((kt + 1) * 2 + w) * 32 + lane);
                    }
                    const uint4* bfr = sFragB + (kt * 16) * 32 + lane;
#pragma unroll
                    for (int nt = 0; nt < 16; nt++) {
                        uint4 b = bfr[nt * 32];
                        mma16816(acc[nt], ah, b.x, b.y);
                        mma16816(acc[nt], ah, b.z, b.w);
                        mma16816(acc[nt], al, b.x, b.y);
                    }
                    ah = nhf; al = nlf;
                }

                // ---- epilogue: tanh + dxdt, butterfly over t4 ----
                float kq[2][4] = {};
#pragma unroll
                for (int nt = 0; nt < 16; nt++) {
                    int hl = nt >> 2, iblk = nt & 3;
                    float y;
                    y = fast_tanh(acc[nt][0]);
                    kq[0][hl] = fmaf(y, dxm[0][iblk * 2],     kq[0][hl]);
                    y = fast_tanh(acc[nt][1]);
                    kq[0][hl] = fmaf(y, dxm[0][iblk * 2 + 1], kq[0][hl]);
                    y = fast_tanh(acc[nt][2]);
                    kq[1][hl] = fmaf(y, dxm[1][iblk * 2],     kq[1][hl]);
                    y = fast_tanh(acc[nt][3]);
                    kq[1][hl] = fmaf(y, dxm[1][iblk * 2 + 1], kq[1][hl]);
                }
#pragma unroll
                for (int rp = 0; rp < 2; rp++)
#pragma unroll
                    for (int hl = 0; hl < 4; hl++) {
                        float v = kq[rp][hl];
                        v += __shfl_xor_sync(0xffffffffu, v, 1);
                        v += __shfl_xor_sync(0xffffffffu, v, 2);
                        kq[rp][hl] = v;
                    }

                // ---- RK update + publish z-frags ----
                const float ws = (s == 0 || s == 3) ? 1.f : 2.f;
                const float cnext = (s == 2) ? hstep : 0.5f * hstep;
                ++cz; const int pzn = cz & 1;
                float zn[2][4];
#pragma unroll
                for (int rp = 0; rp < 2; rp++)
#pragma unroll
                    for (int hl = 0; hl < 4; hl++) {
                        float kv = kq[rp][hl];
                        aacc[rp][hl] = fmaf(ws, kv, aacc[rp][hl]);
                        if (s < 3) {
                            zn[rp][hl] = fmaf(cnext, kv, zb[rp][hl]);
                        } else {
                            zb[rp][hl] = fmaf(h6, aacc[rp][hl], zb[rp][hl]);
                            zn[rp][hl] = zb[rp][hl];
                        }
                    }
                {
                    const int hh_sel = (t4 & 1) * 2;
                    const int rp_sel = t4 >> 1;
                    unsigned short zh0, zl0, zh1, zl1;
                    bf_split(zn[rp_sel][hh_sel],     zh0, zl0);
                    bf_split(zn[rp_sel][hh_sel + 1], zh1, zl1);
                    const int kk0 = 4 * (g & 3) + hh_sel;
                    const int ln  = rsub * 4 + ((kk0 & 7) >> 1);
                    const int reg = rp_sel + 2 * (kk0 >> 3);
                    const int idx = (((g >> 2) * 2 + w) * 32 + ln) * 4 + reg;
                    __stcg(&((u32*)&g_zfh[pzn][chain][0])[idx], ((u32)zh1 << 16) | zh0);
                    __stcg(&((u32*)&g_zfl[pzn][chain][0])[idx], ((u32)zl1 << 16) | zl0);
                }
                warp_publish(&CZ[w], lane);
            }
        }

        // ---- interval end: heads (needs both mt of this chain) ----
        warp_wait(&CZ[0], cz * 32u);
        warp_wait(&CZ[1], cz * 32u);
        {
            const int j   = tid & 63;
            const int r   = j >> 1;
            const int sel = j & 1;            // 0 = mean, 1 = std
            const int b   = rowBase + r;
            const float* wsel = sel ? ssW : smW;
            float acc0 = sel ? ssb[0] : smb_[0];
            float acc1 = sel ? ssb[1] : smb_[1];
            const u32* zfh = (const u32*)&g_zfh[cz & 1][chain][0];
            const u32* zfl = (const u32*)&g_zfl[cz & 1][chain][0];
            const int mt_r = r >> 4;
            const int rit  = r & 15;
            const int lnb  = (rit & 7) * 4;
            const int regb = rit >> 3;
#pragma unroll 4
            for (int hp = 0; hp < 64; hp++) {
                int h  = hp * 2;
                int kt = h >> 4, kk = h & 15;
                int idx = ((kt * 2 + mt_r) * 32 + lnb + ((kk & 7) >> 1)) * 4
                          + regb + 2 * (kk >> 3);
                u32 vh = __ldcg(zfh + idx);
                u32 vl = __ldcg(zfl + idx);
                float z0f = bf2f(vh & 0xffffu) + bf2f(vl & 0xffffu);
                float z1f = bf2f(vh >> 16) + bf2f(vl >> 16);
                acc0 = fmaf(z0f, wsel[h * 2 + 0], acc0);
                acc1 = fmaf(z0f, wsel[h * 2 + 1], acc1);
                acc0 = fmaf(z1f, wsel[(h + 1) * 2 + 0], acc0);
                acc1 = fmaf(z1f, wsel[(h + 1) * 2 + 1], acc1);
            }
            if (sel) { acc0 = softplus_f(acc0); acc1 = softplus_f(acc1); }
            float* dst = out + (sel ? (size_t)NBATCH * NIVL * NOUT : 0)
                         + ((size_t)b * NIVL + tau) * NOUT + g * 2;
            dst[0] = acc0;
            dst[1] = acc1;
        }
    }

    // ---- end-of-kernel reset for deterministic graph replay ----
    gbar_val(p, 1u);
    if (tid == 0 && g == 0) {
#pragma unroll
        for (int cc = 0; cc < 4; cc++) {
            int ch = p * 4 + cc;
#pragma unroll
            for (int q = 0; q < 2; q++) {
                g_czc[ch][q].v = 0u;
                g_c1c[ch][q].v = 0u;
                g_c2c[ch][q].v = 0u;
            }
        }
    }
    gbar_val(p, 0u);
}

extern "C" void kernel_launch(void* const* d_in, const int* in_sizes, int n_in,
                              void* d_out, int out_size) {
    const float* t   = (const float*)d_in[0];
    const float* z0  = (const float*)d_in[1];
    const float* X   = (const float*)d_in[2];
    const float* W1  = (const float*)d_in[3];
    const float* b1  = (const float*)d_in[4];
    const float* W2  = (const float*)d_in[5];
    const float* b2  = (const float*)d_in[6];
    const float* W3  = (const float*)d_in[7];
    const float* b3  = (const float*)d_in[8];
    const float* mW  = (const float*)d_in[9];
    const float* mb  = (const float*)d_in[10];
    const float* sW  = (const float*)d_in[11];
    const float* sb  = (const float*)d_in[12];
    float* out = (float*)d_out;

    cudaFuncSetAttribute(cde_persistent,
                         cudaFuncAttributeMaxDynamicSharedMemorySize, SMEM_BYTES);
    cde_persistent<<<GRID_CTAS, TPB, SMEM_BYTES>>>(t, z0, X, W1, b1, W2, b2,
                                                   W3, b3, mW, mb, sW, sb, out);
}

// round 17
// speedup vs baseline: 2.2952x; 1.0195x over previous
#include <cuda_runtime.h>
#include <cuda_bf16.h>

typedef unsigned long long u64;
typedef unsigned int u32;

#define NBATCH 512
#define NTT    257
#define NIVL   256
#define NIN    32
#define NH     128
#define NBN    256
#define NOUT   64
#define GRID_CTAS 128
#define TPB    256
#define NGRP   32

// ---- shared memory byte offsets (shared by all 4 chains of a CTA) ----
#define SM_FRAGB 0          // W3 B-frags [16kt][16nt][32] uint4 = 128KB
#define SM_W1F   131072     // W1 B-frags [8kt][32] uint4 = 4KB
#define SM_W2F   135168     // W2 B-frags [16kt][32] uint4 = 8KB
#define SM_B3    143360     // [128] f32
#define SM_B1    143872     // [8]
#define SM_B2    143904     // [8]
#define SM_MW    143936     // [128][2]
#define SM_SW    144960     // [128][2]
#define SM_MB    145984     // [2]
#define SM_SB    145992     // [2]
#define SMEM_BYTES 146016

// ---- global frag exchanges: 16 chains of 32 rows, parity 2 ----
__device__ uint4 g_zfh[2][16][512];    // z  frags: 8kt x 2mt x 32
__device__ uint4 g_zfl[2][16][512];
__device__ uint4 g_f1h[2][16][1024];   // h1 frags: 16kt x 2mt x 32
__device__ uint4 g_f1l[2][16][1024];
__device__ uint4 g_fAh[2][16][1024];   // h2 frags
__device__ uint4 g_fAl[2][16][1024];

// ---- diagonal counters: [chain][mt] ----
struct PadCnt { unsigned v; unsigned pad[127]; };
__device__ PadCnt g_czc[16][2];
__device__ PadCnt g_c1c[16][2];
__device__ PadCnt g_c2c[16][2];

struct PadU { unsigned v; unsigned pad[31]; };
__device__ PadU g_cnt[4];
__device__ PadU g_rel[4];

// ---- helpers ----
__device__ __forceinline__ float fast_tanh(float x) {
    float e;
    asm("ex2.approx.f32 %0, %1;" : "=f"(e) : "f"(x * 2.8853900817779268f));
    float r;
    asm("rcp.approx.f32 %0, %1;" : "=f"(r) : "f"(e + 1.0f));
    return fmaf(-2.0f, r, 1.0f);
}
__device__ __forceinline__ float softplus_f(float x) {
    return fmaxf(x, 0.0f) + log1pf(expf(-fabsf(x)));
}
__device__ __forceinline__ void mma16816(float* c, uint4 a, u32 b0, u32 b1) {
    asm volatile(
        "mma.sync.aligned.m16n8k16.row.col.f32.bf16.bf16.f32 "
        "{%0,%1,%2,%3}, {%4,%5,%6,%7}, {%8,%9}, {%0,%1,%2,%3};"
        : "+f"(c[0]), "+f"(c[1]), "+f"(c[2]), "+f"(c[3])
        : "r"(a.x), "r"(a.y), "r"(a.z), "r"(a.w), "r"(b0), "r"(b1));
}
__device__ __forceinline__ void bf_split(float x, unsigned short& h, unsigned short& l) {
    __nv_bfloat16 bh = __float2bfloat16_rn(x);
    __nv_bfloat16 bl = __float2bfloat16_rn(x - __bfloat162float(bh));
    h = __bfloat16_as_ushort(bh);
    l = __bfloat16_as_ushort(bl);
}
__device__ __forceinline__ float bf2f(u32 bits16) {
    return __bfloat162float(__ushort_as_bfloat16((unsigned short)bits16));
}

// ---- warp-granularity publish / wait ----
__device__ __forceinline__ void warp_publish(PadCnt* c, int lane) {
    __syncwarp();
    if (lane == 0)
        asm volatile("red.release.gpu.global.add.u32 [%0], %1;"
                     :: "l"(&c->v), "r"(1u) : "memory");
}
__device__ __forceinline__ void warp_wait(PadCnt* c, unsigned target) {
    unsigned v;
    do {
        asm volatile("ld.acquire.gpu.u32 %0, [%1];"
                     : "=r"(v) : "l"(&c->v) : "memory");
    } while ((int)(v - target) < 0);
}
__device__ __forceinline__ void gbar_val(int grp, unsigned target) {
    __syncthreads();
    if (threadIdx.x == 0) {
        __threadfence();
        unsigned old = atomicAdd(&g_cnt[grp].v, 1u);
        if (old == (NGRP - 1u)) {
            g_cnt[grp].v = 0u;
            asm volatile("st.release.gpu.u32 [%0], %1;"
                         :: "l"(&g_rel[grp].v), "r"(target) : "memory");
        } else {
            unsigned v;
            do {
                asm volatile("ld.acquire.gpu.u32 %0, [%1];"
                             : "=r"(v) : "l"(&g_rel[grp].v) : "memory");
            } while (v != target);
        }
    }
    __syncthreads();
}

// ---- per-warp mma MLP stage: rows mt=w (16 of 32), out 8 cols (N-slice g) ----
template <int NKT>
__device__ __forceinline__ void mlp_mma(const uint4* __restrict__ fAh,
                                        const uint4* __restrict__ fAl,
                                        const uint4* __restrict__ sBf,
                                        const float* __restrict__ sbias,
                                        u64* __restrict__ outHi,
                                        u64* __restrict__ outLo,
                                        int w, int lane, int g) {
    const int c0 = (lane & 3) * 2;
    float aP[4], aQ[4] = {0.f, 0.f, 0.f, 0.f}, aR[4] = {0.f, 0.f, 0.f, 0.f};
    aP[0] = sbias[c0];
    aP[1] = sbias[c0 + 1];
    aP[2] = sbias[c0];
    aP[3] = sbias[c0 + 1];

    uint4 rh[4], rl[4];
#pragma unroll
    for (int d = 0; d < 4; d++) {
        int dd = (d < NKT) ? d : (NKT - 1);
        rh[d] = __ldcg(fAh + (dd * 2 + w) * 32 + lane);
        rl[d] = __ldcg(fAl + (dd * 2 + w) * 32 + lane);
    }
#pragma unroll
    for (int kt = 0; kt < NKT; kt++) {
        uint4 ah = rh[kt & 3], al = rl[kt & 3];
        if (kt + 4 < NKT) {
            rh[kt & 3] = __ldcg(fAh + ((kt + 4) * 2 + w) * 32 + lane);
            rl[kt & 3] = __ldcg(fAl + ((kt + 4) * 2 + w) * 32 + lane);
        }
        uint4 b = sBf[kt * 32 + lane];
        mma16816(aP, ah, b.x, b.y);
        mma16816(aQ, ah, b.z, b.w);
        mma16816(aR, al, b.x, b.y);
    }
    float o0 = fmaxf((aP[0] + aQ[0]) + aR[0], 0.f);
    float o1 = fmaxf((aP[1] + aQ[1]) + aR[1], 0.f);
    float o2 = fmaxf((aP[2] + aQ[2]) + aR[2], 0.f);
    float o3 = fmaxf((aP[3] + aQ[3]) + aR[3], 0.f);

    unsigned short h0, h1, h2, h3, l0, l1, l2, l3;
    bf_split(o0, h0, l0); bf_split(o1, h1, l1);
    bf_split(o2, h2, l2); bf_split(o3, h3, l3);
    u32 hiA = ((u32)h1 << 16) | h0;
    u32 hiB = ((u32)h3 << 16) | h2;
    u32 loA = ((u32)l1 << 16) | l0;
    u32 loB = ((u32)l3 << 16) | l2;

    const int F = ((g >> 1) * 2 + w) * 32 + (lane >> 2) * 4 + (lane & 3);
    const int slot = F * 2 + (g & 1);
    __stcg(&outHi[slot], (u64)hiA | ((u64)hiB << 32));
    __stcg(&outLo[slot], (u64)loA | ((u64)loB << 32));
}

// ================= persistent kernel =================
__global__ void __launch_bounds__(TPB, 1)
cde_persistent(const float* __restrict__ t, const float* __restrict__ z0,
               const float* __restrict__ X,
               const float* __restrict__ W1, const float* __restrict__ b1,
               const float* __restrict__ W2, const float* __restrict__ b2,
               const float* __restrict__ W3, const float* __restrict__ b3,
               const float* __restrict__ mW, const float* __restrict__ mb,
               const float* __restrict__ sWp, const float* __restrict__ sbp,
               float* __restrict__ out) {
    extern __shared__ char smb[];
    uint4* sFragB = (uint4*)(smb + SM_FRAGB);
    uint4* sW1f  = (uint4*)(smb + SM_W1F);
    uint4* sW2f  = (uint4*)(smb + SM_W2F);
    float* sb3   = (float*)(smb + SM_B3);
    float* sb1   = (float*)(smb + SM_B1);
    float* sb2   = (float*)(smb + SM_B2);
    float* smW   = (float*)(smb + SM_MW);
    float* ssW   = (float*)(smb + SM_SW);
    float* smb_  = (float*)(smb + SM_MB);
    float* ssb   = (float*)(smb + SM_SB);

    const int tid  = threadIdx.x;
    const int wid  = tid >> 5;
    const int lane = tid & 31;
    const int p    = blockIdx.x >> 5;      // CTA pool 0..3
    const int g    = blockIdx.x & 31;      // column group 0..31
    const int chx  = wid >> 1;             // chain select within CTA 0..3
    const int w    = wid & 1;              // m-tile index within chain
    const int chain = p * 4 + chx;         // 0..15
    const int rowBase = chain * 32;

    PadCnt* CZ = &g_czc[chain][0];
    PadCnt* C1 = &g_c1c[chain][0];
    PadCnt* C2 = &g_c2c[chain][0];

    // ---- init: W3 slice -> B fragments ----
    for (int i = tid; i < 16 * 16 * 32; i += TPB) {
        int ln = i & 31, nt = (i >> 5) & 15, kt = i >> 9;
        int nl = nt * 8 + (ln >> 2);
        int k0 = kt * 16 + (ln & 3) * 2;
        const float* wp = W3 + (size_t)k0 * 4096 + g * 128 + nl;
        unsigned short h0, h1, h8, h9, l0, l1, l8, l9;
        bf_split(wp[0],        h0, l0);
        bf_split(wp[4096],     h1, l1);
        bf_split(wp[8 * 4096], h8, l8);
        bf_split(wp[9 * 4096], h9, l9);
        uint4 v;
        v.x = ((u32)h1 << 16) | h0;
        v.y = ((u32)h9 << 16) | h8;
        v.z = ((u32)l1 << 16) | l0;
        v.w = ((u32)l9 << 16) | l8;
        sFragB[i] = v;
    }
    for (int i = tid; i < 8 * 32; i += TPB) {
        int kt = i >> 5, ln = i & 31;
        int n  = g * 8 + (ln >> 2);
        int k0 = kt * 16 + (ln & 3) * 2;
        unsigned short h0, h1, h8, h9, l0, l1, l8, l9;
        bf_split(__ldg(&W1[(size_t)k0 * 256 + n]),       h0, l0);
        bf_split(__ldg(&W1[(size_t)(k0 + 1) * 256 + n]), h1, l1);
        bf_split(__ldg(&W1[(size_t)(k0 + 8) * 256 + n]), h8, l8);
        bf_split(__ldg(&W1[(size_t)(k0 + 9) * 256 + n]), h9, l9);
        uint4 v;
        v.x = ((u32)h1 << 16) | h0;
        v.y = ((u32)h9 << 16) | h8;
        v.z = ((u32)l1 << 16) | l0;
        v.w = ((u32)l9 << 16) | l8;
        sW1f[i] = v;
    }
    for (int i = tid; i < 16 * 32; i += TPB) {
        int kt = i >> 5, ln = i & 31;
        int n  = g * 8 + (ln >> 2);
        int k0 = kt * 16 + (ln & 3) * 2;
        unsigned short h0, h1, h8, h9, l0, l1, l8, l9;
        bf_split(__ldg(&W2[(size_t)k0 * 256 + n]),       h0, l0);
        bf_split(__ldg(&W2[(size_t)(k0 + 1) * 256 + n]), h1, l1);
        bf_split(__ldg(&W2[(size_t)(k0 + 8) * 256 + n]), h8, l8);
        bf_split(__ldg(&W2[(size_t)(k0 + 9) * 256 + n]), h9, l9);
        uint4 v;
        v.x = ((u32)h1 << 16) | h0;
        v.y = ((u32)h9 << 16) | h8;
        v.z = ((u32)l1 << 16) | l0;
        v.w = ((u32)l9 << 16) | l8;
        sW2f[i] = v;
    }
    for (int i = tid; i < 128; i += TPB) sb3[i] = __ldg(&b3[g * 128 + i]);
    if (tid < 8)  sb1[tid] = __ldg(&b1[g * 8 + tid]);
    if (tid >= 8 && tid < 16) sb2[tid - 8] = __ldg(&b2[g * 8 + tid - 8]);
    for (int i = tid; i < 256; i += TPB) {
        int h = i >> 1, c = i & 1;
        smW[i] = __ldg(&mW[(size_t)h * 64 + g * 2 + c]);
        ssW[i] = __ldg(&sWp[(size_t)h * 64 + g * 2 + c]);
    }
    if (tid < 2)  smb_[tid] = __ldg(&mb[g * 2 + tid]);
    if (tid >= 2 && tid < 4) ssb[tid - 2] = __ldg(&sbp[g * 2 + tid - 2]);

    // ---- warp-local RK state: rows w*16 + rsub (+8), h cols g*4..g*4+3 ----
    const int rsub = lane >> 2;
    const int t4   = lane & 3;

    float zb[2][4];   // [rp][hh]
#pragma unroll
    for (int rp = 0; rp < 2; rp++) {
        int row = rowBase + w * 16 + rsub + rp * 8;
        float4 z = __ldg((const float4*)&z0[(size_t)row * 128 + g * 4]);
        zb[rp][0] = z.x; zb[rp][1] = z.y; zb[rp][2] = z.z; zb[rp][3] = z.w;
    }

    // ---- bootstrap: z0 frags at parity 1 for all 4 chains of this pool ----
    for (int i = tid; i < 256; i += TPB) {
        int cs = i >> 6, j = i & 63;
        int r = j >> 1, ps = j & 1;
        int chainB = p * 4 + cs;
        int c0 = g * 4 + ps * 2;
        int rowG = chainB * 32 + r;
        float v0 = __ldg(&z0[(size_t)rowG * 128 + c0]);
        float v1 = __ldg(&z0[(size_t)rowG * 128 + c0 + 1]);
        unsigned short h0, l0, h1, l1;
        bf_split(v0, h0, l0);
        bf_split(v1, h1, l1);
        int kt = g >> 2, kk = c0 & 15;
        int mt = r >> 4, rit = r & 15;
        int ln = (rit & 7) * 4 + ((kk & 7) >> 1);
        int reg = (rit >> 3) + 2 * (kk >> 3);
        int idx = ((kt * 2 + mt) * 32 + ln) * 4 + reg;
        ((u32*)&g_zfh[1][chainB][0])[idx] = ((u32)h1 << 16) | h0;
        ((u32*)&g_zfl[1][chainB][0])[idx] = ((u32)l1 << 16) | l0;
    }
    __syncthreads();

    // ---- phase stagger: second chain-set (wid>=4 -> chains 2,3 of each pool)
    // delayed ~half an eval period so the two chains sharing each SMSP run in
    // anti-phase: one computes while the other waits. Offset persists because
    // chains are fully independent and have identical per-eval work.
    if (wid >= 4) {
        long long st = clock64();
        while (clock64() - st < 12000) { }
    }
    warp_publish(&CZ[w], lane);
    unsigned cz = 1, c1 = 0, c2 = 0;

#pragma unroll 1
    for (int tau = 0; tau < NIVL; tau++) {
        float t0v = __ldg(&t[tau]);
        float t1v = __ldg(&t[tau + 1]);
        float dti = t1v - t0v;
        float hstep = dti * 0.25f;
        float h6 = hstep / 6.0f;

        // dxdt into registers [rp][8]
        float dxm[2][8];
#pragma unroll
        for (int rp = 0; rp < 2; rp++) {
            int row = rowBase + w * 16 + rsub + rp * 8;
            const float* Xr = X + ((size_t)row * NTT + tau) * NIN;
#pragma unroll
            for (int blk = 0; blk < 4; blk++) {
                float2 x0 = __ldg((const float2*)(Xr + blk * 8 + t4 * 2));
                float2 x1 = __ldg((const float2*)(Xr + NIN + blk * 8 + t4 * 2));
                dxm[rp][blk * 2 + 0] = (x1.x - x0.x) / dti;
                dxm[rp][blk * 2 + 1] = (x1.y - x0.y) / dti;
            }
        }

#pragma unroll 1
        for (int sub = 0; sub < 4; sub++) {
            float aacc[2][4] = {};
#pragma unroll 1
            for (int s = 0; s < 4; s++) {
                warp_wait(&CZ[w], cz * 32u);
                const int pz = cz & 1;

                // ---- stage 1 ----
                ++c1; const int p1 = c1 & 1;
                mlp_mma<8>(&g_zfh[pz][chain][0], &g_zfl[pz][chain][0], sW1f, sb1,
                           (u64*)&g_f1h[p1][chain][0], (u64*)&g_f1l[p1][chain][0],
                           w, lane, g);
                warp_publish(&C1[w], lane);
                warp_wait(&C1[w], c1 * 32u);

                // ---- stage 2 ----
                ++c2; const int p2 = c2 & 1;
                mlp_mma<16>(&g_f1h[p1][chain][0], &g_f1l[p1][chain][0], sW2f, sb2,
                            (u64*)&g_fAh[p2][chain][0], (u64*)&g_fAl[p2][chain][0],
                            w, lane, g);
                warp_publish(&C2[w], lane);
                warp_wait(&C2[w], c2 * 32u);

                // ---- stage 3: 1 m-tile x 16 n-tiles per warp ----
                float acc[16][4];
#pragma unroll
                for (int nt = 0; nt < 16; nt++) {
                    float bx = sb3[nt * 8 + t4 * 2];
                    float by = sb3[nt * 8 + t4 * 2 + 1];
                    acc[nt][0] = bx; acc[nt][1] = by;
                    acc[nt][2] = bx; acc[nt][3] = by;
                }
                const uint4* fAh = &g_fAh[p2][chain][0];
                const uint4* fAl = &g_fAl[p2][chain][0];
                uint4 ah = __ldcg(fAh + w * 32 + lane);
                uint4 al = __ldcg(fAl + w * 32 + lane);
#pragma unroll 1
                for (int kt = 0; kt < 16; kt++) {
                    uint4 nhf, nlf;
                    if (kt < 15) {
                        nhf = __ldcg(fAh + ((kt + 1) * 2 + w) * 32 + lane);
                        nlf = __ldcg(fAl + ((kt + 1) * 2 + w) * 32 + lane);
                    }
                    const uint4* bfr = sFragB + (kt * 16) * 32 + lane;
#pragma unroll
                    for (int nt = 0; nt < 16; nt++) {
                        uint4 b = bfr[nt * 32];
                        mma16816(acc[nt], ah, b.x, b.y);
                        mma16816(acc[nt], ah, b.z, b.w);
                        mma16816(acc[nt], al, b.x, b.y);
                    }
                    ah = nhf; al = nlf;
                }

                // ---- epilogue: tanh + dxdt, butterfly over t4 ----
                float kq[2][4] = {};
#pragma unroll
                for (int nt = 0; nt < 16; nt++) {
                    int hl = nt >> 2, iblk = nt & 3;
                    float y;
                    y = fast_tanh(acc[nt][0]);
                    kq[0][hl] = fmaf(y, dxm[0][iblk * 2],     kq[0][hl]);
                    y = fast_tanh(acc[nt][1]);
                    kq[0][hl] = fmaf(y, dxm[0][iblk * 2 + 1], kq[0][hl]);
                    y = fast_tanh(acc[nt][2]);
                    kq[1][hl] = fmaf(y, dxm[1][iblk * 2],     kq[1][hl]);
                    y = fast_tanh(acc[nt][3]);
                    kq[1][hl] = fmaf(y, dxm[1][iblk * 2 + 1], kq[1][hl]);
                }
#pragma unroll
                for (int rp = 0; rp < 2; rp++)
#pragma unroll
                    for (int hl = 0; hl < 4; hl++) {
                        float v = kq[rp][hl];
                        v += __shfl_xor_sync(0xffffffffu, v, 1);
                        v += __shfl_xor_sync(0xffffffffu, v, 2);
                        kq[rp][hl] = v;
                    }

                // ---- RK update + publish z-frags ----
                const float ws = (s == 0 || s == 3) ? 1.f : 2.f;
                const float cnext = (s == 2) ? hstep : 0.5f * hstep;
                ++cz; const int pzn = cz & 1;
                float zn[2][4];
#pragma unroll
                for (int rp = 0; rp < 2; rp++)
#pragma unroll
                    for (int hl = 0; hl < 4; hl++) {
                        float kv = kq[rp][hl];
                        aacc[rp][hl] = fmaf(ws, kv, aacc[rp][hl]);
                        if (s < 3) {
                            zn[rp][hl] = fmaf(cnext, kv, zb[rp][hl]);
                        } else {
                            zb[rp][hl] = fmaf(h6, aacc[rp][hl], zb[rp][hl]);
                            zn[rp][hl] = zb[rp][hl];
                        }
                    }
                {
                    const int hh_sel = (t4 & 1) * 2;
                    const int rp_sel = t4 >> 1;
                    unsigned short zh0, zl0, zh1, zl1;
                    bf_split(zn[rp_sel][hh_sel],     zh0, zl0);
                    bf_split(zn[rp_sel][hh_sel + 1], zh1, zl1);
                    const int kk0 = 4 * (g & 3) + hh_sel;
                    const int ln  = rsub * 4 + ((kk0 & 7) >> 1);
                    const int reg = rp_sel + 2 * (kk0 >> 3);
                    const int idx = (((g >> 2) * 2 + w) * 32 + ln) * 4 + reg;
                    __stcg(&((u32*)&g_zfh[pzn][chain][0])[idx], ((u32)zh1 << 16) | zh0);
                    __stcg(&((u32*)&g_zfl[pzn][chain][0])[idx], ((u32)zl1 << 16) | zl0);
                }
                warp_publish(&CZ[w], lane);
            }
        }

        // ---- interval end: heads (needs both mt of this chain) ----
        warp_wait(&CZ[0], cz * 32u);
        warp_wait(&CZ[1], cz * 32u);
        {
            const int j   = tid & 63;
            const int r   = j >> 1;
            const int sel = j & 1;            // 0 = mean, 1 = std
            const int b   = rowBase + r;
            const float* wsel = sel ? ssW : smW;
            float acc0 = sel ? ssb[0] : smb_[0];
            float acc1 = sel ? ssb[1] : smb_[1];
            const u32* zfh = (const u32*)&g_zfh[cz & 1][chain][0];
            const u32* zfl = (const u32*)&g_zfl[cz & 1][chain][0];
            const int mt_r = r >> 4;
            const int rit  = r & 15;
            const int lnb  = (rit & 7) * 4;
            const int regb = rit >> 3;
#pragma unroll 4
            for (int hp = 0; hp < 64; hp++) {
                int h  = hp * 2;
                int kt = h >> 4, kk = h & 15;
                int idx = ((kt * 2 + mt_r) * 32 + lnb + ((kk & 7) >> 1)) * 4
                          + regb + 2 * (kk >> 3);
                u32 vh = __ldcg(zfh + idx);
                u32 vl = __ldcg(zfl + idx);
                float z0f = bf2f(vh & 0xffffu) + bf2f(vl & 0xffffu);
                float z1f = bf2f(vh >> 16) + bf2f(vl >> 16);
                acc0 = fmaf(z0f, wsel[h * 2 + 0], acc0);
                acc1 = fmaf(z0f, wsel[h * 2 + 1], acc1);
                acc0 = fmaf(z1f, wsel[(h + 1) * 2 + 0], acc0);
                acc1 = fmaf(z1f, wsel[(h + 1) * 2 + 1], acc1);
            }
            if (sel) { acc0 = softplus_f(acc0); acc1 = softplus_f(acc1); }
            float* dst = out + (sel ? (size_t)NBATCH * NIVL * NOUT : 0)
                         + ((size_t)b * NIVL + tau) * NOUT + g * 2;
            dst[0] = acc0;
            dst[1] = acc1;
        }
    }

    // ---- end-of-kernel reset for deterministic graph replay ----
    gbar_val(p, 1u);
    if (tid == 0 && g == 0) {
#pragma unroll
        for (int cc = 0; cc < 4; cc++) {
            int ch = p * 4 + cc;
#pragma unroll
            for (int q = 0; q < 2; q++) {
                g_czc[ch][q].v = 0u;
                g_c1c[ch][q].v = 0u;
                g_c2c[ch][q].v = 0u;
            }
        }
    }
    gbar_val(p, 0u);
}

extern "C" void kernel_launch(void* const* d_in, const int* in_sizes, int n_in,
                              void* d_out, int out_size) {
    const float* t   = (const float*)d_in[0];
    const float* z0  = (const float*)d_in[1];
    const float* X   = (const float*)d_in[2];
    const float* W1  = (const float*)d_in[3];
    const float* b1  = (const float*)d_in[4];
    const float* W2  = (const float*)d_in[5];
    const float* b2  = (const float*)d_in[6];
    const float* W3  = (const float*)d_in[7];
    const float* b3  = (const float*)d_in[8];
    const float* mW  = (const float*)d_in[9];
    const float* mb  = (const float*)d_in[10];
    const float* sW  = (const float*)d_in[11];
    const float* sb  = (const float*)d_in[12];
    float* out = (float*)d_out;

    cudaFuncSetAttribute(cde_persistent,
                         cudaFuncAttributeMaxDynamicSharedMemorySize, SMEM_BYTES);
    cde_persistent<<<GRID_CTAS, TPB, SMEM_BYTES>>>(t, z0, X, W1, b1, W2, b2,
                                                   W3, b3, mW, mb, sW, sb, out);
}